// round 3
// baseline (speedup 1.0000x reference)
#include <cuda_runtime.h>

// Problem constants
#define Bc   2
#define Sc   2048
#define Dc   1024
#define Hc   16
#define DKc  64
#define Mc   (Bc * Sc)        // 4096 rows
#define BHc  (Bc * Hc)        // 32 head-batches

// ---------------------------------------------------------------------------
// Scratch (no cudaMalloc allowed)
// ---------------------------------------------------------------------------
__device__ float g_q[(size_t)BHc * Sc * DKc];    // [B,H,S,DK]
__device__ float g_k[(size_t)BHc * Sc * DKc];
__device__ float g_v[(size_t)BHc * Sc * DKc];
__device__ float g_ctx[(size_t)Mc * Dc];         // [B*S, H*DK]
__device__ float g_y[(size_t)Mc * Dc];           // pre-LN output

// ---------------------------------------------------------------------------
// Kernel 1: q/k/v = X @ W + b   (X = Q input, [4096,1024] @ [1024,1024])
// 128x128 tile, BK=8, 256 threads, 8x8 microtile, double-buffered smem.
// Epilogue scatters to [B,H,S,DK].
// ---------------------------------------------------------------------------
__global__ __launch_bounds__(256) void proj_qkv_kernel(
    const float* __restrict__ X,
    const float* __restrict__ Wq, const float* __restrict__ bq,
    const float* __restrict__ Wk, const float* __restrict__ bk,
    const float* __restrict__ Wv, const float* __restrict__ bv)
{
    const float *W, *bias;
    float* out;
    if (blockIdx.z == 0)      { W = Wq; bias = bq; out = g_q; }
    else if (blockIdx.z == 1) { W = Wk; bias = bk; out = g_k; }
    else                      { W = Wv; bias = bv; out = g_v; }

    __shared__ float As[2][8][128];
    __shared__ float Bs[2][8][128];

    const int tid  = threadIdx.x;
    const int row0 = blockIdx.y * 128;
    const int col0 = blockIdx.x * 128;

    const int a_row = tid >> 1;            // 0..127
    const int a_k   = (tid & 1) * 4;       // 0 or 4
    const int b_k   = tid >> 5;            // 0..7
    const int b_col = (tid & 31) * 4;      // 0..124

    const float* Ap = X + (size_t)(row0 + a_row) * Dc + a_k;
    const float* Bp = W + (size_t)b_k * Dc + col0 + b_col;

    const int rb = (tid >> 4) * 8;         // 0..120
    const int cb = (tid & 15) * 8;         // 0..120

    float acc[8][8];
    #pragma unroll
    for (int i = 0; i < 8; ++i)
        #pragma unroll
        for (int j = 0; j < 8; ++j) acc[i][j] = 0.f;

    float4 a_ld = *(const float4*)Ap;
    float4 b_ld = *(const float4*)Bp;
    As[0][a_k + 0][a_row] = a_ld.x;
    As[0][a_k + 1][a_row] = a_ld.y;
    As[0][a_k + 2][a_row] = a_ld.z;
    As[0][a_k + 3][a_row] = a_ld.w;
    *(float4*)&Bs[0][b_k][b_col] = b_ld;
    __syncthreads();

    const int nT = Dc / 8;   // 128
    for (int t = 0; t < nT; ++t) {
        const int cur = t & 1;
        if (t + 1 < nT) {
            a_ld = *(const float4*)(Ap + (t + 1) * 8);
            b_ld = *(const float4*)(Bp + (size_t)(t + 1) * 8 * Dc);
        }
        #pragma unroll
        for (int k = 0; k < 8; ++k) {
            float4 a0 = *(const float4*)&As[cur][k][rb];
            float4 a1 = *(const float4*)&As[cur][k][rb + 4];
            float4 b0 = *(const float4*)&Bs[cur][k][cb];
            float4 b1 = *(const float4*)&Bs[cur][k][cb + 4];
            float av[8] = {a0.x, a0.y, a0.z, a0.w, a1.x, a1.y, a1.z, a1.w};
            float bw[8] = {b0.x, b0.y, b0.z, b0.w, b1.x, b1.y, b1.z, b1.w};
            #pragma unroll
            for (int i = 0; i < 8; ++i)
                #pragma unroll
                for (int j = 0; j < 8; ++j)
                    acc[i][j] = fmaf(av[i], bw[j], acc[i][j]);
        }
        if (t + 1 < nT) {
            const int nxt = cur ^ 1;
            As[nxt][a_k + 0][a_row] = a_ld.x;
            As[nxt][a_k + 1][a_row] = a_ld.y;
            As[nxt][a_k + 2][a_row] = a_ld.z;
            As[nxt][a_k + 3][a_row] = a_ld.w;
            *(float4*)&Bs[nxt][b_k][b_col] = b_ld;
            __syncthreads();
        }
    }

    // epilogue: scatter to [B,H,S,DK] + bias
    float bias8[8];
    *(float4*)&bias8[0] = *(const float4*)&bias[col0 + cb];
    *(float4*)&bias8[4] = *(const float4*)&bias[col0 + cb + 4];
    const int col = col0 + cb;
    const int h   = col >> 6;       // /DK
    const int dk  = col & 63;
    #pragma unroll
    for (int r = 0; r < 8; ++r) {
        const int row  = row0 + rb + r;
        const int bidx = row >> 11;     // /S
        const int s    = row & 2047;
        float* dst = out + (((size_t)(bidx * Hc + h) * Sc + s) * DKc + dk);
        float4 o0 = make_float4(acc[r][0] + bias8[0], acc[r][1] + bias8[1],
                                acc[r][2] + bias8[2], acc[r][3] + bias8[3]);
        float4 o1 = make_float4(acc[r][4] + bias8[4], acc[r][5] + bias8[5],
                                acc[r][6] + bias8[6], acc[r][7] + bias8[7]);
        *(float4*)dst       = o0;
        *(float4*)(dst + 4) = o1;
    }
}

// ---------------------------------------------------------------------------
// Kernel 2: scores = (q @ k^T) * 0.125, masked.  Per (b,h): [2048,64]@[64,2048].
// Tile 64(i) x 128(j), full K=64 resident in smem. Writes raw masked scores
// into the attn region of d_out. Mask read as int32 words (nonzero == masked;
// also correct for a float32 0.0/1.0 mask).
// ---------------------------------------------------------------------------
__global__ __launch_bounds__(256) void scores_kernel(
    const unsigned int* __restrict__ mask, float* __restrict__ attn)
{
    const int bh = blockIdx.z;
    const int i0 = blockIdx.y * 64;
    const int j0 = blockIdx.x * 128;
    const int b  = bh >> 4;   // /H

    const float* qh = g_q + (size_t)bh * Sc * DKc;
    const float* kh = g_k + (size_t)bh * Sc * DKc;

    __shared__ float qs[64][64];    // [k][i]
    __shared__ float ks[64][128];   // [k][j]

    const int tid = threadIdx.x;

    #pragma unroll
    for (int l = 0; l < 4; ++l) {               // 1024 float4 of q tile
        int f  = tid + l * 256;
        int i  = f >> 4;
        int k4 = (f & 15) * 4;
        float4 v = *(const float4*)(qh + (size_t)(i0 + i) * DKc + k4);
        qs[k4 + 0][i] = v.x; qs[k4 + 1][i] = v.y;
        qs[k4 + 2][i] = v.z; qs[k4 + 3][i] = v.w;
    }
    #pragma unroll
    for (int l = 0; l < 8; ++l) {               // 2048 float4 of k tile
        int f  = tid + l * 256;
        int j  = f >> 4;
        int k4 = (f & 15) * 4;
        float4 v = *(const float4*)(kh + (size_t)(j0 + j) * DKc + k4);
        ks[k4 + 0][j] = v.x; ks[k4 + 1][j] = v.y;
        ks[k4 + 2][j] = v.z; ks[k4 + 3][j] = v.w;
    }
    __syncthreads();

    const int rb = (tid >> 4) * 4;   // 0..60
    const int cb = (tid & 15) * 8;   // 0..120

    float acc[4][8];
    #pragma unroll
    for (int i = 0; i < 4; ++i)
        #pragma unroll
        for (int j = 0; j < 8; ++j) acc[i][j] = 0.f;

    #pragma unroll 16
    for (int k = 0; k < 64; ++k) {
        float4 a  = *(const float4*)&qs[k][rb];
        float4 b0 = *(const float4*)&ks[k][cb];
        float4 b1 = *(const float4*)&ks[k][cb + 4];
        float av[4] = {a.x, a.y, a.z, a.w};
        float bw[8] = {b0.x, b0.y, b0.z, b0.w, b1.x, b1.y, b1.z, b1.w};
        #pragma unroll
        for (int i = 0; i < 4; ++i)
            #pragma unroll
            for (int j = 0; j < 8; ++j)
                acc[i][j] = fmaf(av[i], bw[j], acc[i][j]);
    }

    const float scale = 0.125f;
    #pragma unroll
    for (int r = 0; r < 4; ++r) {
        const int i = i0 + rb + r;
        const unsigned int* mrow =
            mask + ((size_t)b * Sc + i) * Sc + j0 + cb;
        float* arow = attn + ((size_t)bh * Sc + i) * Sc + j0 + cb;
        uint4 m0 = *(const uint4*)mrow;
        uint4 m1 = *(const uint4*)(mrow + 4);
        float o[8];
        o[0] = m0.x ? -1e9f : acc[r][0] * scale;
        o[1] = m0.y ? -1e9f : acc[r][1] * scale;
        o[2] = m0.z ? -1e9f : acc[r][2] * scale;
        o[3] = m0.w ? -1e9f : acc[r][3] * scale;
        o[4] = m1.x ? -1e9f : acc[r][4] * scale;
        o[5] = m1.y ? -1e9f : acc[r][5] * scale;
        o[6] = m1.z ? -1e9f : acc[r][6] * scale;
        o[7] = m1.w ? -1e9f : acc[r][7] * scale;
        *(float4*)arow       = make_float4(o[0], o[1], o[2], o[3]);
        *(float4*)(arow + 4) = make_float4(o[4], o[5], o[6], o[7]);
    }
}

// ---------------------------------------------------------------------------
// Kernel 3: in-place row softmax over the attn region. One block per row.
// ---------------------------------------------------------------------------
__global__ __launch_bounds__(256) void softmax_kernel(float* __restrict__ attn)
{
    float* p = attn + (size_t)blockIdx.x * Sc;
    const int tid = threadIdx.x;

    float4 v0 = ((float4*)p)[tid];
    float4 v1 = ((float4*)p)[tid + 256];

    float m = fmaxf(fmaxf(fmaxf(v0.x, v0.y), fmaxf(v0.z, v0.w)),
                    fmaxf(fmaxf(v1.x, v1.y), fmaxf(v1.z, v1.w)));

    __shared__ float s_max[8];
    __shared__ float s_sum[8];

    #pragma unroll
    for (int o = 16; o > 0; o >>= 1)
        m = fmaxf(m, __shfl_xor_sync(0xffffffffu, m, o));
    if ((tid & 31) == 0) s_max[tid >> 5] = m;
    __syncthreads();
    m = s_max[tid & 7];
    #pragma unroll
    for (int o = 4; o > 0; o >>= 1)
        m = fmaxf(m, __shfl_xor_sync(0xffffffffu, m, o));

    float e[8];
    e[0] = __expf(v0.x - m); e[1] = __expf(v0.y - m);
    e[2] = __expf(v0.z - m); e[3] = __expf(v0.w - m);
    e[4] = __expf(v1.x - m); e[5] = __expf(v1.y - m);
    e[6] = __expf(v1.z - m); e[7] = __expf(v1.w - m);

    float sum = e[0] + e[1] + e[2] + e[3] + e[4] + e[5] + e[6] + e[7];
    #pragma unroll
    for (int o = 16; o > 0; o >>= 1)
        sum += __shfl_xor_sync(0xffffffffu, sum, o);
    if ((tid & 31) == 0) s_sum[tid >> 5] = sum;
    __syncthreads();
    sum = s_sum[tid & 7];
    #pragma unroll
    for (int o = 4; o > 0; o >>= 1)
        sum += __shfl_xor_sync(0xffffffffu, sum, o);

    const float inv = 1.0f / sum;
    ((float4*)p)[tid]       = make_float4(e[0] * inv, e[1] * inv, e[2] * inv, e[3] * inv);
    ((float4*)p)[tid + 256] = make_float4(e[4] * inv, e[5] * inv, e[6] * inv, e[7] * inv);
}

// ---------------------------------------------------------------------------
// Kernel 4: context = attn @ v.  Per (b,h): [2048,2048]@[2048,64].
// BM=128, BN=64 (full DK), BK=16, 256 threads, 4x8 microtile, double-buffered.
// Epilogue writes [B*S, H*DK] layout.
// ---------------------------------------------------------------------------
__global__ __launch_bounds__(256) void av_kernel(const float* __restrict__ attn)
{
    const int bh = blockIdx.y;
    const int i0 = blockIdx.x * 128;
    const int b  = bh >> 4;
    const int h  = bh & 15;

    const float* abase = attn + (size_t)bh * Sc * Sc;
    const float* vh    = g_v + (size_t)bh * Sc * DKc;

    __shared__ float As[2][16][132];   // [k][i], padded stride 132
    __shared__ float Bs[2][16][64];    // [k][dk]

    const int tid = threadIdx.x;

    const int kb = tid >> 4;
    const int cv = (tid & 15) * 4;

    const int rb = (tid >> 3) * 4;   // 0..124
    const int cb = (tid & 7) * 8;    // 0..56

    float acc[4][8];
    #pragma unroll
    for (int i = 0; i < 4; ++i)
        #pragma unroll
        for (int j = 0; j < 8; ++j) acc[i][j] = 0.f;

    float4 aL[2];
    #pragma unroll
    for (int l = 0; l < 2; ++l) {
        int f  = tid + l * 256;
        int i  = f >> 2;
        int k4 = (f & 3) * 4;
        aL[l] = *(const float4*)(abase + (size_t)(i0 + i) * Sc + k4);
    }
    float4 bL = *(const float4*)(vh + (size_t)kb * DKc + cv);
    #pragma unroll
    for (int l = 0; l < 2; ++l) {
        int f  = tid + l * 256;
        int i  = f >> 2;
        int k4 = (f & 3) * 4;
        As[0][k4 + 0][i] = aL[l].x; As[0][k4 + 1][i] = aL[l].y;
        As[0][k4 + 2][i] = aL[l].z; As[0][k4 + 3][i] = aL[l].w;
    }
    *(float4*)&Bs[0][kb][cv] = bL;
    __syncthreads();

    const int nT = Sc / 16;  // 128
    for (int t = 0; t < nT; ++t) {
        const int cur = t & 1;
        if (t + 1 < nT) {
            #pragma unroll
            for (int l = 0; l < 2; ++l) {
                int f  = tid + l * 256;
                int i  = f >> 2;
                int k4 = (f & 3) * 4;
                aL[l] = *(const float4*)(abase + (size_t)(i0 + i) * Sc +
                                         (t + 1) * 16 + k4);
            }
            bL = *(const float4*)(vh + (size_t)((t + 1) * 16 + kb) * DKc + cv);
        }
        #pragma unroll
        for (int k = 0; k < 16; ++k) {
            float4 a  = *(const float4*)&As[cur][k][rb];
            float4 b0 = *(const float4*)&Bs[cur][k][cb];
            float4 b1 = *(const float4*)&Bs[cur][k][cb + 4];
            float av[4] = {a.x, a.y, a.z, a.w};
            float bw[8] = {b0.x, b0.y, b0.z, b0.w, b1.x, b1.y, b1.z, b1.w};
            #pragma unroll
            for (int i = 0; i < 4; ++i)
                #pragma unroll
                for (int j = 0; j < 8; ++j)
                    acc[i][j] = fmaf(av[i], bw[j], acc[i][j]);
        }
        if (t + 1 < nT) {
            const int nxt = cur ^ 1;
            #pragma unroll
            for (int l = 0; l < 2; ++l) {
                int f  = tid + l * 256;
                int i  = f >> 2;
                int k4 = (f & 3) * 4;
                As[nxt][k4 + 0][i] = aL[l].x; As[nxt][k4 + 1][i] = aL[l].y;
                As[nxt][k4 + 2][i] = aL[l].z; As[nxt][k4 + 3][i] = aL[l].w;
            }
            *(float4*)&Bs[nxt][kb][cv] = bL;
            __syncthreads();
        }
    }

    #pragma unroll
    for (int r = 0; r < 4; ++r) {
        const int i = i0 + rb + r;
        float* dst = g_ctx + ((size_t)b * Sc + i) * Dc + h * DKc + cb;
        *(float4*)dst       = make_float4(acc[r][0], acc[r][1], acc[r][2], acc[r][3]);
        *(float4*)(dst + 4) = make_float4(acc[r][4], acc[r][5], acc[r][6], acc[r][7]);
    }
}

// ---------------------------------------------------------------------------
// Kernel 5: y = ctx @ Wo + bo + residual(Q input).  Same SGEMM as kernel 1.
// ---------------------------------------------------------------------------
__global__ __launch_bounds__(256) void oproj_kernel(
    const float* __restrict__ Wo, const float* __restrict__ bo,
    const float* __restrict__ Qres)
{
    __shared__ float As[2][8][128];
    __shared__ float Bs[2][8][128];

    const int tid  = threadIdx.x;
    const int row0 = blockIdx.y * 128;
    const int col0 = blockIdx.x * 128;

    const int a_row = tid >> 1;
    const int a_k   = (tid & 1) * 4;
    const int b_k   = tid >> 5;
    const int b_col = (tid & 31) * 4;

    const float* Ap = g_ctx + (size_t)(row0 + a_row) * Dc + a_k;
    const float* Bp = Wo + (size_t)b_k * Dc + col0 + b_col;

    const int rb = (tid >> 4) * 8;
    const int cb = (tid & 15) * 8;

    float acc[8][8];
    #pragma unroll
    for (int i = 0; i < 8; ++i)
        #pragma unroll
        for (int j = 0; j < 8; ++j) acc[i][j] = 0.f;

    float4 a_ld = *(const float4*)Ap;
    float4 b_ld = *(const float4*)Bp;
    As[0][a_k + 0][a_row] = a_ld.x;
    As[0][a_k + 1][a_row] = a_ld.y;
    As[0][a_k + 2][a_row] = a_ld.z;
    As[0][a_k + 3][a_row] = a_ld.w;
    *(float4*)&Bs[0][b_k][b_col] = b_ld;
    __syncthreads();

    const int nT = Dc / 8;
    for (int t = 0; t < nT; ++t) {
        const int cur = t & 1;
        if (t + 1 < nT) {
            a_ld = *(const float4*)(Ap + (t + 1) * 8);
            b_ld = *(const float4*)(Bp + (size_t)(t + 1) * 8 * Dc);
        }
        #pragma unroll
        for (int k = 0; k < 8; ++k) {
            float4 a0 = *(const float4*)&As[cur][k][rb];
            float4 a1 = *(const float4*)&As[cur][k][rb + 4];
            float4 b0 = *(const float4*)&Bs[cur][k][cb];
            float4 b1 = *(const float4*)&Bs[cur][k][cb + 4];
            float av[8] = {a0.x, a0.y, a0.z, a0.w, a1.x, a1.y, a1.z, a1.w};
            float bw[8] = {b0.x, b0.y, b0.z, b0.w, b1.x, b1.y, b1.z, b1.w};
            #pragma unroll
            for (int i = 0; i < 8; ++i)
                #pragma unroll
                for (int j = 0; j < 8; ++j)
                    acc[i][j] = fmaf(av[i], bw[j], acc[i][j]);
        }
        if (t + 1 < nT) {
            const int nxt = cur ^ 1;
            As[nxt][a_k + 0][a_row] = a_ld.x;
            As[nxt][a_k + 1][a_row] = a_ld.y;
            As[nxt][a_k + 2][a_row] = a_ld.z;
            As[nxt][a_k + 3][a_row] = a_ld.w;
            *(float4*)&Bs[nxt][b_k][b_col] = b_ld;
            __syncthreads();
        }
    }

    float bias8[8];
    *(float4*)&bias8[0] = *(const float4*)&bo[col0 + cb];
    *(float4*)&bias8[4] = *(const float4*)&bo[col0 + cb + 4];
    #pragma unroll
    for (int r = 0; r < 8; ++r) {
        const int row = row0 + rb + r;
        const float* res = Qres + (size_t)row * Dc + col0 + cb;
        float4 r0 = *(const float4*)res;
        float4 r1 = *(const float4*)(res + 4);
        float* dst = g_y + (size_t)row * Dc + col0 + cb;
        *(float4*)dst = make_float4(acc[r][0] + bias8[0] + r0.x,
                                    acc[r][1] + bias8[1] + r0.y,
                                    acc[r][2] + bias8[2] + r0.z,
                                    acc[r][3] + bias8[3] + r0.w);
        *(float4*)(dst + 4) = make_float4(acc[r][4] + bias8[4] + r1.x,
                                          acc[r][5] + bias8[5] + r1.y,
                                          acc[r][6] + bias8[6] + r1.z,
                                          acc[r][7] + bias8[7] + r1.w);
    }
}

// ---------------------------------------------------------------------------
// Kernel 6: LayerNorm per row (1024 elems, one block per row).
// ---------------------------------------------------------------------------
__global__ __launch_bounds__(256) void ln_kernel(
    const float* __restrict__ gamma, const float* __restrict__ beta,
    float* __restrict__ out)
{
    const int row = blockIdx.x;
    const int tid = threadIdx.x;
    const float* y = g_y + (size_t)row * Dc;

    float4 v = ((const float4*)y)[tid];
    float s  = v.x + v.y + v.z + v.w;
    float q  = v.x * v.x + v.y * v.y + v.z * v.z + v.w * v.w;

    __shared__ float ss[8];
    __shared__ float sq[8];
    #pragma unroll
    for (int o = 16; o > 0; o >>= 1) {
        s += __shfl_xor_sync(0xffffffffu, s, o);
        q += __shfl_xor_sync(0xffffffffu, q, o);
    }
    if ((tid & 31) == 0) { ss[tid >> 5] = s; sq[tid >> 5] = q; }
    __syncthreads();
    s = ss[tid & 7];
    q = sq[tid & 7];
    #pragma unroll
    for (int o = 4; o > 0; o >>= 1) {
        s += __shfl_xor_sync(0xffffffffu, s, o);
        q += __shfl_xor_sync(0xffffffffu, q, o);
    }

    const float mu  = s * (1.0f / Dc);
    const float var = q * (1.0f / Dc) - mu * mu;
    const float inv = rsqrtf(var + 1e-5f);

    float4 gv = ((const float4*)gamma)[tid];
    float4 bv = ((const float4*)beta)[tid];
    float4 o4 = make_float4((v.x - mu) * inv * gv.x + bv.x,
                            (v.y - mu) * inv * gv.y + bv.y,
                            (v.z - mu) * inv * gv.z + bv.z,
                            (v.w - mu) * inv * gv.w + bv.w);
    ((float4*)(out + (size_t)row * Dc))[tid] = o4;
}

// ---------------------------------------------------------------------------
// Launch
// d_in: 0=Q 1=K(unused) 2=V(unused) 3=attn_mask(int32) 4=Wq 5=bq 6=Wk 7=bk
//       8=Wv 9=bv 10=Wo 11=bo 12=ln_g 13=ln_b
// d_out: [ln_out (B*S*D floats)] [attn (B*H*S*S floats)]
// ---------------------------------------------------------------------------
extern "C" void kernel_launch(void* const* d_in, const int* in_sizes, int n_in,
                              void* d_out, int out_size)
{
    const float* Qin  = (const float*)d_in[0];
    const unsigned int* mask = (const unsigned int*)d_in[3];
    const float* Wq = (const float*)d_in[4];
    const float* bq = (const float*)d_in[5];
    const float* Wk = (const float*)d_in[6];
    const float* bk = (const float*)d_in[7];
    const float* Wv = (const float*)d_in[8];
    const float* bv = (const float*)d_in[9];
    const float* Wo = (const float*)d_in[10];
    const float* bo = (const float*)d_in[11];
    const float* ln_g = (const float*)d_in[12];
    const float* ln_b = (const float*)d_in[13];

    float* out  = (float*)d_out;
    float* attn = out + (size_t)Bc * Sc * Dc;

    proj_qkv_kernel<<<dim3(Dc / 128, Mc / 128, 3), 256>>>(
        Qin, Wq, bq, Wk, bk, Wv, bv);
    scores_kernel<<<dim3(Sc / 128, Sc / 64, BHc), 256>>>(mask, attn);
    softmax_kernel<<<BHc * Sc, 256>>>(attn);
    av_kernel<<<dim3(Sc / 128, BHc), 256>>>(attn);
    oproj_kernel<<<dim3(Dc / 128, Mc / 128), 256>>>(Wo, bo, Qin);
    ln_kernel<<<Mc, 256>>>(ln_g, ln_b, out);
}

// round 5
// speedup vs baseline: 2.4516x; 2.4516x over previous
#include <cuda_runtime.h>
#include <cuda_bf16.h>

#define Bc   2
#define Sc   2048
#define Dc   1024
#define Hc   16
#define DKc  64
#define Mc   (Bc * Sc)        // 4096
#define BHc  (Bc * Hc)        // 32

// ---------------------------------------------------------------------------
// Scratch (__device__ globals; no cudaMalloc allowed)
// ---------------------------------------------------------------------------
__device__ __align__(16) __nv_bfloat16 g_xb [(size_t)Mc * Dc];          // X bf16 (V path)
__device__ __align__(16) __nv_bfloat16 g_wT [4][(size_t)Dc * Dc];       // bf16 W^T (only [2],[3] used)
__device__ __align__(16) float         g_wTf[2][(size_t)Dc * Dc];       // fp32 W^T for Wq,Wk
__device__ __align__(16) float         g_qf [(size_t)BHc * Sc * DKc];   // q fp32 [bh][s][dk]
__device__ __align__(16) float         g_kf [(size_t)BHc * Sc * DKc];   // k fp32 [bh][s][dk]
__device__ __align__(16) __nv_bfloat16 g_vT [(size_t)BHc * DKc * Sc];   // v bf16 [bh][dk][s]
__device__ __align__(16) __nv_bfloat16 g_ctxb[(size_t)Mc * Dc];         // ctx bf16
__device__ float    g_l   [(size_t)BHc * Sc];                            // row sums of exp
__device__ unsigned g_mask[(size_t)Bc * Sc * (Sc / 32)];                 // bit-packed mask
__device__ __align__(16) float g_y [(size_t)Mc * Dc];                    // pre-LN

// ---------------------------------------------------------------------------
// MMA helpers
// ---------------------------------------------------------------------------
__device__ __forceinline__ void mma_bf16(
    float& c0, float& c1, float& c2, float& c3,
    unsigned a0, unsigned a1, unsigned a2, unsigned a3,
    unsigned b0, unsigned b1)
{
    asm volatile(
        "mma.sync.aligned.m16n8k16.row.col.f32.bf16.bf16.f32 "
        "{%0,%1,%2,%3}, {%4,%5,%6,%7}, {%8,%9}, {%0,%1,%2,%3};\n"
        : "+f"(c0), "+f"(c1), "+f"(c2), "+f"(c3)
        : "r"(a0), "r"(a1), "r"(a2), "r"(a3), "r"(b0), "r"(b1));
}

__device__ __forceinline__ void mma_tf32(
    float& c0, float& c1, float& c2, float& c3,
    unsigned a0, unsigned a1, unsigned a2, unsigned a3,
    unsigned b0, unsigned b1)
{
    asm volatile(
        "mma.sync.aligned.m16n8k8.row.col.f32.tf32.tf32.f32 "
        "{%0,%1,%2,%3}, {%4,%5,%6,%7}, {%8,%9}, {%0,%1,%2,%3};\n"
        : "+f"(c0), "+f"(c1), "+f"(c2), "+f"(c3)
        : "r"(a0), "r"(a1), "r"(a2), "r"(a3), "r"(b0), "r"(b1));
}

__device__ __forceinline__ unsigned f2tf(float x)
{
    unsigned r;
    asm("cvt.rna.tf32.f32 %0, %1;" : "=r"(r) : "f"(x));
    return r;
}

// ---------------------------------------------------------------------------
// Pre-pass: X fp32 -> bf16 (V path only)
// ---------------------------------------------------------------------------
__global__ __launch_bounds__(256) void cvt_x_kernel(const float* __restrict__ X)
{
    size_t i = ((size_t)blockIdx.x * 256 + threadIdx.x) * 4;
    float4 v = *(const float4*)(X + i);
    __nv_bfloat162* d = (__nv_bfloat162*)(g_xb + i);
    d[0] = __floats2bfloat162_rn(v.x, v.y);
    d[1] = __floats2bfloat162_rn(v.z, v.w);
}

// ---------------------------------------------------------------------------
// Pre-pass: weights [k][n] -> transposed [n][k]; fp32 for Wq/Wk, bf16 for Wv/Wo
// ---------------------------------------------------------------------------
__global__ __launch_bounds__(256) void cvt_wT_kernel(
    const float* __restrict__ W0, const float* __restrict__ W1,
    const float* __restrict__ W2, const float* __restrict__ W3)
{
    const int z = blockIdx.z;
    const float* W = z == 0 ? W0 : z == 1 ? W1 : z == 2 ? W2 : W3;
    __shared__ float tile[32][33];
    const int tx = threadIdx.x & 31, ty = threadIdx.x >> 5;
    const int k0 = blockIdx.x * 32, n0 = blockIdx.y * 32;
    #pragma unroll
    for (int i = 0; i < 4; ++i)
        tile[ty + i * 8][tx] = W[(size_t)(k0 + ty + i * 8) * Dc + n0 + tx];
    __syncthreads();
    if (z < 2) {
        float* out = g_wTf[z];
        #pragma unroll
        for (int i = 0; i < 4; ++i)
            out[(size_t)(n0 + ty + i * 8) * Dc + k0 + tx] = tile[tx][ty + i * 8];
    } else {
        __nv_bfloat16* out = g_wT[z];
        #pragma unroll
        for (int i = 0; i < 4; ++i)
            out[(size_t)(n0 + ty + i * 8) * Dc + k0 + tx] =
                __float2bfloat16(tile[tx][ty + i * 8]);
    }
}

// ---------------------------------------------------------------------------
// Pre-pass: bit-pack mask (int32 nonzero -> 1 bit)
// ---------------------------------------------------------------------------
__global__ __launch_bounds__(256) void mask_pack_kernel(const unsigned* __restrict__ mask)
{
    const int w    = blockIdx.x * 8 + (threadIdx.x >> 5);
    const int lane = threadIdx.x & 31;
    unsigned v = mask[(size_t)w * 32 + lane];
    unsigned bits = __ballot_sync(0xffffffffu, v != 0);
    if (lane == 0) g_mask[w] = bits;
}

// ---------------------------------------------------------------------------
// Kernel 1a: q/k projections in tf32 (fp32 in, fp32 out).
// C[4096x1024] = X @ W[z] + b.  BM=128 BN=128 BK=32, 8 warps 4x2, warp 32x64.
// ---------------------------------------------------------------------------
__global__ __launch_bounds__(256) void proj_qk_tf32_kernel(
    const float* __restrict__ X,
    const float* __restrict__ bq, const float* __restrict__ bk)
{
    const int z = blockIdx.z;
    const float* Wt = g_wTf[z];
    const float* bias = z == 0 ? bq : bk;
    float* outp = z == 0 ? g_qf : g_kf;

    __shared__ __align__(16) float as[128][36];
    __shared__ __align__(16) float bs[128][36];

    const int tid  = threadIdx.x;
    const int warp = tid >> 5, lane = tid & 31;
    const int g = lane >> 2, t = lane & 3;
    const int wm = warp >> 1, wn = warp & 1;
    const int row0 = blockIdx.y * 128;
    const int col0 = blockIdx.x * 128;

    float c[2][8][4];
    #pragma unroll
    for (int mt = 0; mt < 2; ++mt)
        #pragma unroll
        for (int nt = 0; nt < 8; ++nt)
            #pragma unroll
            for (int q = 0; q < 4; ++q) c[mt][nt][q] = 0.f;

    for (int kk = 0; kk < Dc; kk += 32) {
        __syncthreads();
        #pragma unroll
        for (int it = 0; it < 4; ++it) {
            int f = tid + it * 256;
            int r = f >> 3, c4 = (f & 7) * 4;
            *(float4*)&as[r][c4] = *(const float4*)(X  + (size_t)(row0 + r) * Dc + kk + c4);
            *(float4*)&bs[r][c4] = *(const float4*)(Wt + (size_t)(col0 + r) * Dc + kk + c4);
        }
        __syncthreads();
        #pragma unroll
        for (int kf = 0; kf < 4; ++kf) {
            const int k0 = kf * 8;
            unsigned A[2][4];
            #pragma unroll
            for (int mt = 0; mt < 2; ++mt) {
                int r = wm * 32 + mt * 16 + g;
                A[mt][0] = f2tf(as[r    ][k0 + t]);
                A[mt][1] = f2tf(as[r + 8][k0 + t]);
                A[mt][2] = f2tf(as[r    ][k0 + t + 4]);
                A[mt][3] = f2tf(as[r + 8][k0 + t + 4]);
            }
            #pragma unroll
            for (int nt = 0; nt < 8; ++nt) {
                int n = wn * 64 + nt * 8 + g;
                unsigned b0 = f2tf(bs[n][k0 + t]);
                unsigned b1 = f2tf(bs[n][k0 + t + 4]);
                mma_tf32(c[0][nt][0], c[0][nt][1], c[0][nt][2], c[0][nt][3],
                         A[0][0], A[0][1], A[0][2], A[0][3], b0, b1);
                mma_tf32(c[1][nt][0], c[1][nt][1], c[1][nt][2], c[1][nt][3],
                         A[1][0], A[1][1], A[1][2], A[1][3], b0, b1);
            }
        }
    }

    #pragma unroll
    for (int mt = 0; mt < 2; ++mt) {
        #pragma unroll
        for (int nt = 0; nt < 8; ++nt) {
            const int col = col0 + wn * 64 + nt * 8 + t * 2;
            const int h = col >> 6, dk = col & 63;
            const float bi0 = bias[col], bi1 = bias[col + 1];
            const int r0 = row0 + wm * 32 + mt * 16 + g;
            #pragma unroll
            for (int rr = 0; rr < 2; ++rr) {
                const int rowg = r0 + rr * 8;
                const int b = rowg >> 11, s = rowg & 2047;
                float* dst = outp + ((size_t)(b * Hc + h) * Sc + s) * DKc + dk;
                *(float2*)dst = make_float2(c[mt][nt][rr * 2 + 0] + bi0,
                                            c[mt][nt][rr * 2 + 1] + bi1);
            }
        }
    }
}

// ---------------------------------------------------------------------------
// Kernel 1b: v projection, bf16 MMA -> g_vT [bh][dk][s].
// ---------------------------------------------------------------------------
__global__ __launch_bounds__(256) void proj_v_mma_kernel(const float* __restrict__ bv)
{
    const __nv_bfloat16* Wt = g_wT[2];

    __shared__ __align__(16) __nv_bfloat16 as[128][40];
    __shared__ __align__(16) __nv_bfloat16 bs[128][40];

    const int tid  = threadIdx.x;
    const int warp = tid >> 5, lane = tid & 31;
    const int g = lane >> 2, t = lane & 3;
    const int wm = warp >> 1, wn = warp & 1;
    const int row0 = blockIdx.y * 128;
    const int col0 = blockIdx.x * 128;

    float c[2][8][4];
    #pragma unroll
    for (int mt = 0; mt < 2; ++mt)
        #pragma unroll
        for (int nt = 0; nt < 8; ++nt)
            #pragma unroll
            for (int q = 0; q < 4; ++q) c[mt][nt][q] = 0.f;

    for (int kk = 0; kk < Dc; kk += 32) {
        __syncthreads();
        #pragma unroll
        for (int it = 0; it < 2; ++it) {
            int f = tid + it * 256;
            int r = f >> 2, c8 = (f & 3) * 8;
            *(uint4*)&as[r][c8] = *(const uint4*)(g_xb + (size_t)(row0 + r) * Dc + kk + c8);
            *(uint4*)&bs[r][c8] = *(const uint4*)(Wt   + (size_t)(col0 + r) * Dc + kk + c8);
        }
        __syncthreads();
        #pragma unroll
        for (int kf = 0; kf < 2; ++kf) {
            const int k0 = kf * 16;
            unsigned A[2][4];
            #pragma unroll
            for (int mt = 0; mt < 2; ++mt) {
                int r = wm * 32 + mt * 16 + g;
                A[mt][0] = *(const unsigned*)&as[r    ][k0     + t * 2];
                A[mt][1] = *(const unsigned*)&as[r + 8][k0     + t * 2];
                A[mt][2] = *(const unsigned*)&as[r    ][k0 + 8 + t * 2];
                A[mt][3] = *(const unsigned*)&as[r + 8][k0 + 8 + t * 2];
            }
            #pragma unroll
            for (int nt = 0; nt < 8; ++nt) {
                int n = wn * 64 + nt * 8 + g;
                unsigned b0 = *(const unsigned*)&bs[n][k0     + t * 2];
                unsigned b1 = *(const unsigned*)&bs[n][k0 + 8 + t * 2];
                mma_bf16(c[0][nt][0], c[0][nt][1], c[0][nt][2], c[0][nt][3],
                         A[0][0], A[0][1], A[0][2], A[0][3], b0, b1);
                mma_bf16(c[1][nt][0], c[1][nt][1], c[1][nt][2], c[1][nt][3],
                         A[1][0], A[1][1], A[1][2], A[1][3], b0, b1);
            }
        }
    }

    #pragma unroll
    for (int mt = 0; mt < 2; ++mt) {
        #pragma unroll
        for (int nt = 0; nt < 8; ++nt) {
            const int col = col0 + wn * 64 + nt * 8 + t * 2;
            const int h = col >> 6, dk = col & 63;
            const float bi0 = bv[col], bi1 = bv[col + 1];
            const int r0 = row0 + wm * 32 + mt * 16 + g;
            #pragma unroll
            for (int rr = 0; rr < 2; ++rr) {
                const int rowg = r0 + rr * 8;
                const int b = rowg >> 11, s = rowg & 2047;
                g_vT[((size_t)(b * Hc + h) * DKc + dk    ) * Sc + s] =
                    __float2bfloat16(c[mt][nt][rr * 2 + 0] + bi0);
                g_vT[((size_t)(b * Hc + h) * DKc + dk + 1) * Sc + s] =
                    __float2bfloat16(c[mt][nt][rr * 2 + 1] + bi1);
            }
        }
    }
}

// ---------------------------------------------------------------------------
// Kernel 2: fused scores (tf32) + mask + unnormalized exp.
// e = exp(0.125 * q.k^T) (masked -> 0) fp32 into attn; row sums -> g_l.
// ---------------------------------------------------------------------------
__global__ __launch_bounds__(256) void scores_tf32_kernel(float* __restrict__ attn)
{
    const int bh = blockIdx.y;
    const int i0 = blockIdx.x * 128;
    const int b  = bh >> 4;

    __shared__ __align__(16) float qs[128][68];
    __shared__ __align__(16) float ks[64][68];

    const int tid = threadIdx.x, warp = tid >> 5, lane = tid & 31;
    const int g = lane >> 2, t = lane & 3;

    const float* qbase = g_qf + ((size_t)bh * Sc + i0) * DKc;
    const float* kbase = g_kf + (size_t)bh * Sc * DKc;

    #pragma unroll
    for (int it = 0; it < 8; ++it) {
        int f = tid + it * 256;
        int r = f >> 4, c4 = (f & 15) * 4;
        *(float4*)&qs[r][c4] = *(const float4*)(qbase + (size_t)r * DKc + c4);
    }
    __syncthreads();

    unsigned A[8][4];
    {
        const int r = warp * 16 + g;
        #pragma unroll
        for (int kf = 0; kf < 8; ++kf) {
            const int k0 = kf * 8;
            A[kf][0] = f2tf(qs[r    ][k0 + t]);
            A[kf][1] = f2tf(qs[r + 8][k0 + t]);
            A[kf][2] = f2tf(qs[r    ][k0 + t + 4]);
            A[kf][3] = f2tf(qs[r + 8][k0 + t + 4]);
        }
    }

    const int ig0 = i0 + warp * 16 + g;
    const int ig1 = ig0 + 8;
    const unsigned* mp0 = g_mask + ((size_t)b * Sc + ig0) * (Sc / 32);
    const unsigned* mp1 = g_mask + ((size_t)b * Sc + ig1) * (Sc / 32);
    float* arow0 = attn + ((size_t)bh * Sc + ig0) * Sc;
    float* arow1 = attn + ((size_t)bh * Sc + ig1) * Sc;

    float rsum0 = 0.f, rsum1 = 0.f;

    for (int jj = 0; jj < Sc; jj += 64) {
        __syncthreads();
        #pragma unroll
        for (int it = 0; it < 4; ++it) {
            int f = tid + it * 256;
            int r = f >> 4, c4 = (f & 15) * 4;
            *(float4*)&ks[r][c4] = *(const float4*)(kbase + (size_t)(jj + r) * DKc + c4);
        }
        __syncthreads();

        float c[8][4];
        #pragma unroll
        for (int nt = 0; nt < 8; ++nt)
            #pragma unroll
            for (int q = 0; q < 4; ++q) c[nt][q] = 0.f;

        #pragma unroll
        for (int kf = 0; kf < 8; ++kf) {
            const int k0 = kf * 8;
            #pragma unroll
            for (int nt = 0; nt < 8; ++nt) {
                unsigned b0 = f2tf(ks[nt * 8 + g][k0 + t]);
                unsigned b1 = f2tf(ks[nt * 8 + g][k0 + t + 4]);
                mma_tf32(c[nt][0], c[nt][1], c[nt][2], c[nt][3],
                         A[kf][0], A[kf][1], A[kf][2], A[kf][3], b0, b1);
            }
        }

        const unsigned m00 = mp0[jj >> 5], m01 = mp0[(jj >> 5) + 1];
        const unsigned m10 = mp1[jj >> 5], m11 = mp1[(jj >> 5) + 1];

        #pragma unroll
        for (int nt = 0; nt < 8; ++nt) {
            const int jl = nt * 8 + t * 2;
            const unsigned w0 = (jl & 32) ? m01 : m00;
            const unsigned w1 = (jl & 32) ? m11 : m10;
            const int sh = jl & 31;
            float e0 = ((w0 >> sh)       & 1u) ? 0.f : __expf(c[nt][0] * 0.125f);
            float e1 = ((w0 >> (sh + 1)) & 1u) ? 0.f : __expf(c[nt][1] * 0.125f);
            float e2 = ((w1 >> sh)       & 1u) ? 0.f : __expf(c[nt][2] * 0.125f);
            float e3 = ((w1 >> (sh + 1)) & 1u) ? 0.f : __expf(c[nt][3] * 0.125f);
            rsum0 += e0 + e1;
            rsum1 += e2 + e3;
            *(float2*)(arow0 + jj + jl) = make_float2(e0, e1);
            *(float2*)(arow1 + jj + jl) = make_float2(e2, e3);
        }
    }

    rsum0 += __shfl_xor_sync(0xffffffffu, rsum0, 1);
    rsum0 += __shfl_xor_sync(0xffffffffu, rsum0, 2);
    rsum1 += __shfl_xor_sync(0xffffffffu, rsum1, 1);
    rsum1 += __shfl_xor_sync(0xffffffffu, rsum1, 2);
    if (t == 0) {
        g_l[(size_t)bh * Sc + ig0] = rsum0;
        g_l[(size_t)bh * Sc + ig1] = rsum1;
    }
}

// ---------------------------------------------------------------------------
// Kernel 3: av. Reads e, normalizes p=e/l, writes p back in-place (the attn
// output), accumulates ctx = p @ V via bf16 MMA.
// ---------------------------------------------------------------------------
__global__ __launch_bounds__(256) void av_mma_kernel(float* __restrict__ attn)
{
    const int bh = blockIdx.y;
    const int i0 = blockIdx.x * 128;
    const int b  = bh >> 4, h = bh & 15;

    __shared__ __align__(16) __nv_bfloat16 ps[128][72];
    __shared__ __align__(16) __nv_bfloat16 vs[64][72];
    __shared__ float sinvl[128];

    const int tid = threadIdx.x, warp = tid >> 5, lane = tid & 31;
    const int g = lane >> 2, t = lane & 3;

    if (tid < 128) sinvl[tid] = 1.0f / g_l[(size_t)bh * Sc + i0 + tid];

    float c[8][4];
    #pragma unroll
    for (int nt = 0; nt < 8; ++nt)
        #pragma unroll
        for (int q = 0; q < 4; ++q) c[nt][q] = 0.f;

    float* abase = attn + ((size_t)bh * Sc + i0) * Sc;
    const __nv_bfloat16* vbase = g_vT + (size_t)bh * DKc * Sc;

    for (int jj = 0; jj < Sc; jj += 64) {
        __syncthreads();
        #pragma unroll
        for (int it = 0; it < 8; ++it) {
            int f = tid + it * 256;
            int r = f >> 4, c4 = (f & 15) * 4;
            float* ap = abase + (size_t)r * Sc + jj + c4;
            float4 e = *(float4*)ap;
            float il = sinvl[r];
            float4 p = make_float4(e.x * il, e.y * il, e.z * il, e.w * il);
            *(float4*)ap = p;
            *(__nv_bfloat162*)&ps[r][c4]     = __floats2bfloat162_rn(p.x, p.y);
            *(__nv_bfloat162*)&ps[r][c4 + 2] = __floats2bfloat162_rn(p.z, p.w);
        }
        #pragma unroll
        for (int it = 0; it < 2; ++it) {
            int f = tid + it * 256;
            int dk = f >> 3, c8 = (f & 7) * 8;
            *(uint4*)&vs[dk][c8] = *(const uint4*)(vbase + (size_t)dk * Sc + jj + c8);
        }
        __syncthreads();

        const int r = warp * 16 + g;
        #pragma unroll
        for (int kf = 0; kf < 4; ++kf) {
            const int k0 = kf * 16;
            unsigned a0 = *(const unsigned*)&ps[r    ][k0     + t * 2];
            unsigned a1 = *(const unsigned*)&ps[r + 8][k0     + t * 2];
            unsigned a2 = *(const unsigned*)&ps[r    ][k0 + 8 + t * 2];
            unsigned a3 = *(const unsigned*)&ps[r + 8][k0 + 8 + t * 2];
            #pragma unroll
            for (int nt = 0; nt < 8; ++nt) {
                unsigned b0 = *(const unsigned*)&vs[nt * 8 + g][k0     + t * 2];
                unsigned b1 = *(const unsigned*)&vs[nt * 8 + g][k0 + 8 + t * 2];
                mma_bf16(c[nt][0], c[nt][1], c[nt][2], c[nt][3],
                         a0, a1, a2, a3, b0, b1);
            }
        }
    }

    const int s = i0 + warp * 16 + g;
    const size_t crow0 = ((size_t)b * Sc + s)     * Dc;
    const size_t crow1 = ((size_t)b * Sc + s + 8) * Dc;
    #pragma unroll
    for (int nt = 0; nt < 8; ++nt) {
        const int col = h * DKc + nt * 8 + t * 2;
        *(__nv_bfloat162*)&g_ctxb[crow0 + col] = __floats2bfloat162_rn(c[nt][0], c[nt][1]);
        *(__nv_bfloat162*)&g_ctxb[crow1 + col] = __floats2bfloat162_rn(c[nt][2], c[nt][3]);
    }
}

// ---------------------------------------------------------------------------
// Kernel 4: output projection, bf16 MMA. y = ctxb @ Wo + bo + residual (fp32).
// ---------------------------------------------------------------------------
__global__ __launch_bounds__(256) void oproj_mma_kernel(
    const float* __restrict__ bo, const float* __restrict__ Qres)
{
    const __nv_bfloat16* Wt = g_wT[3];

    __shared__ __align__(16) __nv_bfloat16 as[128][40];
    __shared__ __align__(16) __nv_bfloat16 bs[128][40];

    const int tid  = threadIdx.x;
    const int warp = tid >> 5, lane = tid & 31;
    const int g = lane >> 2, t = lane & 3;
    const int wm = warp >> 1, wn = warp & 1;
    const int row0 = blockIdx.y * 128;
    const int col0 = blockIdx.x * 128;

    float c[2][8][4];
    #pragma unroll
    for (int mt = 0; mt < 2; ++mt)
        #pragma unroll
        for (int nt = 0; nt < 8; ++nt)
            #pragma unroll
            for (int q = 0; q < 4; ++q) c[mt][nt][q] = 0.f;

    for (int kk = 0; kk < Dc; kk += 32) {
        __syncthreads();
        #pragma unroll
        for (int it = 0; it < 2; ++it) {
            int f = tid + it * 256;
            int r = f >> 2, c8 = (f & 3) * 8;
            *(uint4*)&as[r][c8] = *(const uint4*)(g_ctxb + (size_t)(row0 + r) * Dc + kk + c8);
            *(uint4*)&bs[r][c8] = *(const uint4*)(Wt     + (size_t)(col0 + r) * Dc + kk + c8);
        }
        __syncthreads();
        #pragma unroll
        for (int kf = 0; kf < 2; ++kf) {
            const int k0 = kf * 16;
            unsigned A[2][4];
            #pragma unroll
            for (int mt = 0; mt < 2; ++mt) {
                int r = wm * 32 + mt * 16 + g;
                A[mt][0] = *(const unsigned*)&as[r    ][k0     + t * 2];
                A[mt][1] = *(const unsigned*)&as[r + 8][k0     + t * 2];
                A[mt][2] = *(const unsigned*)&as[r    ][k0 + 8 + t * 2];
                A[mt][3] = *(const unsigned*)&as[r + 8][k0 + 8 + t * 2];
            }
            #pragma unroll
            for (int nt = 0; nt < 8; ++nt) {
                int n = wn * 64 + nt * 8 + g;
                unsigned b0 = *(const unsigned*)&bs[n][k0     + t * 2];
                unsigned b1 = *(const unsigned*)&bs[n][k0 + 8 + t * 2];
                mma_bf16(c[0][nt][0], c[0][nt][1], c[0][nt][2], c[0][nt][3],
                         A[0][0], A[0][1], A[0][2], A[0][3], b0, b1);
                mma_bf16(c[1][nt][0], c[1][nt][1], c[1][nt][2], c[1][nt][3],
                         A[1][0], A[1][1], A[1][2], A[1][3], b0, b1);
            }
        }
    }

    #pragma unroll
    for (int mt = 0; mt < 2; ++mt) {
        #pragma unroll
        for (int nt = 0; nt < 8; ++nt) {
            const int col = col0 + wn * 64 + nt * 8 + t * 2;
            const float bi0 = bo[col], bi1 = bo[col + 1];
            const int r0 = row0 + wm * 32 + mt * 16 + g;
            #pragma unroll
            for (int rr = 0; rr < 2; ++rr) {
                const int rowg = r0 + rr * 8;
                const float* res = Qres + (size_t)rowg * Dc + col;
                float2 rv = *(const float2*)res;
                float2 o = make_float2(c[mt][nt][rr * 2 + 0] + bi0 + rv.x,
                                       c[mt][nt][rr * 2 + 1] + bi1 + rv.y);
                *(float2*)(g_y + (size_t)rowg * Dc + col) = o;
            }
        }
    }
}

// ---------------------------------------------------------------------------
// Kernel 5: LayerNorm per row (fp32).
// ---------------------------------------------------------------------------
__global__ __launch_bounds__(256) void ln_kernel(
    const float* __restrict__ gamma, const float* __restrict__ beta,
    float* __restrict__ out)
{
    const int row = blockIdx.x;
    const int tid = threadIdx.x;
    const float* y = g_y + (size_t)row * Dc;

    float4 v = ((const float4*)y)[tid];
    float s  = v.x + v.y + v.z + v.w;
    float q  = v.x * v.x + v.y * v.y + v.z * v.z + v.w * v.w;

    __shared__ float ss[8];
    __shared__ float sq[8];
    #pragma unroll
    for (int o = 16; o > 0; o >>= 1) {
        s += __shfl_xor_sync(0xffffffffu, s, o);
        q += __shfl_xor_sync(0xffffffffu, q, o);
    }
    if ((tid & 31) == 0) { ss[tid >> 5] = s; sq[tid >> 5] = q; }
    __syncthreads();
    s = ss[tid & 7];
    q = sq[tid & 7];
    #pragma unroll
    for (int o = 4; o > 0; o >>= 1) {
        s += __shfl_xor_sync(0xffffffffu, s, o);
        q += __shfl_xor_sync(0xffffffffu, q, o);
    }

    const float mu  = s * (1.0f / Dc);
    const float var = q * (1.0f / Dc) - mu * mu;
    const float inv = rsqrtf(var + 1e-5f);

    float4 gv = ((const float4*)gamma)[tid];
    float4 bv = ((const float4*)beta)[tid];
    float4 o4 = make_float4((v.x - mu) * inv * gv.x + bv.x,
                            (v.y - mu) * inv * gv.y + bv.y,
                            (v.z - mu) * inv * gv.z + bv.z,
                            (v.w - mu) * inv * gv.w + bv.w);
    ((float4*)(out + (size_t)row * Dc))[tid] = o4;
}

// ---------------------------------------------------------------------------
// Launch
// ---------------------------------------------------------------------------
extern "C" void kernel_launch(void* const* d_in, const int* in_sizes, int n_in,
                              void* d_out, int out_size)
{
    const float* Qin  = (const float*)d_in[0];
    const unsigned* mask = (const unsigned*)d_in[3];
    const float* Wq = (const float*)d_in[4];
    const float* bq = (const float*)d_in[5];
    const float* Wk = (const float*)d_in[6];
    const float* bk = (const float*)d_in[7];
    const float* Wv = (const float*)d_in[8];
    const float* bv = (const float*)d_in[9];
    const float* Wo = (const float*)d_in[10];
    const float* bo = (const float*)d_in[11];
    const float* ln_g = (const float*)d_in[12];
    const float* ln_b = (const float*)d_in[13];

    float* out  = (float*)d_out;
    float* attn = out + (size_t)Bc * Sc * Dc;

    cvt_x_kernel    <<<(Mc * Dc) / 1024, 256>>>(Qin);
    cvt_wT_kernel   <<<dim3(32, 32, 4), 256>>>(Wq, Wk, Wv, Wo);
    mask_pack_kernel<<<(Bc * Sc * (Sc / 32)) / 8, 256>>>(mask);

    proj_qk_tf32_kernel<<<dim3(Dc / 128, Mc / 128, 2), 256>>>(Qin, bq, bk);
    proj_v_mma_kernel  <<<dim3(Dc / 128, Mc / 128), 256>>>(bv);
    scores_tf32_kernel <<<dim3(Sc / 128, BHc), 256>>>(attn);
    av_mma_kernel      <<<dim3(Sc / 128, BHc), 256>>>(attn);
    oproj_mma_kernel   <<<dim3(Dc / 128, Mc / 128), 256>>>(bo, Qin);
    ln_kernel          <<<Mc, 256>>>(ln_g, ln_b, out);
}

// round 7
// speedup vs baseline: 2.7153x; 1.1076x over previous
#include <cuda_runtime.h>
#include <cuda_bf16.h>

#define Bc   2
#define Sc   2048
#define Dc   1024
#define Hc   16
#define DKc  64
#define Mc   (Bc * Sc)        // 4096
#define BHc  (Bc * Hc)        // 32

// ---------------------------------------------------------------------------
// Scratch (__device__ globals; no cudaMalloc allowed)
// ---------------------------------------------------------------------------
__device__ __align__(16) __nv_bfloat16 g_xb [(size_t)Mc * Dc];          // X bf16 (V path)
__device__ __align__(16) float         g_xtf[(size_t)Mc * Dc];          // X tf32-rounded (QK path)
__device__ __align__(16) __nv_bfloat16 g_wT [4][(size_t)Dc * Dc];       // bf16 W^T ([2],[3] used)
__device__ __align__(16) float         g_wTf[2][(size_t)Dc * Dc];       // tf32-rounded W^T (Wq,Wk)
__device__ __align__(16) float         g_qf [(size_t)BHc * Sc * DKc];   // q tf32-rounded [bh][s][dk]
__device__ __align__(16) float         g_kf [(size_t)BHc * Sc * DKc];   // k tf32-rounded [bh][s][dk]
__device__ __align__(16) __nv_bfloat16 g_vT [(size_t)BHc * DKc * Sc];   // v bf16 [bh][dk][s]
__device__ __align__(16) __nv_bfloat16 g_ctxb[(size_t)Mc * Dc];         // ctx bf16
__device__ unsigned g_mask[(size_t)Bc * Sc * (Sc / 32)];                 // bit-packed mask
__device__ __align__(16) float g_y [(size_t)Mc * Dc];                    // pre-LN

// ---------------------------------------------------------------------------
// MMA helpers
// ---------------------------------------------------------------------------
__device__ __forceinline__ void mma_bf16(
    float& c0, float& c1, float& c2, float& c3,
    unsigned a0, unsigned a1, unsigned a2, unsigned a3,
    unsigned b0, unsigned b1)
{
    asm volatile(
        "mma.sync.aligned.m16n8k16.row.col.f32.bf16.bf16.f32 "
        "{%0,%1,%2,%3}, {%4,%5,%6,%7}, {%8,%9}, {%0,%1,%2,%3};\n"
        : "+f"(c0), "+f"(c1), "+f"(c2), "+f"(c3)
        : "r"(a0), "r"(a1), "r"(a2), "r"(a3), "r"(b0), "r"(b1));
}

__device__ __forceinline__ void mma_tf32(
    float& c0, float& c1, float& c2, float& c3,
    unsigned a0, unsigned a1, unsigned a2, unsigned a3,
    unsigned b0, unsigned b1)
{
    asm volatile(
        "mma.sync.aligned.m16n8k8.row.col.f32.tf32.tf32.f32 "
        "{%0,%1,%2,%3}, {%4,%5,%6,%7}, {%8,%9}, {%0,%1,%2,%3};\n"
        : "+f"(c0), "+f"(c1), "+f"(c2), "+f"(c3)
        : "r"(a0), "r"(a1), "r"(a2), "r"(a3), "r"(b0), "r"(b1));
}

__device__ __forceinline__ float f2tf_f(float x)
{
    unsigned r;
    asm("cvt.rna.tf32.f32 %0, %1;" : "=r"(r) : "f"(x));
    return __uint_as_float(r);
}

// pack two floats into a bf16x2 register (lo = a, hi = b)
__device__ __forceinline__ unsigned pack_bf16x2(float a, float b)
{
    unsigned r;
    asm("cvt.rn.bf16x2.f32 %0, %1, %2;" : "=r"(r) : "f"(b), "f"(a));
    return r;
}

// ---------------------------------------------------------------------------
// Pre-pass: X fp32 -> bf16 (V path) + tf32-rounded fp32 (QK path)
// ---------------------------------------------------------------------------
__global__ __launch_bounds__(256) void cvt_x_kernel(const float* __restrict__ X)
{
    size_t i = ((size_t)blockIdx.x * 256 + threadIdx.x) * 4;
    float4 v = *(const float4*)(X + i);
    __nv_bfloat162* d = (__nv_bfloat162*)(g_xb + i);
    d[0] = __floats2bfloat162_rn(v.x, v.y);
    d[1] = __floats2bfloat162_rn(v.z, v.w);
    float4 tv = make_float4(f2tf_f(v.x), f2tf_f(v.y), f2tf_f(v.z), f2tf_f(v.w));
    *(float4*)(g_xtf + i) = tv;
}

// ---------------------------------------------------------------------------
// Pre-pass: weights [k][n] -> transposed [n][k]; tf32 for Wq/Wk, bf16 Wv/Wo
// ---------------------------------------------------------------------------
__global__ __launch_bounds__(256) void cvt_wT_kernel(
    const float* __restrict__ W0, const float* __restrict__ W1,
    const float* __restrict__ W2, const float* __restrict__ W3)
{
    const int z = blockIdx.z;
    const float* W = z == 0 ? W0 : z == 1 ? W1 : z == 2 ? W2 : W3;
    __shared__ float tile[32][33];
    const int tx = threadIdx.x & 31, ty = threadIdx.x >> 5;
    const int k0 = blockIdx.x * 32, n0 = blockIdx.y * 32;
    #pragma unroll
    for (int i = 0; i < 4; ++i)
        tile[ty + i * 8][tx] = W[(size_t)(k0 + ty + i * 8) * Dc + n0 + tx];
    __syncthreads();
    if (z < 2) {
        float* out = g_wTf[z];
        #pragma unroll
        for (int i = 0; i < 4; ++i)
            out[(size_t)(n0 + ty + i * 8) * Dc + k0 + tx] = f2tf_f(tile[tx][ty + i * 8]);
    } else {
        __nv_bfloat16* out = g_wT[z];
        #pragma unroll
        for (int i = 0; i < 4; ++i)
            out[(size_t)(n0 + ty + i * 8) * Dc + k0 + tx] =
                __float2bfloat16(tile[tx][ty + i * 8]);
    }
}

// ---------------------------------------------------------------------------
// Pre-pass: bit-pack mask (int32 nonzero -> 1 bit)
// ---------------------------------------------------------------------------
__global__ __launch_bounds__(256) void mask_pack_kernel(const unsigned* __restrict__ mask)
{
    const int w    = blockIdx.x * 8 + (threadIdx.x >> 5);
    const int lane = threadIdx.x & 31;
    unsigned v = mask[(size_t)w * 32 + lane];
    unsigned bits = __ballot_sync(0xffffffffu, v != 0);
    if (lane == 0) g_mask[w] = bits;
}

// ---------------------------------------------------------------------------
// Kernel 1a: q/k projections in tf32 (pre-rounded inputs, no cvt in loop,
// register-prefetch pipelined). Outputs stored tf32-rounded.
// ---------------------------------------------------------------------------
__global__ __launch_bounds__(256) void proj_qk_tf32_kernel(
    const float* __restrict__ bq, const float* __restrict__ bk)
{
    const int z = blockIdx.z;
    const float* Wt = g_wTf[z];
    const float* bias = z == 0 ? bq : bk;
    float* outp = z == 0 ? g_qf : g_kf;

    __shared__ __align__(16) float as[128][36];
    __shared__ __align__(16) float bs[128][36];

    const int tid  = threadIdx.x;
    const int warp = tid >> 5, lane = tid & 31;
    const int g = lane >> 2, t = lane & 3;
    const int wm = warp >> 1, wn = warp & 1;
    const int row0 = blockIdx.y * 128;
    const int col0 = blockIdx.x * 128;

    float c[2][8][4];
    #pragma unroll
    for (int mt = 0; mt < 2; ++mt)
        #pragma unroll
        for (int nt = 0; nt < 8; ++nt)
            #pragma unroll
            for (int q = 0; q < 4; ++q) c[mt][nt][q] = 0.f;

    float4 aR[4], bR[4];
    #pragma unroll
    for (int it = 0; it < 4; ++it) {
        int f = tid + it * 256;
        int r = f >> 3, c4 = (f & 7) * 4;
        aR[it] = *(const float4*)(g_xtf + (size_t)(row0 + r) * Dc + c4);
        bR[it] = *(const float4*)(Wt    + (size_t)(col0 + r) * Dc + c4);
    }
    #pragma unroll
    for (int it = 0; it < 4; ++it) {
        int f = tid + it * 256;
        int r = f >> 3, c4 = (f & 7) * 4;
        *(float4*)&as[r][c4] = aR[it];
        *(float4*)&bs[r][c4] = bR[it];
    }

    for (int kk = 0; kk < Dc; kk += 32) {
        __syncthreads();
        if (kk + 32 < Dc) {
            #pragma unroll
            for (int it = 0; it < 4; ++it) {
                int f = tid + it * 256;
                int r = f >> 3, c4 = (f & 7) * 4;
                aR[it] = *(const float4*)(g_xtf + (size_t)(row0 + r) * Dc + kk + 32 + c4);
                bR[it] = *(const float4*)(Wt    + (size_t)(col0 + r) * Dc + kk + 32 + c4);
            }
        }
        #pragma unroll
        for (int kf = 0; kf < 4; ++kf) {
            const int k0 = kf * 8;
            unsigned A[2][4];
            #pragma unroll
            for (int mt = 0; mt < 2; ++mt) {
                int r = wm * 32 + mt * 16 + g;
                A[mt][0] = __float_as_uint(as[r    ][k0 + t]);
                A[mt][1] = __float_as_uint(as[r + 8][k0 + t]);
                A[mt][2] = __float_as_uint(as[r    ][k0 + t + 4]);
                A[mt][3] = __float_as_uint(as[r + 8][k0 + t + 4]);
            }
            #pragma unroll
            for (int nt = 0; nt < 8; ++nt) {
                int n = wn * 64 + nt * 8 + g;
                unsigned b0 = __float_as_uint(bs[n][k0 + t]);
                unsigned b1 = __float_as_uint(bs[n][k0 + t + 4]);
                mma_tf32(c[0][nt][0], c[0][nt][1], c[0][nt][2], c[0][nt][3],
                         A[0][0], A[0][1], A[0][2], A[0][3], b0, b1);
                mma_tf32(c[1][nt][0], c[1][nt][1], c[1][nt][2], c[1][nt][3],
                         A[1][0], A[1][1], A[1][2], A[1][3], b0, b1);
            }
        }
        __syncthreads();
        if (kk + 32 < Dc) {
            #pragma unroll
            for (int it = 0; it < 4; ++it) {
                int f = tid + it * 256;
                int r = f >> 3, c4 = (f & 7) * 4;
                *(float4*)&as[r][c4] = aR[it];
                *(float4*)&bs[r][c4] = bR[it];
            }
        }
    }

    #pragma unroll
    for (int mt = 0; mt < 2; ++mt) {
        #pragma unroll
        for (int nt = 0; nt < 8; ++nt) {
            const int col = col0 + wn * 64 + nt * 8 + t * 2;
            const int h = col >> 6, dk = col & 63;
            const float bi0 = bias[col], bi1 = bias[col + 1];
            const int r0 = row0 + wm * 32 + mt * 16 + g;
            #pragma unroll
            for (int rr = 0; rr < 2; ++rr) {
                const int rowg = r0 + rr * 8;
                const int b = rowg >> 11, s = rowg & 2047;
                float* dst = outp + ((size_t)(b * Hc + h) * Sc + s) * DKc + dk;
                *(float2*)dst = make_float2(f2tf_f(c[mt][nt][rr * 2 + 0] + bi0),
                                            f2tf_f(c[mt][nt][rr * 2 + 1] + bi1));
            }
        }
    }
}

// ---------------------------------------------------------------------------
// Kernel 1b: v projection, bf16 MMA -> g_vT [bh][dk][s], prefetch pipelined.
// ---------------------------------------------------------------------------
__global__ __launch_bounds__(256) void proj_v_mma_kernel(const float* __restrict__ bv)
{
    const __nv_bfloat16* Wt = g_wT[2];

    __shared__ __align__(16) __nv_bfloat16 as[128][40];
    __shared__ __align__(16) __nv_bfloat16 bs[128][40];

    const int tid  = threadIdx.x;
    const int warp = tid >> 5, lane = tid & 31;
    const int g = lane >> 2, t = lane & 3;
    const int wm = warp >> 1, wn = warp & 1;
    const int row0 = blockIdx.y * 128;
    const int col0 = blockIdx.x * 128;

    float c[2][8][4];
    #pragma unroll
    for (int mt = 0; mt < 2; ++mt)
        #pragma unroll
        for (int nt = 0; nt < 8; ++nt)
            #pragma unroll
            for (int q = 0; q < 4; ++q) c[mt][nt][q] = 0.f;

    uint4 aR[2], bR[2];
    #pragma unroll
    for (int it = 0; it < 2; ++it) {
        int f = tid + it * 256;
        int r = f >> 2, c8 = (f & 3) * 8;
        aR[it] = *(const uint4*)(g_xb + (size_t)(row0 + r) * Dc + c8);
        bR[it] = *(const uint4*)(Wt   + (size_t)(col0 + r) * Dc + c8);
    }
    #pragma unroll
    for (int it = 0; it < 2; ++it) {
        int f = tid + it * 256;
        int r = f >> 2, c8 = (f & 3) * 8;
        *(uint4*)&as[r][c8] = aR[it];
        *(uint4*)&bs[r][c8] = bR[it];
    }

    for (int kk = 0; kk < Dc; kk += 32) {
        __syncthreads();
        if (kk + 32 < Dc) {
            #pragma unroll
            for (int it = 0; it < 2; ++it) {
                int f = tid + it * 256;
                int r = f >> 2, c8 = (f & 3) * 8;
                aR[it] = *(const uint4*)(g_xb + (size_t)(row0 + r) * Dc + kk + 32 + c8);
                bR[it] = *(const uint4*)(Wt   + (size_t)(col0 + r) * Dc + kk + 32 + c8);
            }
        }
        #pragma unroll
        for (int kf = 0; kf < 2; ++kf) {
            const int k0 = kf * 16;
            unsigned A[2][4];
            #pragma unroll
            for (int mt = 0; mt < 2; ++mt) {
                int r = wm * 32 + mt * 16 + g;
                A[mt][0] = *(const unsigned*)&as[r    ][k0     + t * 2];
                A[mt][1] = *(const unsigned*)&as[r + 8][k0     + t * 2];
                A[mt][2] = *(const unsigned*)&as[r    ][k0 + 8 + t * 2];
                A[mt][3] = *(const unsigned*)&as[r + 8][k0 + 8 + t * 2];
            }
            #pragma unroll
            for (int nt = 0; nt < 8; ++nt) {
                int n = wn * 64 + nt * 8 + g;
                unsigned b0 = *(const unsigned*)&bs[n][k0     + t * 2];
                unsigned b1 = *(const unsigned*)&bs[n][k0 + 8 + t * 2];
                mma_bf16(c[0][nt][0], c[0][nt][1], c[0][nt][2], c[0][nt][3],
                         A[0][0], A[0][1], A[0][2], A[0][3], b0, b1);
                mma_bf16(c[1][nt][0], c[1][nt][1], c[1][nt][2], c[1][nt][3],
                         A[1][0], A[1][1], A[1][2], A[1][3], b0, b1);
            }
        }
        __syncthreads();
        if (kk + 32 < Dc) {
            #pragma unroll
            for (int it = 0; it < 2; ++it) {
                int f = tid + it * 256;
                int r = f >> 2, c8 = (f & 3) * 8;
                *(uint4*)&as[r][c8] = aR[it];
                *(uint4*)&bs[r][c8] = bR[it];
            }
        }
    }

    #pragma unroll
    for (int mt = 0; mt < 2; ++mt) {
        #pragma unroll
        for (int nt = 0; nt < 8; ++nt) {
            const int col = col0 + wn * 64 + nt * 8 + t * 2;
            const int h = col >> 6, dk = col & 63;
            const float bi0 = bv[col], bi1 = bv[col + 1];
            const int r0 = row0 + wm * 32 + mt * 16 + g;
            #pragma unroll
            for (int rr = 0; rr < 2; ++rr) {
                const int rowg = r0 + rr * 8;
                const int b = rowg >> 11, s = rowg & 2047;
                g_vT[((size_t)(b * Hc + h) * DKc + dk    ) * Sc + s] =
                    __float2bfloat16(c[mt][nt][rr * 2 + 0] + bi0);
                g_vT[((size_t)(b * Hc + h) * DKc + dk + 1) * Sc + s] =
                    __float2bfloat16(c[mt][nt][rr * 2 + 1] + bi1);
            }
        }
    }
}

// ---------------------------------------------------------------------------
// Kernel 2: FUSED attention. Two passes over K:
//   pass 1: s = q.k^T (tf32), e = exp(0.125 s) masked, accumulate row sums.
//   pass 2: recompute e, p = e/l, write p (the attn output), and feed p
//           directly from MMA C-fragments into bf16 A-fragments for p @ V.
// ---------------------------------------------------------------------------
__global__ __launch_bounds__(256) void attn_fused_kernel(float* __restrict__ attn)
{
    const int bh = blockIdx.y;
    const int i0 = blockIdx.x * 128;
    const int b  = bh >> 4, h = bh & 15;

    // smem: phase A: qs[128][68] f32 (34816 B). main: ks[64][68] f32 (17408 B)
    // + vs[64][72] bf16 (9216 B) at offset 17408.
    __shared__ __align__(16) unsigned char sbuf[34816];
    float (*qs)[68] = (float (*)[68])sbuf;
    float (*ks)[68] = (float (*)[68])sbuf;
    __nv_bfloat16 (*vs)[72] = (__nv_bfloat16 (*)[72])(sbuf + 17408);

    const int tid = threadIdx.x, warp = tid >> 5, lane = tid & 31;
    const int g = lane >> 2, t = lane & 3;

    const float* qbase = g_qf + ((size_t)bh * Sc + i0) * DKc;
    const float* kbase = g_kf + (size_t)bh * Sc * DKc;
    const __nv_bfloat16* vbase = g_vT + (size_t)bh * DKc * Sc;

    #pragma unroll
    for (int it = 0; it < 8; ++it) {
        int f = tid + it * 256;
        int r = f >> 4, c4 = (f & 15) * 4;
        *(float4*)&qs[r][c4] = *(const float4*)(qbase + (size_t)r * DKc + c4);
    }
    __syncthreads();

    unsigned A[8][4];
    {
        const int r = warp * 16 + g;
        #pragma unroll
        for (int kf = 0; kf < 8; ++kf) {
            const int k0 = kf * 8;
            A[kf][0] = __float_as_uint(qs[r    ][k0 + t]);
            A[kf][1] = __float_as_uint(qs[r + 8][k0 + t]);
            A[kf][2] = __float_as_uint(qs[r    ][k0 + t + 4]);
            A[kf][3] = __float_as_uint(qs[r + 8][k0 + t + 4]);
        }
    }

    const int ig0 = i0 + warp * 16 + g;
    const int ig1 = ig0 + 8;
    const unsigned* mp0 = g_mask + ((size_t)b * Sc + ig0) * (Sc / 32);
    const unsigned* mp1 = g_mask + ((size_t)b * Sc + ig1) * (Sc / 32);
    float* arow0 = attn + ((size_t)bh * Sc + ig0) * Sc;
    float* arow1 = attn + ((size_t)bh * Sc + ig1) * Sc;

    // ---------------- pass 1: row sums only ----------------
    float rsum0 = 0.f, rsum1 = 0.f;
    for (int jj = 0; jj < Sc; jj += 64) {
        __syncthreads();
        #pragma unroll
        for (int it = 0; it < 4; ++it) {
            int f = tid + it * 256;
            int r = f >> 4, c4 = (f & 15) * 4;
            *(float4*)&ks[r][c4] = *(const float4*)(kbase + (size_t)(jj + r) * DKc + c4);
        }
        __syncthreads();

        float c[8][4];
        #pragma unroll
        for (int nt = 0; nt < 8; ++nt)
            #pragma unroll
            for (int q = 0; q < 4; ++q) c[nt][q] = 0.f;
        #pragma unroll
        for (int kf = 0; kf < 8; ++kf) {
            const int k0 = kf * 8;
            #pragma unroll
            for (int nt = 0; nt < 8; ++nt) {
                unsigned b0 = __float_as_uint(ks[nt * 8 + g][k0 + t]);
                unsigned b1 = __float_as_uint(ks[nt * 8 + g][k0 + t + 4]);
                mma_tf32(c[nt][0], c[nt][1], c[nt][2], c[nt][3],
                         A[kf][0], A[kf][1], A[kf][2], A[kf][3], b0, b1);
            }
        }

        const unsigned m00 = mp0[jj >> 5], m01 = mp0[(jj >> 5) + 1];
        const unsigned m10 = mp1[jj >> 5], m11 = mp1[(jj >> 5) + 1];
        #pragma unroll
        for (int nt = 0; nt < 8; ++nt) {
            const int jl = nt * 8 + t * 2;
            const unsigned w0 = (jl & 32) ? m01 : m00;
            const unsigned w1 = (jl & 32) ? m11 : m10;
            const int sh = jl & 31;
            rsum0 += (((w0 >> sh)       & 1u) ? 0.f : __expf(c[nt][0] * 0.125f))
                   + (((w0 >> (sh + 1)) & 1u) ? 0.f : __expf(c[nt][1] * 0.125f));
            rsum1 += (((w1 >> sh)       & 1u) ? 0.f : __expf(c[nt][2] * 0.125f))
                   + (((w1 >> (sh + 1)) & 1u) ? 0.f : __expf(c[nt][3] * 0.125f));
        }
    }
    rsum0 += __shfl_xor_sync(0xffffffffu, rsum0, 1);
    rsum0 += __shfl_xor_sync(0xffffffffu, rsum0, 2);
    rsum1 += __shfl_xor_sync(0xffffffffu, rsum1, 1);
    rsum1 += __shfl_xor_sync(0xffffffffu, rsum1, 2);
    const float invl0 = 1.0f / rsum0;
    const float invl1 = 1.0f / rsum1;

    // ---------------- pass 2: write p, accumulate ctx = p @ V ----------------
    float ctx[8][4];
    #pragma unroll
    for (int nt = 0; nt < 8; ++nt)
        #pragma unroll
        for (int q = 0; q < 4; ++q) ctx[nt][q] = 0.f;

    for (int jj = 0; jj < Sc; jj += 64) {
        __syncthreads();
        #pragma unroll
        for (int it = 0; it < 4; ++it) {
            int f = tid + it * 256;
            int r = f >> 4, c4 = (f & 15) * 4;
            *(float4*)&ks[r][c4] = *(const float4*)(kbase + (size_t)(jj + r) * DKc + c4);
        }
        #pragma unroll
        for (int it = 0; it < 2; ++it) {
            int f = tid + it * 256;
            int dk = f >> 3, c8 = (f & 7) * 8;
            *(uint4*)&vs[dk][c8] = *(const uint4*)(vbase + (size_t)dk * Sc + jj + c8);
        }
        __syncthreads();

        float c[8][4];
        #pragma unroll
        for (int nt = 0; nt < 8; ++nt)
            #pragma unroll
            for (int q = 0; q < 4; ++q) c[nt][q] = 0.f;
        #pragma unroll
        for (int kf = 0; kf < 8; ++kf) {
            const int k0 = kf * 8;
            #pragma unroll
            for (int nt = 0; nt < 8; ++nt) {
                unsigned b0 = __float_as_uint(ks[nt * 8 + g][k0 + t]);
                unsigned b1 = __float_as_uint(ks[nt * 8 + g][k0 + t + 4]);
                mma_tf32(c[nt][0], c[nt][1], c[nt][2], c[nt][3],
                         A[kf][0], A[kf][1], A[kf][2], A[kf][3], b0, b1);
            }
        }

        const unsigned m00 = mp0[jj >> 5], m01 = mp0[(jj >> 5) + 1];
        const unsigned m10 = mp1[jj >> 5], m11 = mp1[(jj >> 5) + 1];

        unsigned pf[8][2];   // bf16x2 A-fragments of p
        #pragma unroll
        for (int nt = 0; nt < 8; ++nt) {
            const int jl = nt * 8 + t * 2;
            const unsigned w0 = (jl & 32) ? m01 : m00;
            const unsigned w1 = (jl & 32) ? m11 : m10;
            const int sh = jl & 31;
            float p0 = ((w0 >> sh)       & 1u) ? 0.f : __expf(c[nt][0] * 0.125f) * invl0;
            float p1 = ((w0 >> (sh + 1)) & 1u) ? 0.f : __expf(c[nt][1] * 0.125f) * invl0;
            float p2 = ((w1 >> sh)       & 1u) ? 0.f : __expf(c[nt][2] * 0.125f) * invl1;
            float p3 = ((w1 >> (sh + 1)) & 1u) ? 0.f : __expf(c[nt][3] * 0.125f) * invl1;
            *(float2*)(arow0 + jj + jl) = make_float2(p0, p1);
            *(float2*)(arow1 + jj + jl) = make_float2(p2, p3);
            pf[nt][0] = pack_bf16x2(p0, p1);
            pf[nt][1] = pack_bf16x2(p2, p3);
        }

        #pragma unroll
        for (int kf = 0; kf < 4; ++kf) {
            const unsigned a0 = pf[2 * kf    ][0];
            const unsigned a1 = pf[2 * kf    ][1];
            const unsigned a2 = pf[2 * kf + 1][0];
            const unsigned a3 = pf[2 * kf + 1][1];
            const int k0 = kf * 16;
            #pragma unroll
            for (int nt = 0; nt < 8; ++nt) {
                unsigned b0 = *(const unsigned*)&vs[nt * 8 + g][k0     + t * 2];
                unsigned b1 = *(const unsigned*)&vs[nt * 8 + g][k0 + 8 + t * 2];
                mma_bf16(ctx[nt][0], ctx[nt][1], ctx[nt][2], ctx[nt][3],
                         a0, a1, a2, a3, b0, b1);
            }
        }
    }

    const int s = i0 + warp * 16 + g;
    const size_t crow0 = ((size_t)b * Sc + s)     * Dc;
    const size_t crow1 = ((size_t)b * Sc + s + 8) * Dc;
    #pragma unroll
    for (int nt = 0; nt < 8; ++nt) {
        const int col = h * DKc + nt * 8 + t * 2;
        *(__nv_bfloat162*)&g_ctxb[crow0 + col] = __floats2bfloat162_rn(ctx[nt][0], ctx[nt][1]);
        *(__nv_bfloat162*)&g_ctxb[crow1 + col] = __floats2bfloat162_rn(ctx[nt][2], ctx[nt][3]);
    }
}

// ---------------------------------------------------------------------------
// Kernel 3: output projection, bf16 MMA, prefetch pipelined.
// ---------------------------------------------------------------------------
__global__ __launch_bounds__(256) void oproj_mma_kernel(
    const float* __restrict__ bo, const float* __restrict__ Qres)
{
    const __nv_bfloat16* Wt = g_wT[3];

    __shared__ __align__(16) __nv_bfloat16 as[128][40];
    __shared__ __align__(16) __nv_bfloat16 bs[128][40];

    const int tid  = threadIdx.x;
    const int warp = tid >> 5, lane = tid & 31;
    const int g = lane >> 2, t = lane & 3;
    const int wm = warp >> 1, wn = warp & 1;
    const int row0 = blockIdx.y * 128;
    const int col0 = blockIdx.x * 128;

    float c[2][8][4];
    #pragma unroll
    for (int mt = 0; mt < 2; ++mt)
        #pragma unroll
        for (int nt = 0; nt < 8; ++nt)
            #pragma unroll
            for (int q = 0; q < 4; ++q) c[mt][nt][q] = 0.f;

    uint4 aR[2], bR[2];
    #pragma unroll
    for (int it = 0; it < 2; ++it) {
        int f = tid + it * 256;
        int r = f >> 2, c8 = (f & 3) * 8;
        aR[it] = *(const uint4*)(g_ctxb + (size_t)(row0 + r) * Dc + c8);
        bR[it] = *(const uint4*)(Wt     + (size_t)(col0 + r) * Dc + c8);
    }
    #pragma unroll
    for (int it = 0; it < 2; ++it) {
        int f = tid + it * 256;
        int r = f >> 2, c8 = (f & 3) * 8;
        *(uint4*)&as[r][c8] = aR[it];
        *(uint4*)&bs[r][c8] = bR[it];
    }

    for (int kk = 0; kk < Dc; kk += 32) {
        __syncthreads();
        if (kk + 32 < Dc) {
            #pragma unroll
            for (int it = 0; it < 2; ++it) {
                int f = tid + it * 256;
                int r = f >> 2, c8 = (f & 3) * 8;
                aR[it] = *(const uint4*)(g_ctxb + (size_t)(row0 + r) * Dc + kk + 32 + c8);
                bR[it] = *(const uint4*)(Wt     + (size_t)(col0 + r) * Dc + kk + 32 + c8);
            }
        }
        #pragma unroll
        for (int kf = 0; kf < 2; ++kf) {
            const int k0 = kf * 16;
            unsigned A[2][4];
            #pragma unroll
            for (int mt = 0; mt < 2; ++mt) {
                int r = wm * 32 + mt * 16 + g;
                A[mt][0] = *(const unsigned*)&as[r    ][k0     + t * 2];
                A[mt][1] = *(const unsigned*)&as[r + 8][k0     + t * 2];
                A[mt][2] = *(const unsigned*)&as[r    ][k0 + 8 + t * 2];
                A[mt][3] = *(const unsigned*)&as[r + 8][k0 + 8 + t * 2];
            }
            #pragma unroll
            for (int nt = 0; nt < 8; ++nt) {
                int n = wn * 64 + nt * 8 + g;
                unsigned b0 = *(const unsigned*)&bs[n][k0     + t * 2];
                unsigned b1 = *(const unsigned*)&bs[n][k0 + 8 + t * 2];
                mma_bf16(c[0][nt][0], c[0][nt][1], c[0][nt][2], c[0][nt][3],
                         A[0][0], A[0][1], A[0][2], A[0][3], b0, b1);
                mma_bf16(c[1][nt][0], c[1][nt][1], c[1][nt][2], c[1][nt][3],
                         A[1][0], A[1][1], A[1][2], A[1][3], b0, b1);
            }
        }
        __syncthreads();
        if (kk + 32 < Dc) {
            #pragma unroll
            for (int it = 0; it < 2; ++it) {
                int f = tid + it * 256;
                int r = f >> 2, c8 = (f & 3) * 8;
                *(uint4*)&as[r][c8] = aR[it];
                *(uint4*)&bs[r][c8] = bR[it];
            }
        }
    }

    #pragma unroll
    for (int mt = 0; mt < 2; ++mt) {
        #pragma unroll
        for (int nt = 0; nt < 8; ++nt) {
            const int col = col0 + wn * 64 + nt * 8 + t * 2;
            const float bi0 = bo[col], bi1 = bo[col + 1];
            const int r0 = row0 + wm * 32 + mt * 16 + g;
            #pragma unroll
            for (int rr = 0; rr < 2; ++rr) {
                const int rowg = r0 + rr * 8;
                const float* res = Qres + (size_t)rowg * Dc + col;
                float2 rv = *(const float2*)res;
                float2 o = make_float2(c[mt][nt][rr * 2 + 0] + bi0 + rv.x,
                                       c[mt][nt][rr * 2 + 1] + bi1 + rv.y);
                *(float2*)(g_y + (size_t)rowg * Dc + col) = o;
            }
        }
    }
}

// ---------------------------------------------------------------------------
// Kernel 4: LayerNorm per row (fp32).
// ---------------------------------------------------------------------------
__global__ __launch_bounds__(256) void ln_kernel(
    const float* __restrict__ gamma, const float* __restrict__ beta,
    float* __restrict__ out)
{
    const int row = blockIdx.x;
    const int tid = threadIdx.x;
    const float* y = g_y + (size_t)row * Dc;

    float4 v = ((const float4*)y)[tid];
    float s  = v.x + v.y + v.z + v.w;
    float q  = v.x * v.x + v.y * v.y + v.z * v.z + v.w * v.w;

    __shared__ float ss[8];
    __shared__ float sq[8];
    #pragma unroll
    for (int o = 16; o > 0; o >>= 1) {
        s += __shfl_xor_sync(0xffffffffu, s, o);
        q += __shfl_xor_sync(0xffffffffu, q, o);
    }
    if ((tid & 31) == 0) { ss[tid >> 5] = s; sq[tid >> 5] = q; }
    __syncthreads();
    s = ss[tid & 7];
    q = sq[tid & 7];
    #pragma unroll
    for (int o = 4; o > 0; o >>= 1) {
        s += __shfl_xor_sync(0xffffffffu, s, o);
        q += __shfl_xor_sync(0xffffffffu, q, o);
    }

    const float mu  = s * (1.0f / Dc);
    const float var = q * (1.0f / Dc) - mu * mu;
    const float inv = rsqrtf(var + 1e-5f);

    float4 gv = ((const float4*)gamma)[tid];
    float4 bv = ((const float4*)beta)[tid];
    float4 o4 = make_float4((v.x - mu) * inv * gv.x + bv.x,
                            (v.y - mu) * inv * gv.y + bv.y,
                            (v.z - mu) * inv * gv.z + bv.z,
                            (v.w - mu) * inv * gv.w + bv.w);
    ((float4*)(out + (size_t)row * Dc))[tid] = o4;
}

// ---------------------------------------------------------------------------
// Launch
// ---------------------------------------------------------------------------
extern "C" void kernel_launch(void* const* d_in, const int* in_sizes, int n_in,
                              void* d_out, int out_size)
{
    const float* Qin  = (const float*)d_in[0];
    const unsigned* mask = (const unsigned*)d_in[3];
    const float* Wq = (const float*)d_in[4];
    const float* bq = (const float*)d_in[5];
    const float* Wk = (const float*)d_in[6];
    const float* bk = (const float*)d_in[7];
    const float* Wv = (const float*)d_in[8];
    const float* bv = (const float*)d_in[9];
    const float* Wo = (const float*)d_in[10];
    const float* bo = (const float*)d_in[11];
    const float* ln_g = (const float*)d_in[12];
    const float* ln_b = (const float*)d_in[13];

    float* out  = (float*)d_out;
    float* attn = out + (size_t)Bc * Sc * Dc;

    cvt_x_kernel    <<<(Mc * Dc) / 1024, 256>>>(Qin);
    cvt_wT_kernel   <<<dim3(32, 32, 4), 256>>>(Wq, Wk, Wv, Wo);
    mask_pack_kernel<<<(Bc * Sc * (Sc / 32)) / 8, 256>>>(mask);

    proj_qk_tf32_kernel<<<dim3(Dc / 128, Mc / 128, 2), 256>>>(bq, bk);
    proj_v_mma_kernel  <<<dim3(Dc / 128, Mc / 128), 256>>>(bv);
    attn_fused_kernel  <<<dim3(Sc / 128, BHc), 256>>>(attn);
    oproj_mma_kernel   <<<dim3(Dc / 128, Mc / 128), 256>>>(bo, Qin);
    ln_kernel          <<<Mc, 256>>>(ln_g, ln_b, out);
}

// round 8
// speedup vs baseline: 2.8308x; 1.0425x over previous
#include <cuda_runtime.h>
#include <cuda_bf16.h>

#define Bc   2
#define Sc   2048
#define Dc   1024
#define Hc   16
#define DKc  64
#define Mc   (Bc * Sc)        // 4096
#define BHc  (Bc * Hc)        // 32

// ---------------------------------------------------------------------------
// Scratch (__device__ globals; no cudaMalloc allowed)
// ---------------------------------------------------------------------------
__device__ __align__(16) __nv_bfloat16 g_xb [(size_t)Mc * Dc];          // X bf16 (V path)
__device__ __align__(16) float         g_xtf[(size_t)Mc * Dc];          // X tf32-rounded (QK path)
__device__ __align__(16) __nv_bfloat16 g_wT [4][(size_t)Dc * Dc];       // bf16 W^T ([2],[3] used)
__device__ __align__(16) float         g_wTf[2][(size_t)Dc * Dc];       // tf32-rounded W^T (Wq,Wk)
__device__ __align__(16) float         g_qf [(size_t)BHc * Sc * DKc];   // q tf32-rounded [bh][s][dk]
__device__ __align__(16) float         g_kf [(size_t)BHc * Sc * DKc];   // k tf32-rounded [bh][s][dk]
__device__ __align__(16) __nv_bfloat16 g_vT [(size_t)BHc * DKc * Sc];   // v bf16 [bh][dk][s]
__device__ __align__(16) __nv_bfloat16 g_ctxb[(size_t)Mc * Dc];         // ctx bf16
__device__ unsigned g_mask[(size_t)Bc * Sc * (Sc / 32)];                 // bit-packed mask
__device__ __align__(16) float g_y [(size_t)Mc * Dc];                    // pre-LN

// ---------------------------------------------------------------------------
// MMA + async-copy helpers
// ---------------------------------------------------------------------------
__device__ __forceinline__ void mma_bf16(
    float& c0, float& c1, float& c2, float& c3,
    unsigned a0, unsigned a1, unsigned a2, unsigned a3,
    unsigned b0, unsigned b1)
{
    asm volatile(
        "mma.sync.aligned.m16n8k16.row.col.f32.bf16.bf16.f32 "
        "{%0,%1,%2,%3}, {%4,%5,%6,%7}, {%8,%9}, {%0,%1,%2,%3};\n"
        : "+f"(c0), "+f"(c1), "+f"(c2), "+f"(c3)
        : "r"(a0), "r"(a1), "r"(a2), "r"(a3), "r"(b0), "r"(b1));
}

__device__ __forceinline__ void mma_tf32(
    float& c0, float& c1, float& c2, float& c3,
    unsigned a0, unsigned a1, unsigned a2, unsigned a3,
    unsigned b0, unsigned b1)
{
    asm volatile(
        "mma.sync.aligned.m16n8k8.row.col.f32.tf32.tf32.f32 "
        "{%0,%1,%2,%3}, {%4,%5,%6,%7}, {%8,%9}, {%0,%1,%2,%3};\n"
        : "+f"(c0), "+f"(c1), "+f"(c2), "+f"(c3)
        : "r"(a0), "r"(a1), "r"(a2), "r"(a3), "r"(b0), "r"(b1));
}

__device__ __forceinline__ float f2tf_f(float x)
{
    unsigned r;
    asm("cvt.rna.tf32.f32 %0, %1;" : "=r"(r) : "f"(x));
    return __uint_as_float(r);
}

// pack two floats into a bf16x2 register (lo = a, hi = b)
__device__ __forceinline__ unsigned pack_bf16x2(float a, float b)
{
    unsigned r;
    asm("cvt.rn.bf16x2.f32 %0, %1, %2;" : "=r"(r) : "f"(b), "f"(a));
    return r;
}

__device__ __forceinline__ void cp16(void* smem, const void* gmem)
{
    unsigned sa = (unsigned)__cvta_generic_to_shared(smem);
    asm volatile("cp.async.cg.shared.global [%0], [%1], 16;\n"
                 :: "r"(sa), "l"(gmem));
}
__device__ __forceinline__ void cp_commit()
{
    asm volatile("cp.async.commit_group;\n");
}
template<int N> __device__ __forceinline__ void cp_wait()
{
    asm volatile("cp.async.wait_group %0;\n" :: "n"(N));
}

// ---------------------------------------------------------------------------
// Pre-pass: X fp32 -> bf16 (V path) + tf32-rounded fp32 (QK path)
// ---------------------------------------------------------------------------
__global__ __launch_bounds__(256) void cvt_x_kernel(const float* __restrict__ X)
{
    size_t i = ((size_t)blockIdx.x * 256 + threadIdx.x) * 4;
    float4 v = *(const float4*)(X + i);
    __nv_bfloat162* d = (__nv_bfloat162*)(g_xb + i);
    d[0] = __floats2bfloat162_rn(v.x, v.y);
    d[1] = __floats2bfloat162_rn(v.z, v.w);
    float4 tv = make_float4(f2tf_f(v.x), f2tf_f(v.y), f2tf_f(v.z), f2tf_f(v.w));
    *(float4*)(g_xtf + i) = tv;
}

// ---------------------------------------------------------------------------
// Pre-pass: weights [k][n] -> transposed [n][k]; tf32 for Wq/Wk, bf16 Wv/Wo
// ---------------------------------------------------------------------------
__global__ __launch_bounds__(256) void cvt_wT_kernel(
    const float* __restrict__ W0, const float* __restrict__ W1,
    const float* __restrict__ W2, const float* __restrict__ W3)
{
    const int z = blockIdx.z;
    const float* W = z == 0 ? W0 : z == 1 ? W1 : z == 2 ? W2 : W3;
    __shared__ float tile[32][33];
    const int tx = threadIdx.x & 31, ty = threadIdx.x >> 5;
    const int k0 = blockIdx.x * 32, n0 = blockIdx.y * 32;
    #pragma unroll
    for (int i = 0; i < 4; ++i)
        tile[ty + i * 8][tx] = W[(size_t)(k0 + ty + i * 8) * Dc + n0 + tx];
    __syncthreads();
    if (z < 2) {
        float* out = g_wTf[z];
        #pragma unroll
        for (int i = 0; i < 4; ++i)
            out[(size_t)(n0 + ty + i * 8) * Dc + k0 + tx] = f2tf_f(tile[tx][ty + i * 8]);
    } else {
        __nv_bfloat16* out = g_wT[z];
        #pragma unroll
        for (int i = 0; i < 4; ++i)
            out[(size_t)(n0 + ty + i * 8) * Dc + k0 + tx] =
                __float2bfloat16(tile[tx][ty + i * 8]);
    }
}

// ---------------------------------------------------------------------------
// Pre-pass: bit-pack mask (int32 nonzero -> 1 bit)
// ---------------------------------------------------------------------------
__global__ __launch_bounds__(256) void mask_pack_kernel(const unsigned* __restrict__ mask)
{
    const int w    = blockIdx.x * 8 + (threadIdx.x >> 5);
    const int lane = threadIdx.x & 31;
    unsigned v = mask[(size_t)w * 32 + lane];
    unsigned bits = __ballot_sync(0xffffffffu, v != 0);
    if (lane == 0) g_mask[w] = bits;
}

// ---------------------------------------------------------------------------
// Kernel 1a: q/k projections, tf32, cp.async 2-stage, BK=16.
// ---------------------------------------------------------------------------
__global__ __launch_bounds__(256) void proj_qk_tf32_kernel(
    const float* __restrict__ bq, const float* __restrict__ bk)
{
    const int z = blockIdx.z;
    const float* Wt = g_wTf[z];
    const float* bias = z == 0 ? bq : bk;
    float* outp = z == 0 ? g_qf : g_kf;

    __shared__ __align__(16) float as[2][128][20];   // 80B row stride
    __shared__ __align__(16) float bs[2][128][20];

    const int tid  = threadIdx.x;
    const int warp = tid >> 5, lane = tid & 31;
    const int g = lane >> 2, t = lane & 3;
    const int wm = warp >> 1, wn = warp & 1;
    const int row0 = blockIdx.y * 128;
    const int col0 = blockIdx.x * 128;

    const int lr = tid >> 2;            // 0..63? no: f>>2 over f in [0,512)
    float c[2][8][4];
    #pragma unroll
    for (int mt = 0; mt < 2; ++mt)
        #pragma unroll
        for (int nt = 0; nt < 8; ++nt)
            #pragma unroll
            for (int q = 0; q < 4; ++q) c[mt][nt][q] = 0.f;
    (void)lr;

    // stage loader: 128 rows x 16 floats = 512 chunks of 16B per array
    auto load_stage = [&](int kk, int st) {
        #pragma unroll
        for (int it = 0; it < 2; ++it) {
            int f = tid + it * 256;
            int r = f >> 2, c4 = (f & 3) * 4;
            cp16(&as[st][r][c4], g_xtf + (size_t)(row0 + r) * Dc + kk + c4);
            cp16(&bs[st][r][c4], Wt    + (size_t)(col0 + r) * Dc + kk + c4);
        }
        cp_commit();
    };

    load_stage(0, 0);

    const int nT = Dc / 16;   // 64
    for (int tt = 0; tt < nT; ++tt) {
        const int cur = tt & 1;
        if (tt + 1 < nT) { load_stage((tt + 1) * 16, cur ^ 1); cp_wait<1>(); }
        else             { cp_wait<0>(); }
        __syncthreads();

        #pragma unroll
        for (int kf = 0; kf < 2; ++kf) {
            const int k0 = kf * 8;
            unsigned A[2][4];
            #pragma unroll
            for (int mt = 0; mt < 2; ++mt) {
                int r = wm * 32 + mt * 16 + g;
                A[mt][0] = __float_as_uint(as[cur][r    ][k0 + t]);
                A[mt][1] = __float_as_uint(as[cur][r + 8][k0 + t]);
                A[mt][2] = __float_as_uint(as[cur][r    ][k0 + t + 4]);
                A[mt][3] = __float_as_uint(as[cur][r + 8][k0 + t + 4]);
            }
            #pragma unroll
            for (int nt = 0; nt < 8; ++nt) {
                int n = wn * 64 + nt * 8 + g;
                unsigned b0 = __float_as_uint(bs[cur][n][k0 + t]);
                unsigned b1 = __float_as_uint(bs[cur][n][k0 + t + 4]);
                mma_tf32(c[0][nt][0], c[0][nt][1], c[0][nt][2], c[0][nt][3],
                         A[0][0], A[0][1], A[0][2], A[0][3], b0, b1);
                mma_tf32(c[1][nt][0], c[1][nt][1], c[1][nt][2], c[1][nt][3],
                         A[1][0], A[1][1], A[1][2], A[1][3], b0, b1);
            }
        }
        __syncthreads();
    }

    #pragma unroll
    for (int mt = 0; mt < 2; ++mt) {
        #pragma unroll
        for (int nt = 0; nt < 8; ++nt) {
            const int col = col0 + wn * 64 + nt * 8 + t * 2;
            const int h = col >> 6, dk = col & 63;
            const float bi0 = bias[col], bi1 = bias[col + 1];
            const int r0 = row0 + wm * 32 + mt * 16 + g;
            #pragma unroll
            for (int rr = 0; rr < 2; ++rr) {
                const int rowg = r0 + rr * 8;
                const int b = rowg >> 11, s = rowg & 2047;
                float* dst = outp + ((size_t)(b * Hc + h) * Sc + s) * DKc + dk;
                *(float2*)dst = make_float2(f2tf_f(c[mt][nt][rr * 2 + 0] + bi0),
                                            f2tf_f(c[mt][nt][rr * 2 + 1] + bi1));
            }
        }
    }
}

// ---------------------------------------------------------------------------
// Kernel 1b: v projection, bf16 MMA, cp.async 2-stage, BK=32.
// ---------------------------------------------------------------------------
__global__ __launch_bounds__(256) void proj_v_mma_kernel(const float* __restrict__ bv)
{
    const __nv_bfloat16* Wt = g_wT[2];

    __shared__ __align__(16) __nv_bfloat16 as[2][128][40];   // 80B row stride
    __shared__ __align__(16) __nv_bfloat16 bs[2][128][40];

    const int tid  = threadIdx.x;
    const int warp = tid >> 5, lane = tid & 31;
    const int g = lane >> 2, t = lane & 3;
    const int wm = warp >> 1, wn = warp & 1;
    const int row0 = blockIdx.y * 128;
    const int col0 = blockIdx.x * 128;

    float c[2][8][4];
    #pragma unroll
    for (int mt = 0; mt < 2; ++mt)
        #pragma unroll
        for (int nt = 0; nt < 8; ++nt)
            #pragma unroll
            for (int q = 0; q < 4; ++q) c[mt][nt][q] = 0.f;

    auto load_stage = [&](int kk, int st) {
        #pragma unroll
        for (int it = 0; it < 2; ++it) {
            int f = tid + it * 256;
            int r = f >> 2, c8 = (f & 3) * 8;
            cp16(&as[st][r][c8], g_xb + (size_t)(row0 + r) * Dc + kk + c8);
            cp16(&bs[st][r][c8], Wt   + (size_t)(col0 + r) * Dc + kk + c8);
        }
        cp_commit();
    };

    load_stage(0, 0);

    const int nT = Dc / 32;   // 32
    for (int tt = 0; tt < nT; ++tt) {
        const int cur = tt & 1;
        if (tt + 1 < nT) { load_stage((tt + 1) * 32, cur ^ 1); cp_wait<1>(); }
        else             { cp_wait<0>(); }
        __syncthreads();

        #pragma unroll
        for (int kf = 0; kf < 2; ++kf) {
            const int k0 = kf * 16;
            unsigned A[2][4];
            #pragma unroll
            for (int mt = 0; mt < 2; ++mt) {
                int r = wm * 32 + mt * 16 + g;
                A[mt][0] = *(const unsigned*)&as[cur][r    ][k0     + t * 2];
                A[mt][1] = *(const unsigned*)&as[cur][r + 8][k0     + t * 2];
                A[mt][2] = *(const unsigned*)&as[cur][r    ][k0 + 8 + t * 2];
                A[mt][3] = *(const unsigned*)&as[cur][r + 8][k0 + 8 + t * 2];
            }
            #pragma unroll
            for (int nt = 0; nt < 8; ++nt) {
                int n = wn * 64 + nt * 8 + g;
                unsigned b0 = *(const unsigned*)&bs[cur][n][k0     + t * 2];
                unsigned b1 = *(const unsigned*)&bs[cur][n][k0 + 8 + t * 2];
                mma_bf16(c[0][nt][0], c[0][nt][1], c[0][nt][2], c[0][nt][3],
                         A[0][0], A[0][1], A[0][2], A[0][3], b0, b1);
                mma_bf16(c[1][nt][0], c[1][nt][1], c[1][nt][2], c[1][nt][3],
                         A[1][0], A[1][1], A[1][2], A[1][3], b0, b1);
            }
        }
        __syncthreads();
    }

    #pragma unroll
    for (int mt = 0; mt < 2; ++mt) {
        #pragma unroll
        for (int nt = 0; nt < 8; ++nt) {
            const int col = col0 + wn * 64 + nt * 8 + t * 2;
            const int h = col >> 6, dk = col & 63;
            const float bi0 = bv[col], bi1 = bv[col + 1];
            const int r0 = row0 + wm * 32 + mt * 16 + g;
            #pragma unroll
            for (int rr = 0; rr < 2; ++rr) {
                const int rowg = r0 + rr * 8;
                const int b = rowg >> 11, s = rowg & 2047;
                g_vT[((size_t)(b * Hc + h) * DKc + dk    ) * Sc + s] =
                    __float2bfloat16(c[mt][nt][rr * 2 + 0] + bi0);
                g_vT[((size_t)(b * Hc + h) * DKc + dk + 1) * Sc + s] =
                    __float2bfloat16(c[mt][nt][rr * 2 + 1] + bi1);
            }
        }
    }
}

// ---------------------------------------------------------------------------
// Kernel 2: FUSED attention.
//   pass 1: bf16 q.k^T (fragments packed on the fly from fp32 smem) -> row
//           sums of masked exp only. (bf16 errors average out in the sum.)
//   pass 2: tf32 q.k^T -> p = e/l, write p, feed C-frags as bf16 A-frags of
//           p @ V. cp.async 2-stage on K tiles, single-stage V.
// ---------------------------------------------------------------------------
__global__ __launch_bounds__(256) void attn_fused_kernel(float* __restrict__ attn)
{
    const int bh = blockIdx.y;
    const int i0 = blockIdx.x * 128;
    const int b  = bh >> 4, h = bh & 15;

    // smem: ks[2][64][68] f32 (34816 B) + vs[64][72] bf16 (9216 B) = 44032 B.
    // qs[128][68] f32 (34816 B) aliases the ks region during setup.
    __shared__ __align__(16) unsigned char sbuf[44032];
    float (*qs)[68] = (float (*)[68])sbuf;
    float (*ks0)[68] = (float (*)[68])sbuf;
    float (*ks1)[68] = (float (*)[68])(sbuf + 17408);
    __nv_bfloat16 (*vs)[72] = (__nv_bfloat16 (*)[72])(sbuf + 34816);

    const int tid = threadIdx.x, warp = tid >> 5, lane = tid & 31;
    const int g = lane >> 2, t = lane & 3;

    const float* qbase = g_qf + ((size_t)bh * Sc + i0) * DKc;
    const float* kbase = g_kf + (size_t)bh * Sc * DKc;
    const __nv_bfloat16* vbase = g_vT + (size_t)bh * DKc * Sc;

    #pragma unroll
    for (int it = 0; it < 8; ++it) {
        int f = tid + it * 256;
        int r = f >> 4, c4 = (f & 15) * 4;
        *(float4*)&qs[r][c4] = *(const float4*)(qbase + (size_t)r * DKc + c4);
    }
    __syncthreads();

    unsigned A[8][4];    // tf32 fragments (pass 2)
    unsigned Ab[4][4];   // bf16 fragments (pass 1)
    {
        const int r = warp * 16 + g;
        #pragma unroll
        for (int kf = 0; kf < 8; ++kf) {
            const int k0 = kf * 8;
            A[kf][0] = __float_as_uint(qs[r    ][k0 + t]);
            A[kf][1] = __float_as_uint(qs[r + 8][k0 + t]);
            A[kf][2] = __float_as_uint(qs[r    ][k0 + t + 4]);
            A[kf][3] = __float_as_uint(qs[r + 8][k0 + t + 4]);
        }
        #pragma unroll
        for (int kf = 0; kf < 4; ++kf) {
            const int k0 = kf * 16;
            Ab[kf][0] = pack_bf16x2(qs[r    ][k0     + t * 2], qs[r    ][k0     + t * 2 + 1]);
            Ab[kf][1] = pack_bf16x2(qs[r + 8][k0     + t * 2], qs[r + 8][k0     + t * 2 + 1]);
            Ab[kf][2] = pack_bf16x2(qs[r    ][k0 + 8 + t * 2], qs[r    ][k0 + 8 + t * 2 + 1]);
            Ab[kf][3] = pack_bf16x2(qs[r + 8][k0 + 8 + t * 2], qs[r + 8][k0 + 8 + t * 2 + 1]);
        }
    }
    __syncthreads();   // done with qs before ks overwrites it

    const int ig0 = i0 + warp * 16 + g;
    const int ig1 = ig0 + 8;
    const unsigned* mp0 = g_mask + ((size_t)b * Sc + ig0) * (Sc / 32);
    const unsigned* mp1 = g_mask + ((size_t)b * Sc + ig1) * (Sc / 32);
    float* arow0 = attn + ((size_t)bh * Sc + ig0) * Sc;
    float* arow1 = attn + ((size_t)bh * Sc + ig1) * Sc;

    auto load_k = [&](int jj, int st) {
        float (*dst)[68] = st ? ks1 : ks0;
        #pragma unroll
        for (int it = 0; it < 4; ++it) {
            int f = tid + it * 256;
            int r = f >> 4, c4 = (f & 15) * 4;
            cp16(&dst[r][c4], kbase + (size_t)(jj + r) * DKc + c4);
        }
        cp_commit();
    };
    auto load_v = [&](int jj) {
        #pragma unroll
        for (int it = 0; it < 2; ++it) {
            int f = tid + it * 256;
            int dk = f >> 3, c8 = (f & 7) * 8;
            cp16(&vs[dk][c8], vbase + (size_t)dk * Sc + jj + c8);
        }
        cp_commit();
    };

    // ---------------- pass 1: row sums (bf16 MMA) ----------------
    float rsum0 = 0.f, rsum1 = 0.f;
    load_k(0, 0);
    for (int jj = 0; jj < Sc; jj += 64) {
        const int cur = (jj >> 6) & 1;
        if (jj + 64 < Sc) { load_k(jj + 64, cur ^ 1); cp_wait<1>(); }
        else              { cp_wait<0>(); }
        __syncthreads();
        float (*ks)[68] = cur ? ks1 : ks0;

        float c[8][4];
        #pragma unroll
        for (int nt = 0; nt < 8; ++nt)
            #pragma unroll
            for (int q = 0; q < 4; ++q) c[nt][q] = 0.f;
        #pragma unroll
        for (int kf = 0; kf < 4; ++kf) {
            const int k0 = kf * 16;
            #pragma unroll
            for (int nt = 0; nt < 8; ++nt) {
                const int n = nt * 8 + g;
                unsigned b0 = pack_bf16x2(ks[n][k0     + t * 2], ks[n][k0     + t * 2 + 1]);
                unsigned b1 = pack_bf16x2(ks[n][k0 + 8 + t * 2], ks[n][k0 + 8 + t * 2 + 1]);
                mma_bf16(c[nt][0], c[nt][1], c[nt][2], c[nt][3],
                         Ab[kf][0], Ab[kf][1], Ab[kf][2], Ab[kf][3], b0, b1);
            }
        }

        const unsigned m00 = mp0[jj >> 5], m01 = mp0[(jj >> 5) + 1];
        const unsigned m10 = mp1[jj >> 5], m11 = mp1[(jj >> 5) + 1];
        #pragma unroll
        for (int nt = 0; nt < 8; ++nt) {
            const int jl = nt * 8 + t * 2;
            const unsigned w0 = (jl & 32) ? m01 : m00;
            const unsigned w1 = (jl & 32) ? m11 : m10;
            const int sh = jl & 31;
            rsum0 += (((w0 >> sh)       & 1u) ? 0.f : __expf(c[nt][0] * 0.125f))
                   + (((w0 >> (sh + 1)) & 1u) ? 0.f : __expf(c[nt][1] * 0.125f));
            rsum1 += (((w1 >> sh)       & 1u) ? 0.f : __expf(c[nt][2] * 0.125f))
                   + (((w1 >> (sh + 1)) & 1u) ? 0.f : __expf(c[nt][3] * 0.125f));
        }
        __syncthreads();
    }
    rsum0 += __shfl_xor_sync(0xffffffffu, rsum0, 1);
    rsum0 += __shfl_xor_sync(0xffffffffu, rsum0, 2);
    rsum1 += __shfl_xor_sync(0xffffffffu, rsum1, 1);
    rsum1 += __shfl_xor_sync(0xffffffffu, rsum1, 2);
    const float invl0 = 1.0f / rsum0;
    const float invl1 = 1.0f / rsum1;

    // ---------------- pass 2: write p, ctx = p @ V (tf32 scores) ----------
    float ctx[8][4];
    #pragma unroll
    for (int nt = 0; nt < 8; ++nt)
        #pragma unroll
        for (int q = 0; q < 4; ++q) ctx[nt][q] = 0.f;

    load_k(0, 0);
    for (int jj = 0; jj < Sc; jj += 64) {
        const int cur = (jj >> 6) & 1;
        load_v(jj);                                   // group A (current v)
        if (jj + 64 < Sc) { load_k(jj + 64, cur ^ 1); cp_wait<1>(); }  // group B pending
        else              { cp_wait<0>(); }
        __syncthreads();
        float (*ks)[68] = cur ? ks1 : ks0;

        float c[8][4];
        #pragma unroll
        for (int nt = 0; nt < 8; ++nt)
            #pragma unroll
            for (int q = 0; q < 4; ++q) c[nt][q] = 0.f;
        #pragma unroll
        for (int kf = 0; kf < 8; ++kf) {
            const int k0 = kf * 8;
            #pragma unroll
            for (int nt = 0; nt < 8; ++nt) {
                const int n = nt * 8 + g;
                unsigned b0 = __float_as_uint(ks[n][k0 + t]);
                unsigned b1 = __float_as_uint(ks[n][k0 + t + 4]);
                mma_tf32(c[nt][0], c[nt][1], c[nt][2], c[nt][3],
                         A[kf][0], A[kf][1], A[kf][2], A[kf][3], b0, b1);
            }
        }

        const unsigned m00 = mp0[jj >> 5], m01 = mp0[(jj >> 5) + 1];
        const unsigned m10 = mp1[jj >> 5], m11 = mp1[(jj >> 5) + 1];

        unsigned pf[8][2];
        #pragma unroll
        for (int nt = 0; nt < 8; ++nt) {
            const int jl = nt * 8 + t * 2;
            const unsigned w0 = (jl & 32) ? m01 : m00;
            const unsigned w1 = (jl & 32) ? m11 : m10;
            const int sh = jl & 31;
            float p0 = ((w0 >> sh)       & 1u) ? 0.f : __expf(c[nt][0] * 0.125f) * invl0;
            float p1 = ((w0 >> (sh + 1)) & 1u) ? 0.f : __expf(c[nt][1] * 0.125f) * invl0;
            float p2 = ((w1 >> sh)       & 1u) ? 0.f : __expf(c[nt][2] * 0.125f) * invl1;
            float p3 = ((w1 >> (sh + 1)) & 1u) ? 0.f : __expf(c[nt][3] * 0.125f) * invl1;
            *(float2*)(arow0 + jj + jl) = make_float2(p0, p1);
            *(float2*)(arow1 + jj + jl) = make_float2(p2, p3);
            pf[nt][0] = pack_bf16x2(p0, p1);
            pf[nt][1] = pack_bf16x2(p2, p3);
        }

        #pragma unroll
        for (int kf = 0; kf < 4; ++kf) {
            const unsigned a0 = pf[2 * kf    ][0];
            const unsigned a1 = pf[2 * kf    ][1];
            const unsigned a2 = pf[2 * kf + 1][0];
            const unsigned a3 = pf[2 * kf + 1][1];
            const int k0 = kf * 16;
            #pragma unroll
            for (int nt = 0; nt < 8; ++nt) {
                unsigned b0 = *(const unsigned*)&vs[nt * 8 + g][k0     + t * 2];
                unsigned b1 = *(const unsigned*)&vs[nt * 8 + g][k0 + 8 + t * 2];
                mma_bf16(ctx[nt][0], ctx[nt][1], ctx[nt][2], ctx[nt][3],
                         a0, a1, a2, a3, b0, b1);
            }
        }
        __syncthreads();
    }

    const int s = i0 + warp * 16 + g;
    const size_t crow0 = ((size_t)b * Sc + s)     * Dc;
    const size_t crow1 = ((size_t)b * Sc + s + 8) * Dc;
    #pragma unroll
    for (int nt = 0; nt < 8; ++nt) {
        const int col = h * DKc + nt * 8 + t * 2;
        *(__nv_bfloat162*)&g_ctxb[crow0 + col] = __floats2bfloat162_rn(ctx[nt][0], ctx[nt][1]);
        *(__nv_bfloat162*)&g_ctxb[crow1 + col] = __floats2bfloat162_rn(ctx[nt][2], ctx[nt][3]);
    }
}

// ---------------------------------------------------------------------------
// Kernel 3: output projection, bf16 MMA, cp.async 2-stage.
// ---------------------------------------------------------------------------
__global__ __launch_bounds__(256) void oproj_mma_kernel(
    const float* __restrict__ bo, const float* __restrict__ Qres)
{
    const __nv_bfloat16* Wt = g_wT[3];

    __shared__ __align__(16) __nv_bfloat16 as[2][128][40];
    __shared__ __align__(16) __nv_bfloat16 bs[2][128][40];

    const int tid  = threadIdx.x;
    const int warp = tid >> 5, lane = tid & 31;
    const int g = lane >> 2, t = lane & 3;
    const int wm = warp >> 1, wn = warp & 1;
    const int row0 = blockIdx.y * 128;
    const int col0 = blockIdx.x * 128;

    float c[2][8][4];
    #pragma unroll
    for (int mt = 0; mt < 2; ++mt)
        #pragma unroll
        for (int nt = 0; nt < 8; ++nt)
            #pragma unroll
            for (int q = 0; q < 4; ++q) c[mt][nt][q] = 0.f;

    auto load_stage = [&](int kk, int st) {
        #pragma unroll
        for (int it = 0; it < 2; ++it) {
            int f = tid + it * 256;
            int r = f >> 2, c8 = (f & 3) * 8;
            cp16(&as[st][r][c8], g_ctxb + (size_t)(row0 + r) * Dc + kk + c8);
            cp16(&bs[st][r][c8], Wt     + (size_t)(col0 + r) * Dc + kk + c8);
        }
        cp_commit();
    };

    load_stage(0, 0);

    const int nT = Dc / 32;
    for (int tt = 0; tt < nT; ++tt) {
        const int cur = tt & 1;
        if (tt + 1 < nT) { load_stage((tt + 1) * 32, cur ^ 1); cp_wait<1>(); }
        else             { cp_wait<0>(); }
        __syncthreads();

        #pragma unroll
        for (int kf = 0; kf < 2; ++kf) {
            const int k0 = kf * 16;
            unsigned A[2][4];
            #pragma unroll
            for (int mt = 0; mt < 2; ++mt) {
                int r = wm * 32 + mt * 16 + g;
                A[mt][0] = *(const unsigned*)&as[cur][r    ][k0     + t * 2];
                A[mt][1] = *(const unsigned*)&as[cur][r + 8][k0     + t * 2];
                A[mt][2] = *(const unsigned*)&as[cur][r    ][k0 + 8 + t * 2];
                A[mt][3] = *(const unsigned*)&as[cur][r + 8][k0 + 8 + t * 2];
            }
            #pragma unroll
            for (int nt = 0; nt < 8; ++nt) {
                int n = wn * 64 + nt * 8 + g;
                unsigned b0 = *(const unsigned*)&bs[cur][n][k0     + t * 2];
                unsigned b1 = *(const unsigned*)&bs[cur][n][k0 + 8 + t * 2];
                mma_bf16(c[0][nt][0], c[0][nt][1], c[0][nt][2], c[0][nt][3],
                         A[0][0], A[0][1], A[0][2], A[0][3], b0, b1);
                mma_bf16(c[1][nt][0], c[1][nt][1], c[1][nt][2], c[1][nt][3],
                         A[1][0], A[1][1], A[1][2], A[1][3], b0, b1);
            }
        }
        __syncthreads();
    }

    #pragma unroll
    for (int mt = 0; mt < 2; ++mt) {
        #pragma unroll
        for (int nt = 0; nt < 8; ++nt) {
            const int col = col0 + wn * 64 + nt * 8 + t * 2;
            const float bi0 = bo[col], bi1 = bo[col + 1];
            const int r0 = row0 + wm * 32 + mt * 16 + g;
            #pragma unroll
            for (int rr = 0; rr < 2; ++rr) {
                const int rowg = r0 + rr * 8;
                const float* res = Qres + (size_t)rowg * Dc + col;
                float2 rv = *(const float2*)res;
                float2 o = make_float2(c[mt][nt][rr * 2 + 0] + bi0 + rv.x,
                                       c[mt][nt][rr * 2 + 1] + bi1 + rv.y);
                *(float2*)(g_y + (size_t)rowg * Dc + col) = o;
            }
        }
    }
}

// ---------------------------------------------------------------------------
// Kernel 4: LayerNorm per row (fp32).
// ---------------------------------------------------------------------------
__global__ __launch_bounds__(256) void ln_kernel(
    const float* __restrict__ gamma, const float* __restrict__ beta,
    float* __restrict__ out)
{
    const int row = blockIdx.x;
    const int tid = threadIdx.x;
    const float* y = g_y + (size_t)row * Dc;

    float4 v = ((const float4*)y)[tid];
    float s  = v.x + v.y + v.z + v.w;
    float q  = v.x * v.x + v.y * v.y + v.z * v.z + v.w * v.w;

    __shared__ float ss[8];
    __shared__ float sq[8];
    #pragma unroll
    for (int o = 16; o > 0; o >>= 1) {
        s += __shfl_xor_sync(0xffffffffu, s, o);
        q += __shfl_xor_sync(0xffffffffu, q, o);
    }
    if ((tid & 31) == 0) { ss[tid >> 5] = s; sq[tid >> 5] = q; }
    __syncthreads();
    s = ss[tid & 7];
    q = sq[tid & 7];
    #pragma unroll
    for (int o = 4; o > 0; o >>= 1) {
        s += __shfl_xor_sync(0xffffffffu, s, o);
        q += __shfl_xor_sync(0xffffffffu, q, o);
    }

    const float mu  = s * (1.0f / Dc);
    const float var = q * (1.0f / Dc) - mu * mu;
    const float inv = rsqrtf(var + 1e-5f);

    float4 gv = ((const float4*)gamma)[tid];
    float4 bv = ((const float4*)beta)[tid];
    float4 o4 = make_float4((v.x - mu) * inv * gv.x + bv.x,
                            (v.y - mu) * inv * gv.y + bv.y,
                            (v.z - mu) * inv * gv.z + bv.z,
                            (v.w - mu) * inv * gv.w + bv.w);
    ((float4*)(out + (size_t)row * Dc))[tid] = o4;
}

// ---------------------------------------------------------------------------
// Launch
// ---------------------------------------------------------------------------
extern "C" void kernel_launch(void* const* d_in, const int* in_sizes, int n_in,
                              void* d_out, int out_size)
{
    const float* Qin  = (const float*)d_in[0];
    const unsigned* mask = (const unsigned*)d_in[3];
    const float* Wq = (const float*)d_in[4];
    const float* bq = (const float*)d_in[5];
    const float* Wk = (const float*)d_in[6];
    const float* bk = (const float*)d_in[7];
    const float* Wv = (const float*)d_in[8];
    const float* bv = (const float*)d_in[9];
    const float* Wo = (const float*)d_in[10];
    const float* bo = (const float*)d_in[11];
    const float* ln_g = (const float*)d_in[12];
    const float* ln_b = (const float*)d_in[13];

    float* out  = (float*)d_out;
    float* attn = out + (size_t)Bc * Sc * Dc;

    cvt_x_kernel    <<<(Mc * Dc) / 1024, 256>>>(Qin);
    cvt_wT_kernel   <<<dim3(32, 32, 4), 256>>>(Wq, Wk, Wv, Wo);
    mask_pack_kernel<<<(Bc * Sc * (Sc / 32)) / 8, 256>>>(mask);

    proj_qk_tf32_kernel<<<dim3(Dc / 128, Mc / 128, 2), 256>>>(bq, bk);
    proj_v_mma_kernel  <<<dim3(Dc / 128, Mc / 128), 256>>>(bv);
    attn_fused_kernel  <<<dim3(Sc / 128, BHc), 256>>>(attn);
    oproj_mma_kernel   <<<dim3(Dc / 128, Mc / 128), 256>>>(bo, Qin);
    ln_kernel          <<<Mc, 256>>>(ln_g, ln_b, out);
}

// round 9
// speedup vs baseline: 3.0956x; 1.0935x over previous
#include <cuda_runtime.h>
#include <cuda_bf16.h>

#define Bc   2
#define Sc   2048
#define Dc   1024
#define Hc   16
#define DKc  64
#define Mc   (Bc * Sc)        // 4096
#define BHc  (Bc * Hc)        // 32

// ---------------------------------------------------------------------------
// Scratch (__device__ globals; no cudaMalloc allowed)
// ---------------------------------------------------------------------------
__device__ __align__(16) __nv_bfloat16 g_xb [(size_t)Mc * Dc];          // X bf16 (V path)
__device__ __align__(16) float         g_xtf[(size_t)Mc * Dc];          // X tf32-rounded (QK path)
__device__ __align__(16) __nv_bfloat16 g_wT [4][(size_t)Dc * Dc];       // bf16 W^T ([2],[3] used)
__device__ __align__(16) float         g_wTf[2][(size_t)Dc * Dc];       // tf32-rounded W^T (Wq,Wk)
__device__ __align__(16) float         g_qf [(size_t)BHc * Sc * DKc];   // q tf32-rounded [bh][s][dk]
__device__ __align__(16) float         g_kf [(size_t)BHc * Sc * DKc];   // k tf32-rounded [bh][s][dk]
__device__ __align__(16) __nv_bfloat16 g_kb [(size_t)BHc * Sc * DKc];   // k bf16 (pass-1 sums)
__device__ __align__(16) __nv_bfloat16 g_vT [(size_t)BHc * DKc * Sc];   // v bf16 [bh][dk][s]
__device__ __align__(16) __nv_bfloat16 g_ctxb[(size_t)Mc * Dc];         // ctx bf16
__device__ unsigned g_mask[(size_t)Bc * Sc * (Sc / 32)];                 // bit-packed mask
__device__ __align__(16) float g_y [(size_t)Mc * Dc];                    // pre-LN

// ---------------------------------------------------------------------------
// MMA + async-copy + ldmatrix helpers
// ---------------------------------------------------------------------------
__device__ __forceinline__ void mma_bf16(
    float& c0, float& c1, float& c2, float& c3,
    unsigned a0, unsigned a1, unsigned a2, unsigned a3,
    unsigned b0, unsigned b1)
{
    asm volatile(
        "mma.sync.aligned.m16n8k16.row.col.f32.bf16.bf16.f32 "
        "{%0,%1,%2,%3}, {%4,%5,%6,%7}, {%8,%9}, {%0,%1,%2,%3};\n"
        : "+f"(c0), "+f"(c1), "+f"(c2), "+f"(c3)
        : "r"(a0), "r"(a1), "r"(a2), "r"(a3), "r"(b0), "r"(b1));
}

__device__ __forceinline__ void mma_tf32(
    float& c0, float& c1, float& c2, float& c3,
    unsigned a0, unsigned a1, unsigned a2, unsigned a3,
    unsigned b0, unsigned b1)
{
    asm volatile(
        "mma.sync.aligned.m16n8k8.row.col.f32.tf32.tf32.f32 "
        "{%0,%1,%2,%3}, {%4,%5,%6,%7}, {%8,%9}, {%0,%1,%2,%3};\n"
        : "+f"(c0), "+f"(c1), "+f"(c2), "+f"(c3)
        : "r"(a0), "r"(a1), "r"(a2), "r"(a3), "r"(b0), "r"(b1));
}

__device__ __forceinline__ float f2tf_f(float x)
{
    unsigned r;
    asm("cvt.rna.tf32.f32 %0, %1;" : "=r"(r) : "f"(x));
    return __uint_as_float(r);
}

__device__ __forceinline__ unsigned pack_bf16x2(float a, float b)
{
    unsigned r;
    asm("cvt.rn.bf16x2.f32 %0, %1, %2;" : "=r"(r) : "f"(b), "f"(a));
    return r;
}

__device__ __forceinline__ void cp16(void* smem, const void* gmem)
{
    unsigned sa = (unsigned)__cvta_generic_to_shared(smem);
    asm volatile("cp.async.cg.shared.global [%0], [%1], 16;\n"
                 :: "r"(sa), "l"(gmem));
}
__device__ __forceinline__ void cp_commit()
{
    asm volatile("cp.async.commit_group;\n");
}
template<int N> __device__ __forceinline__ void cp_wait()
{
    asm volatile("cp.async.wait_group %0;\n" :: "n"(N));
}

__device__ __forceinline__ void ldm_x4(unsigned& r0, unsigned& r1,
                                       unsigned& r2, unsigned& r3, const void* p)
{
    unsigned a = (unsigned)__cvta_generic_to_shared(p);
    asm volatile("ldmatrix.sync.aligned.m8n8.x4.shared.b16 {%0,%1,%2,%3}, [%4];\n"
                 : "=r"(r0), "=r"(r1), "=r"(r2), "=r"(r3) : "r"(a));
}

// ---------------------------------------------------------------------------
// Pre-pass: X fp32 -> bf16 (V path) + tf32-rounded fp32 (QK path)
// ---------------------------------------------------------------------------
__global__ __launch_bounds__(256) void cvt_x_kernel(const float* __restrict__ X)
{
    size_t i = ((size_t)blockIdx.x * 256 + threadIdx.x) * 4;
    float4 v = *(const float4*)(X + i);
    __nv_bfloat162* d = (__nv_bfloat162*)(g_xb + i);
    d[0] = __floats2bfloat162_rn(v.x, v.y);
    d[1] = __floats2bfloat162_rn(v.z, v.w);
    float4 tv = make_float4(f2tf_f(v.x), f2tf_f(v.y), f2tf_f(v.z), f2tf_f(v.w));
    *(float4*)(g_xtf + i) = tv;
}

// ---------------------------------------------------------------------------
// Pre-pass: weights [k][n] -> transposed [n][k]; tf32 for Wq/Wk, bf16 Wv/Wo
// ---------------------------------------------------------------------------
__global__ __launch_bounds__(256) void cvt_wT_kernel(
    const float* __restrict__ W0, const float* __restrict__ W1,
    const float* __restrict__ W2, const float* __restrict__ W3)
{
    const int z = blockIdx.z;
    const float* W = z == 0 ? W0 : z == 1 ? W1 : z == 2 ? W2 : W3;
    __shared__ float tile[32][33];
    const int tx = threadIdx.x & 31, ty = threadIdx.x >> 5;
    const int k0 = blockIdx.x * 32, n0 = blockIdx.y * 32;
    #pragma unroll
    for (int i = 0; i < 4; ++i)
        tile[ty + i * 8][tx] = W[(size_t)(k0 + ty + i * 8) * Dc + n0 + tx];
    __syncthreads();
    if (z < 2) {
        float* out = g_wTf[z];
        #pragma unroll
        for (int i = 0; i < 4; ++i)
            out[(size_t)(n0 + ty + i * 8) * Dc + k0 + tx] = f2tf_f(tile[tx][ty + i * 8]);
    } else {
        __nv_bfloat16* out = g_wT[z];
        #pragma unroll
        for (int i = 0; i < 4; ++i)
            out[(size_t)(n0 + ty + i * 8) * Dc + k0 + tx] =
                __float2bfloat16(tile[tx][ty + i * 8]);
    }
}

// ---------------------------------------------------------------------------
// Pre-pass: bit-pack mask (int32 nonzero -> 1 bit)
// ---------------------------------------------------------------------------
__global__ __launch_bounds__(256) void mask_pack_kernel(const unsigned* __restrict__ mask)
{
    const int w    = blockIdx.x * 8 + (threadIdx.x >> 5);
    const int lane = threadIdx.x & 31;
    unsigned v = mask[(size_t)w * 32 + lane];
    unsigned bits = __ballot_sync(0xffffffffu, v != 0);
    if (lane == 0) g_mask[w] = bits;
}

// ---------------------------------------------------------------------------
// Kernel 1a: q/k projections, tf32, cp.async 2-stage, BK=16.
// z==1 additionally stores a bf16 copy of k (for attn pass-1 row sums).
// ---------------------------------------------------------------------------
__global__ __launch_bounds__(256) void proj_qk_tf32_kernel(
    const float* __restrict__ bq, const float* __restrict__ bk)
{
    const int z = blockIdx.z;
    const float* Wt = g_wTf[z];
    const float* bias = z == 0 ? bq : bk;
    float* outp = z == 0 ? g_qf : g_kf;

    __shared__ __align__(16) float as[2][128][20];
    __shared__ __align__(16) float bs[2][128][20];

    const int tid  = threadIdx.x;
    const int warp = tid >> 5, lane = tid & 31;
    const int g = lane >> 2, t = lane & 3;
    const int wm = warp >> 1, wn = warp & 1;
    const int row0 = blockIdx.y * 128;
    const int col0 = blockIdx.x * 128;

    float c[2][8][4];
    #pragma unroll
    for (int mt = 0; mt < 2; ++mt)
        #pragma unroll
        for (int nt = 0; nt < 8; ++nt)
            #pragma unroll
            for (int q = 0; q < 4; ++q) c[mt][nt][q] = 0.f;

    auto load_stage = [&](int kk, int st) {
        #pragma unroll
        for (int it = 0; it < 2; ++it) {
            int f = tid + it * 256;
            int r = f >> 2, c4 = (f & 3) * 4;
            cp16(&as[st][r][c4], g_xtf + (size_t)(row0 + r) * Dc + kk + c4);
            cp16(&bs[st][r][c4], Wt    + (size_t)(col0 + r) * Dc + kk + c4);
        }
        cp_commit();
    };

    load_stage(0, 0);

    const int nT = Dc / 16;   // 64
    for (int tt = 0; tt < nT; ++tt) {
        const int cur = tt & 1;
        if (tt + 1 < nT) { load_stage((tt + 1) * 16, cur ^ 1); cp_wait<1>(); }
        else             { cp_wait<0>(); }
        __syncthreads();

        #pragma unroll
        for (int kf = 0; kf < 2; ++kf) {
            const int k0 = kf * 8;
            unsigned A[2][4];
            #pragma unroll
            for (int mt = 0; mt < 2; ++mt) {
                int r = wm * 32 + mt * 16 + g;
                A[mt][0] = __float_as_uint(as[cur][r    ][k0 + t]);
                A[mt][1] = __float_as_uint(as[cur][r + 8][k0 + t]);
                A[mt][2] = __float_as_uint(as[cur][r    ][k0 + t + 4]);
                A[mt][3] = __float_as_uint(as[cur][r + 8][k0 + t + 4]);
            }
            #pragma unroll
            for (int nt = 0; nt < 8; ++nt) {
                int n = wn * 64 + nt * 8 + g;
                unsigned b0 = __float_as_uint(bs[cur][n][k0 + t]);
                unsigned b1 = __float_as_uint(bs[cur][n][k0 + t + 4]);
                mma_tf32(c[0][nt][0], c[0][nt][1], c[0][nt][2], c[0][nt][3],
                         A[0][0], A[0][1], A[0][2], A[0][3], b0, b1);
                mma_tf32(c[1][nt][0], c[1][nt][1], c[1][nt][2], c[1][nt][3],
                         A[1][0], A[1][1], A[1][2], A[1][3], b0, b1);
            }
        }
        __syncthreads();
    }

    #pragma unroll
    for (int mt = 0; mt < 2; ++mt) {
        #pragma unroll
        for (int nt = 0; nt < 8; ++nt) {
            const int col = col0 + wn * 64 + nt * 8 + t * 2;
            const int h = col >> 6, dk = col & 63;
            const float bi0 = bias[col], bi1 = bias[col + 1];
            const int r0 = row0 + wm * 32 + mt * 16 + g;
            #pragma unroll
            for (int rr = 0; rr < 2; ++rr) {
                const int rowg = r0 + rr * 8;
                const int b = rowg >> 11, s = rowg & 2047;
                const float v0 = c[mt][nt][rr * 2 + 0] + bi0;
                const float v1 = c[mt][nt][rr * 2 + 1] + bi1;
                const size_t off = ((size_t)(b * Hc + h) * Sc + s) * DKc + dk;
                *(float2*)(outp + off) = make_float2(f2tf_f(v0), f2tf_f(v1));
                if (z == 1)
                    *(__nv_bfloat162*)(g_kb + off) = __floats2bfloat162_rn(v0, v1);
            }
        }
    }
}

// ---------------------------------------------------------------------------
// Kernel 1b: v projection, bf16 MMA, cp.async 2-stage, BK=32.
// ---------------------------------------------------------------------------
__global__ __launch_bounds__(256) void proj_v_mma_kernel(const float* __restrict__ bv)
{
    const __nv_bfloat16* Wt = g_wT[2];

    __shared__ __align__(16) __nv_bfloat16 as[2][128][40];
    __shared__ __align__(16) __nv_bfloat16 bs[2][128][40];

    const int tid  = threadIdx.x;
    const int warp = tid >> 5, lane = tid & 31;
    const int g = lane >> 2, t = lane & 3;
    const int wm = warp >> 1, wn = warp & 1;
    const int row0 = blockIdx.y * 128;
    const int col0 = blockIdx.x * 128;

    float c[2][8][4];
    #pragma unroll
    for (int mt = 0; mt < 2; ++mt)
        #pragma unroll
        for (int nt = 0; nt < 8; ++nt)
            #pragma unroll
            for (int q = 0; q < 4; ++q) c[mt][nt][q] = 0.f;

    auto load_stage = [&](int kk, int st) {
        #pragma unroll
        for (int it = 0; it < 2; ++it) {
            int f = tid + it * 256;
            int r = f >> 2, c8 = (f & 3) * 8;
            cp16(&as[st][r][c8], g_xb + (size_t)(row0 + r) * Dc + kk + c8);
            cp16(&bs[st][r][c8], Wt   + (size_t)(col0 + r) * Dc + kk + c8);
        }
        cp_commit();
    };

    load_stage(0, 0);

    const int nT = Dc / 32;   // 32
    for (int tt = 0; tt < nT; ++tt) {
        const int cur = tt & 1;
        if (tt + 1 < nT) { load_stage((tt + 1) * 32, cur ^ 1); cp_wait<1>(); }
        else             { cp_wait<0>(); }
        __syncthreads();

        #pragma unroll
        for (int kf = 0; kf < 2; ++kf) {
            const int k0 = kf * 16;
            unsigned A[2][4];
            #pragma unroll
            for (int mt = 0; mt < 2; ++mt) {
                int r = wm * 32 + mt * 16 + g;
                A[mt][0] = *(const unsigned*)&as[cur][r    ][k0     + t * 2];
                A[mt][1] = *(const unsigned*)&as[cur][r + 8][k0     + t * 2];
                A[mt][2] = *(const unsigned*)&as[cur][r    ][k0 + 8 + t * 2];
                A[mt][3] = *(const unsigned*)&as[cur][r + 8][k0 + 8 + t * 2];
            }
            #pragma unroll
            for (int nt = 0; nt < 8; ++nt) {
                int n = wn * 64 + nt * 8 + g;
                unsigned b0 = *(const unsigned*)&bs[cur][n][k0     + t * 2];
                unsigned b1 = *(const unsigned*)&bs[cur][n][k0 + 8 + t * 2];
                mma_bf16(c[0][nt][0], c[0][nt][1], c[0][nt][2], c[0][nt][3],
                         A[0][0], A[0][1], A[0][2], A[0][3], b0, b1);
                mma_bf16(c[1][nt][0], c[1][nt][1], c[1][nt][2], c[1][nt][3],
                         A[1][0], A[1][1], A[1][2], A[1][3], b0, b1);
            }
        }
        __syncthreads();
    }

    #pragma unroll
    for (int mt = 0; mt < 2; ++mt) {
        #pragma unroll
        for (int nt = 0; nt < 8; ++nt) {
            const int col = col0 + wn * 64 + nt * 8 + t * 2;
            const int h = col >> 6, dk = col & 63;
            const float bi0 = bv[col], bi1 = bv[col + 1];
            const int r0 = row0 + wm * 32 + mt * 16 + g;
            #pragma unroll
            for (int rr = 0; rr < 2; ++rr) {
                const int rowg = r0 + rr * 8;
                const int b = rowg >> 11, s = rowg & 2047;
                g_vT[((size_t)(b * Hc + h) * DKc + dk    ) * Sc + s] =
                    __float2bfloat16(c[mt][nt][rr * 2 + 0] + bi0);
                g_vT[((size_t)(b * Hc + h) * DKc + dk + 1) * Sc + s] =
                    __float2bfloat16(c[mt][nt][rr * 2 + 1] + bi1);
            }
        }
    }
}

// ---------------------------------------------------------------------------
// Kernel 2: FUSED attention.
//   pass 1: bf16 q.k^T (K loaded bf16, fragments via ldmatrix) -> masked-exp
//           row sums only.
//   pass 2: tf32 q.k^T -> p = e/l, write p, C-frags -> bf16 A-frags of
//           p @ V (V fragments via ldmatrix).
// ---------------------------------------------------------------------------
__global__ __launch_bounds__(256) void attn_fused_kernel(float* __restrict__ attn)
{
    const int bh = blockIdx.y;
    const int i0 = blockIdx.x * 128;
    const int b  = bh >> 4, h = bh & 15;

    // unions: setup qs f32[128][68] (34816B)
    //   pass1: kb[2][64][72] bf16 (18432B)
    //   pass2: ks0 f32[64][68] @0, ks1 @17408, vs bf16[64][72] @34816 (total 44032B)
    __shared__ __align__(16) unsigned char sbuf[44032];
    float (*qs)[68] = (float (*)[68])sbuf;
    __nv_bfloat16 (*kb0)[72] = (__nv_bfloat16 (*)[72])sbuf;
    __nv_bfloat16 (*kb1)[72] = (__nv_bfloat16 (*)[72])(sbuf + 9216);
    float (*ks0)[68] = (float (*)[68])sbuf;
    float (*ks1)[68] = (float (*)[68])(sbuf + 17408);
    __nv_bfloat16 (*vs)[72] = (__nv_bfloat16 (*)[72])(sbuf + 34816);

    const int tid = threadIdx.x, warp = tid >> 5, lane = tid & 31;
    const int g = lane >> 2, t = lane & 3;
    const int lm = lane >> 3, lr = lane & 7;   // ldmatrix: matrix id, row id

    const float* qbase = g_qf + ((size_t)bh * Sc + i0) * DKc;
    const float* kbase = g_kf + (size_t)bh * Sc * DKc;
    const __nv_bfloat16* kbbase = g_kb + (size_t)bh * Sc * DKc;
    const __nv_bfloat16* vbase  = g_vT + (size_t)bh * DKc * Sc;

    #pragma unroll
    for (int it = 0; it < 8; ++it) {
        int f = tid + it * 256;
        int r = f >> 4, c4 = (f & 15) * 4;
        *(float4*)&qs[r][c4] = *(const float4*)(qbase + (size_t)r * DKc + c4);
    }
    __syncthreads();

    unsigned A[8][4];    // tf32 fragments (pass 2)
    unsigned Ab[4][4];   // bf16 fragments (pass 1)
    {
        const int r = warp * 16 + g;
        #pragma unroll
        for (int kf = 0; kf < 8; ++kf) {
            const int k0 = kf * 8;
            A[kf][0] = __float_as_uint(qs[r    ][k0 + t]);
            A[kf][1] = __float_as_uint(qs[r + 8][k0 + t]);
            A[kf][2] = __float_as_uint(qs[r    ][k0 + t + 4]);
            A[kf][3] = __float_as_uint(qs[r + 8][k0 + t + 4]);
        }
        #pragma unroll
        for (int kf = 0; kf < 4; ++kf) {
            const int k0 = kf * 16;
            Ab[kf][0] = pack_bf16x2(qs[r    ][k0     + t * 2], qs[r    ][k0     + t * 2 + 1]);
            Ab[kf][1] = pack_bf16x2(qs[r + 8][k0     + t * 2], qs[r + 8][k0     + t * 2 + 1]);
            Ab[kf][2] = pack_bf16x2(qs[r    ][k0 + 8 + t * 2], qs[r    ][k0 + 8 + t * 2 + 1]);
            Ab[kf][3] = pack_bf16x2(qs[r + 8][k0 + 8 + t * 2], qs[r + 8][k0 + 8 + t * 2 + 1]);
        }
    }
    __syncthreads();   // done with qs before pass buffers overwrite it

    const int ig0 = i0 + warp * 16 + g;
    const int ig1 = ig0 + 8;
    const unsigned* mp0 = g_mask + ((size_t)b * Sc + ig0) * (Sc / 32);
    const unsigned* mp1 = g_mask + ((size_t)b * Sc + ig1) * (Sc / 32);
    float* arow0 = attn + ((size_t)bh * Sc + ig0) * Sc;
    float* arow1 = attn + ((size_t)bh * Sc + ig1) * Sc;

    auto load_kb = [&](int jj, int st) {
        __nv_bfloat16 (*dst)[72] = st ? kb1 : kb0;
        #pragma unroll
        for (int it = 0; it < 2; ++it) {
            int f = tid + it * 256;
            int r = f >> 3, c8 = (f & 7) * 8;
            cp16(&dst[r][c8], kbbase + (size_t)(jj + r) * DKc + c8);
        }
        cp_commit();
    };
    auto load_k = [&](int jj, int st) {
        float (*dst)[68] = st ? ks1 : ks0;
        #pragma unroll
        for (int it = 0; it < 4; ++it) {
            int f = tid + it * 256;
            int r = f >> 4, c4 = (f & 15) * 4;
            cp16(&dst[r][c4], kbase + (size_t)(jj + r) * DKc + c4);
        }
        cp_commit();
    };
    auto load_v = [&](int jj) {
        #pragma unroll
        for (int it = 0; it < 2; ++it) {
            int f = tid + it * 256;
            int dk = f >> 3, c8 = (f & 7) * 8;
            cp16(&vs[dk][c8], vbase + (size_t)dk * Sc + jj + c8);
        }
        cp_commit();
    };

    // ---------------- pass 1: row sums (bf16 MMA, ldmatrix B) ----------------
    float rsum0 = 0.f, rsum1 = 0.f;
    load_kb(0, 0);
    for (int jj = 0; jj < Sc; jj += 64) {
        const int cur = (jj >> 6) & 1;
        if (jj + 64 < Sc) { load_kb(jj + 64, cur ^ 1); cp_wait<1>(); }
        else              { cp_wait<0>(); }
        __syncthreads();
        __nv_bfloat16 (*kb)[72] = cur ? kb1 : kb0;

        float c[8][4];
        #pragma unroll
        for (int nt = 0; nt < 8; ++nt)
            #pragma unroll
            for (int q = 0; q < 4; ++q) c[nt][q] = 0.f;
        #pragma unroll
        for (int kf = 0; kf < 4; ++kf) {
            const int k0 = kf * 16;
            #pragma unroll
            for (int q = 0; q < 4; ++q) {
                const int nt0 = 2 * q;
                unsigned r0, r1, r2, r3;
                ldm_x4(r0, r1, r2, r3,
                       &kb[(nt0 + (lm >> 1)) * 8 + lr][k0 + (lm & 1) * 8]);
                mma_bf16(c[nt0][0], c[nt0][1], c[nt0][2], c[nt0][3],
                         Ab[kf][0], Ab[kf][1], Ab[kf][2], Ab[kf][3], r0, r1);
                mma_bf16(c[nt0 + 1][0], c[nt0 + 1][1], c[nt0 + 1][2], c[nt0 + 1][3],
                         Ab[kf][0], Ab[kf][1], Ab[kf][2], Ab[kf][3], r2, r3);
            }
        }

        const unsigned m00 = mp0[jj >> 5], m01 = mp0[(jj >> 5) + 1];
        const unsigned m10 = mp1[jj >> 5], m11 = mp1[(jj >> 5) + 1];
        #pragma unroll
        for (int nt = 0; nt < 8; ++nt) {
            const int jl = nt * 8 + t * 2;
            const unsigned w0 = (jl & 32) ? m01 : m00;
            const unsigned w1 = (jl & 32) ? m11 : m10;
            const int sh = jl & 31;
            rsum0 += (((w0 >> sh)       & 1u) ? 0.f : __expf(c[nt][0] * 0.125f))
                   + (((w0 >> (sh + 1)) & 1u) ? 0.f : __expf(c[nt][1] * 0.125f));
            rsum1 += (((w1 >> sh)       & 1u) ? 0.f : __expf(c[nt][2] * 0.125f))
                   + (((w1 >> (sh + 1)) & 1u) ? 0.f : __expf(c[nt][3] * 0.125f));
        }
        __syncthreads();
    }
    rsum0 += __shfl_xor_sync(0xffffffffu, rsum0, 1);
    rsum0 += __shfl_xor_sync(0xffffffffu, rsum0, 2);
    rsum1 += __shfl_xor_sync(0xffffffffu, rsum1, 1);
    rsum1 += __shfl_xor_sync(0xffffffffu, rsum1, 2);
    const float invl0 = 1.0f / rsum0;
    const float invl1 = 1.0f / rsum1;

    // ---------------- pass 2: write p, ctx = p @ V (tf32 scores) ----------
    float ctx[8][4];
    #pragma unroll
    for (int nt = 0; nt < 8; ++nt)
        #pragma unroll
        for (int q = 0; q < 4; ++q) ctx[nt][q] = 0.f;

    load_k(0, 0);
    for (int jj = 0; jj < Sc; jj += 64) {
        const int cur = (jj >> 6) & 1;
        load_v(jj);
        if (jj + 64 < Sc) { load_k(jj + 64, cur ^ 1); cp_wait<1>(); }
        else              { cp_wait<0>(); }
        __syncthreads();
        float (*ks)[68] = cur ? ks1 : ks0;

        float c[8][4];
        #pragma unroll
        for (int nt = 0; nt < 8; ++nt)
            #pragma unroll
            for (int q = 0; q < 4; ++q) c[nt][q] = 0.f;
        #pragma unroll
        for (int kf = 0; kf < 8; ++kf) {
            const int k0 = kf * 8;
            #pragma unroll
            for (int nt = 0; nt < 8; ++nt) {
                const int n = nt * 8 + g;
                unsigned b0 = __float_as_uint(ks[n][k0 + t]);
                unsigned b1 = __float_as_uint(ks[n][k0 + t + 4]);
                mma_tf32(c[nt][0], c[nt][1], c[nt][2], c[nt][3],
                         A[kf][0], A[kf][1], A[kf][2], A[kf][3], b0, b1);
            }
        }

        const unsigned m00 = mp0[jj >> 5], m01 = mp0[(jj >> 5) + 1];
        const unsigned m10 = mp1[jj >> 5], m11 = mp1[(jj >> 5) + 1];

        unsigned pf[8][2];
        #pragma unroll
        for (int nt = 0; nt < 8; ++nt) {
            const int jl = nt * 8 + t * 2;
            const unsigned w0 = (jl & 32) ? m01 : m00;
            const unsigned w1 = (jl & 32) ? m11 : m10;
            const int sh = jl & 31;
            float p0 = ((w0 >> sh)       & 1u) ? 0.f : __expf(c[nt][0] * 0.125f) * invl0;
            float p1 = ((w0 >> (sh + 1)) & 1u) ? 0.f : __expf(c[nt][1] * 0.125f) * invl0;
            float p2 = ((w1 >> sh)       & 1u) ? 0.f : __expf(c[nt][2] * 0.125f) * invl1;
            float p3 = ((w1 >> (sh + 1)) & 1u) ? 0.f : __expf(c[nt][3] * 0.125f) * invl1;
            *(float2*)(arow0 + jj + jl) = make_float2(p0, p1);
            *(float2*)(arow1 + jj + jl) = make_float2(p2, p3);
            pf[nt][0] = pack_bf16x2(p0, p1);
            pf[nt][1] = pack_bf16x2(p2, p3);
        }

        #pragma unroll
        for (int kf = 0; kf < 4; ++kf) {
            const unsigned a0 = pf[2 * kf    ][0];
            const unsigned a1 = pf[2 * kf    ][1];
            const unsigned a2 = pf[2 * kf + 1][0];
            const unsigned a3 = pf[2 * kf + 1][1];
            const int k0 = kf * 16;
            #pragma unroll
            for (int q = 0; q < 4; ++q) {
                const int nt0 = 2 * q;
                unsigned r0, r1, r2, r3;
                ldm_x4(r0, r1, r2, r3,
                       &vs[(nt0 + (lm >> 1)) * 8 + lr][k0 + (lm & 1) * 8]);
                mma_bf16(ctx[nt0][0], ctx[nt0][1], ctx[nt0][2], ctx[nt0][3],
                         a0, a1, a2, a3, r0, r1);
                mma_bf16(ctx[nt0 + 1][0], ctx[nt0 + 1][1], ctx[nt0 + 1][2], ctx[nt0 + 1][3],
                         a0, a1, a2, a3, r2, r3);
            }
        }
        __syncthreads();
    }

    const int s = i0 + warp * 16 + g;
    const size_t crow0 = ((size_t)b * Sc + s)     * Dc;
    const size_t crow1 = ((size_t)b * Sc + s + 8) * Dc;
    #pragma unroll
    for (int nt = 0; nt < 8; ++nt) {
        const int col = h * DKc + nt * 8 + t * 2;
        *(__nv_bfloat162*)&g_ctxb[crow0 + col] = __floats2bfloat162_rn(ctx[nt][0], ctx[nt][1]);
        *(__nv_bfloat162*)&g_ctxb[crow1 + col] = __floats2bfloat162_rn(ctx[nt][2], ctx[nt][3]);
    }
}

// ---------------------------------------------------------------------------
// Kernel 3: output projection, bf16 MMA, cp.async 2-stage.
// ---------------------------------------------------------------------------
__global__ __launch_bounds__(256) void oproj_mma_kernel(
    const float* __restrict__ bo, const float* __restrict__ Qres)
{
    const __nv_bfloat16* Wt = g_wT[3];

    __shared__ __align__(16) __nv_bfloat16 as[2][128][40];
    __shared__ __align__(16) __nv_bfloat16 bs[2][128][40];

    const int tid  = threadIdx.x;
    const int warp = tid >> 5, lane = tid & 31;
    const int g = lane >> 2, t = lane & 3;
    const int wm = warp >> 1, wn = warp & 1;
    const int row0 = blockIdx.y * 128;
    const int col0 = blockIdx.x * 128;

    float c[2][8][4];
    #pragma unroll
    for (int mt = 0; mt < 2; ++mt)
        #pragma unroll
        for (int nt = 0; nt < 8; ++nt)
            #pragma unroll
            for (int q = 0; q < 4; ++q) c[mt][nt][q] = 0.f;

    auto load_stage = [&](int kk, int st) {
        #pragma unroll
        for (int it = 0; it < 2; ++it) {
            int f = tid + it * 256;
            int r = f >> 2, c8 = (f & 3) * 8;
            cp16(&as[st][r][c8], g_ctxb + (size_t)(row0 + r) * Dc + kk + c8);
            cp16(&bs[st][r][c8], Wt     + (size_t)(col0 + r) * Dc + kk + c8);
        }
        cp_commit();
    };

    load_stage(0, 0);

    const int nT = Dc / 32;
    for (int tt = 0; tt < nT; ++tt) {
        const int cur = tt & 1;
        if (tt + 1 < nT) { load_stage((tt + 1) * 32, cur ^ 1); cp_wait<1>(); }
        else             { cp_wait<0>(); }
        __syncthreads();

        #pragma unroll
        for (int kf = 0; kf < 2; ++kf) {
            const int k0 = kf * 16;
            unsigned A[2][4];
            #pragma unroll
            for (int mt = 0; mt < 2; ++mt) {
                int r = wm * 32 + mt * 16 + g;
                A[mt][0] = *(const unsigned*)&as[cur][r    ][k0     + t * 2];
                A[mt][1] = *(const unsigned*)&as[cur][r + 8][k0     + t * 2];
                A[mt][2] = *(const unsigned*)&as[cur][r    ][k0 + 8 + t * 2];
                A[mt][3] = *(const unsigned*)&as[cur][r + 8][k0 + 8 + t * 2];
            }
            #pragma unroll
            for (int nt = 0; nt < 8; ++nt) {
                int n = wn * 64 + nt * 8 + g;
                unsigned b0 = *(const unsigned*)&bs[cur][n][k0     + t * 2];
                unsigned b1 = *(const unsigned*)&bs[cur][n][k0 + 8 + t * 2];
                mma_bf16(c[0][nt][0], c[0][nt][1], c[0][nt][2], c[0][nt][3],
                         A[0][0], A[0][1], A[0][2], A[0][3], b0, b1);
                mma_bf16(c[1][nt][0], c[1][nt][1], c[1][nt][2], c[1][nt][3],
                         A[1][0], A[1][1], A[1][2], A[1][3], b0, b1);
            }
        }
        __syncthreads();
    }

    #pragma unroll
    for (int mt = 0; mt < 2; ++mt) {
        #pragma unroll
        for (int nt = 0; nt < 8; ++nt) {
            const int col = col0 + wn * 64 + nt * 8 + t * 2;
            const float bi0 = bo[col], bi1 = bo[col + 1];
            const int r0 = row0 + wm * 32 + mt * 16 + g;
            #pragma unroll
            for (int rr = 0; rr < 2; ++rr) {
                const int rowg = r0 + rr * 8;
                const float* res = Qres + (size_t)rowg * Dc + col;
                float2 rv = *(const float2*)res;
                float2 o = make_float2(c[mt][nt][rr * 2 + 0] + bi0 + rv.x,
                                       c[mt][nt][rr * 2 + 1] + bi1 + rv.y);
                *(float2*)(g_y + (size_t)rowg * Dc + col) = o;
            }
        }
    }
}

// ---------------------------------------------------------------------------
// Kernel 4: LayerNorm per row (fp32).
// ---------------------------------------------------------------------------
__global__ __launch_bounds__(256) void ln_kernel(
    const float* __restrict__ gamma, const float* __restrict__ beta,
    float* __restrict__ out)
{
    const int row = blockIdx.x;
    const int tid = threadIdx.x;
    const float* y = g_y + (size_t)row * Dc;

    float4 v = ((const float4*)y)[tid];
    float s  = v.x + v.y + v.z + v.w;
    float q  = v.x * v.x + v.y * v.y + v.z * v.z + v.w * v.w;

    __shared__ float ss[8];
    __shared__ float sq[8];
    #pragma unroll
    for (int o = 16; o > 0; o >>= 1) {
        s += __shfl_xor_sync(0xffffffffu, s, o);
        q += __shfl_xor_sync(0xffffffffu, q, o);
    }
    if ((tid & 31) == 0) { ss[tid >> 5] = s; sq[tid >> 5] = q; }
    __syncthreads();
    s = ss[tid & 7];
    q = sq[tid & 7];
    #pragma unroll
    for (int o = 4; o > 0; o >>= 1) {
        s += __shfl_xor_sync(0xffffffffu, s, o);
        q += __shfl_xor_sync(0xffffffffu, q, o);
    }

    const float mu  = s * (1.0f / Dc);
    const float var = q * (1.0f / Dc) - mu * mu;
    const float inv = rsqrtf(var + 1e-5f);

    float4 gv = ((const float4*)gamma)[tid];
    float4 bv = ((const float4*)beta)[tid];
    float4 o4 = make_float4((v.x - mu) * inv * gv.x + bv.x,
                            (v.y - mu) * inv * gv.y + bv.y,
                            (v.z - mu) * inv * gv.z + bv.z,
                            (v.w - mu) * inv * gv.w + bv.w);
    ((float4*)(out + (size_t)row * Dc))[tid] = o4;
}

// ---------------------------------------------------------------------------
// Launch
// ---------------------------------------------------------------------------
extern "C" void kernel_launch(void* const* d_in, const int* in_sizes, int n_in,
                              void* d_out, int out_size)
{
    const float* Qin  = (const float*)d_in[0];
    const unsigned* mask = (const unsigned*)d_in[3];
    const float* Wq = (const float*)d_in[4];
    const float* bq = (const float*)d_in[5];
    const float* Wk = (const float*)d_in[6];
    const float* bk = (const float*)d_in[7];
    const float* Wv = (const float*)d_in[8];
    const float* bv = (const float*)d_in[9];
    const float* Wo = (const float*)d_in[10];
    const float* bo = (const float*)d_in[11];
    const float* ln_g = (const float*)d_in[12];
    const float* ln_b = (const float*)d_in[13];

    float* out  = (float*)d_out;
    float* attn = out + (size_t)Bc * Sc * Dc;

    cvt_x_kernel    <<<(Mc * Dc) / 1024, 256>>>(Qin);
    cvt_wT_kernel   <<<dim3(32, 32, 4), 256>>>(Wq, Wk, Wv, Wo);
    mask_pack_kernel<<<(Bc * Sc * (Sc / 32)) / 8, 256>>>(mask);

    proj_qk_tf32_kernel<<<dim3(Dc / 128, Mc / 128, 2), 256>>>(bq, bk);
    proj_v_mma_kernel  <<<dim3(Dc / 128, Mc / 128), 256>>>(bv);
    attn_fused_kernel  <<<dim3(Sc / 128, BHc), 256>>>(attn);
    oproj_mma_kernel   <<<dim3(Dc / 128, Mc / 128), 256>>>(bo, Qin);
    ln_kernel          <<<Mc, 256>>>(ln_g, ln_b, out);
}

// round 10
// speedup vs baseline: 3.8323x; 1.2380x over previous
#include <cuda_runtime.h>
#include <cuda_bf16.h>

#define Bc   2
#define Sc   2048
#define Dc   1024
#define Hc   16
#define DKc  64
#define Mc   (Bc * Sc)        // 4096
#define BHc  (Bc * Hc)        // 32

// ---------------------------------------------------------------------------
// Scratch (__device__ globals; no cudaMalloc allowed)
// ---------------------------------------------------------------------------
__device__ __align__(16) __nv_bfloat16 g_xb [(size_t)Mc * Dc];          // X bf16 (V path)
__device__ __align__(16) float         g_xtf[(size_t)Mc * Dc];          // X tf32-rounded (QK path)
__device__ __align__(16) __nv_bfloat16 g_wT [4][(size_t)Dc * Dc];       // bf16 W^T ([2],[3] used)
__device__ __align__(16) float         g_wTf[2][(size_t)Dc * Dc];       // tf32-rounded W^T (Wq,Wk)
__device__ __align__(16) float         g_qf [(size_t)BHc * Sc * DKc];   // q tf32-rounded [bh][s][dk]
__device__ __align__(16) float         g_kf [(size_t)BHc * Sc * DKc];   // k tf32-rounded [bh][s][dk]
__device__ __align__(16) __nv_bfloat16 g_kb [(size_t)BHc * Sc * DKc];   // k bf16 (pass-1 sums)
__device__ __align__(16) __nv_bfloat16 g_vT [(size_t)BHc * DKc * Sc];   // v bf16 [bh][dk][s]
__device__ __align__(16) __nv_bfloat16 g_ctxb[(size_t)Mc * Dc];         // ctx bf16
__device__ unsigned g_mask[(size_t)Bc * Sc * (Sc / 32)];                 // bit-packed mask
__device__ __align__(16) float g_y [(size_t)Mc * Dc];                    // pre-LN

// ---------------------------------------------------------------------------
// MMA + async-copy + ldmatrix helpers
// ---------------------------------------------------------------------------
__device__ __forceinline__ void mma_bf16(
    float& c0, float& c1, float& c2, float& c3,
    unsigned a0, unsigned a1, unsigned a2, unsigned a3,
    unsigned b0, unsigned b1)
{
    asm volatile(
        "mma.sync.aligned.m16n8k16.row.col.f32.bf16.bf16.f32 "
        "{%0,%1,%2,%3}, {%4,%5,%6,%7}, {%8,%9}, {%0,%1,%2,%3};\n"
        : "+f"(c0), "+f"(c1), "+f"(c2), "+f"(c3)
        : "r"(a0), "r"(a1), "r"(a2), "r"(a3), "r"(b0), "r"(b1));
}

__device__ __forceinline__ void mma_tf32(
    float& c0, float& c1, float& c2, float& c3,
    unsigned a0, unsigned a1, unsigned a2, unsigned a3,
    unsigned b0, unsigned b1)
{
    asm volatile(
        "mma.sync.aligned.m16n8k8.row.col.f32.tf32.tf32.f32 "
        "{%0,%1,%2,%3}, {%4,%5,%6,%7}, {%8,%9}, {%0,%1,%2,%3};\n"
        : "+f"(c0), "+f"(c1), "+f"(c2), "+f"(c3)
        : "r"(a0), "r"(a1), "r"(a2), "r"(a3), "r"(b0), "r"(b1));
}

__device__ __forceinline__ float f2tf_f(float x)
{
    unsigned r;
    asm("cvt.rna.tf32.f32 %0, %1;" : "=r"(r) : "f"(x));
    return __uint_as_float(r);
}

__device__ __forceinline__ unsigned pack_bf16x2(float a, float b)
{
    unsigned r;
    asm("cvt.rn.bf16x2.f32 %0, %1, %2;" : "=r"(r) : "f"(b), "f"(a));
    return r;
}

__device__ __forceinline__ void cp16(void* smem, const void* gmem)
{
    unsigned sa = (unsigned)__cvta_generic_to_shared(smem);
    asm volatile("cp.async.cg.shared.global [%0], [%1], 16;\n"
                 :: "r"(sa), "l"(gmem));
}
__device__ __forceinline__ void cp_commit()
{
    asm volatile("cp.async.commit_group;\n");
}
template<int N> __device__ __forceinline__ void cp_wait()
{
    asm volatile("cp.async.wait_group %0;\n" :: "n"(N));
}

__device__ __forceinline__ void ldm_x4(unsigned& r0, unsigned& r1,
                                       unsigned& r2, unsigned& r3, const void* p)
{
    unsigned a = (unsigned)__cvta_generic_to_shared(p);
    asm volatile("ldmatrix.sync.aligned.m8n8.x4.shared.b16 {%0,%1,%2,%3}, [%4];\n"
                 : "=r"(r0), "=r"(r1), "=r"(r2), "=r"(r3) : "r"(a));
}

__device__ __forceinline__ void stcs2(float* p, float a, float b)
{
    asm volatile("st.global.cs.v2.f32 [%0], {%1, %2};\n"
                 :: "l"(p), "f"(a), "f"(b) : "memory");
}

// ---------------------------------------------------------------------------
// Pre-pass: X fp32 -> bf16 (V path) + tf32-rounded fp32 (QK path)
// ---------------------------------------------------------------------------
__global__ __launch_bounds__(256) void cvt_x_kernel(const float* __restrict__ X)
{
    size_t i = ((size_t)blockIdx.x * 256 + threadIdx.x) * 4;
    float4 v = *(const float4*)(X + i);
    __nv_bfloat162* d = (__nv_bfloat162*)(g_xb + i);
    d[0] = __floats2bfloat162_rn(v.x, v.y);
    d[1] = __floats2bfloat162_rn(v.z, v.w);
    float4 tv = make_float4(f2tf_f(v.x), f2tf_f(v.y), f2tf_f(v.z), f2tf_f(v.w));
    *(float4*)(g_xtf + i) = tv;
}

// ---------------------------------------------------------------------------
// Pre-pass: weights [k][n] -> transposed [n][k]; tf32 for Wq/Wk, bf16 Wv/Wo
// ---------------------------------------------------------------------------
__global__ __launch_bounds__(256) void cvt_wT_kernel(
    const float* __restrict__ W0, const float* __restrict__ W1,
    const float* __restrict__ W2, const float* __restrict__ W3)
{
    const int z = blockIdx.z;
    const float* W = z == 0 ? W0 : z == 1 ? W1 : z == 2 ? W2 : W3;
    __shared__ float tile[32][33];
    const int tx = threadIdx.x & 31, ty = threadIdx.x >> 5;
    const int k0 = blockIdx.x * 32, n0 = blockIdx.y * 32;
    #pragma unroll
    for (int i = 0; i < 4; ++i)
        tile[ty + i * 8][tx] = W[(size_t)(k0 + ty + i * 8) * Dc + n0 + tx];
    __syncthreads();
    if (z < 2) {
        float* out = g_wTf[z];
        #pragma unroll
        for (int i = 0; i < 4; ++i)
            out[(size_t)(n0 + ty + i * 8) * Dc + k0 + tx] = f2tf_f(tile[tx][ty + i * 8]);
    } else {
        __nv_bfloat16* out = g_wT[z];
        #pragma unroll
        for (int i = 0; i < 4; ++i)
            out[(size_t)(n0 + ty + i * 8) * Dc + k0 + tx] =
                __float2bfloat16(tile[tx][ty + i * 8]);
    }
}

// ---------------------------------------------------------------------------
// Pre-pass: bit-pack mask (int32 nonzero -> 1 bit)
// ---------------------------------------------------------------------------
__global__ __launch_bounds__(256) void mask_pack_kernel(const unsigned* __restrict__ mask)
{
    const int w    = blockIdx.x * 8 + (threadIdx.x >> 5);
    const int lane = threadIdx.x & 31;
    unsigned v = mask[(size_t)w * 32 + lane];
    unsigned bits = __ballot_sync(0xffffffffu, v != 0);
    if (lane == 0) g_mask[w] = bits;
}

// ---------------------------------------------------------------------------
// Kernel 1a: q/k projections, tf32, cp.async 2-stage, BK=16.
// z==1 additionally stores a bf16 copy of k (for attn pass-1 row sums).
// ---------------------------------------------------------------------------
__global__ __launch_bounds__(256) void proj_qk_tf32_kernel(
    const float* __restrict__ bq, const float* __restrict__ bk)
{
    const int z = blockIdx.z;
    const float* Wt = g_wTf[z];
    const float* bias = z == 0 ? bq : bk;
    float* outp = z == 0 ? g_qf : g_kf;

    __shared__ __align__(16) float as[2][128][20];
    __shared__ __align__(16) float bs[2][128][20];

    const int tid  = threadIdx.x;
    const int warp = tid >> 5, lane = tid & 31;
    const int g = lane >> 2, t = lane & 3;
    const int wm = warp >> 1, wn = warp & 1;
    const int row0 = blockIdx.y * 128;
    const int col0 = blockIdx.x * 128;

    float c[2][8][4];
    #pragma unroll
    for (int mt = 0; mt < 2; ++mt)
        #pragma unroll
        for (int nt = 0; nt < 8; ++nt)
            #pragma unroll
            for (int q = 0; q < 4; ++q) c[mt][nt][q] = 0.f;

    auto load_stage = [&](int kk, int st) {
        #pragma unroll
        for (int it = 0; it < 2; ++it) {
            int f = tid + it * 256;
            int r = f >> 2, c4 = (f & 3) * 4;
            cp16(&as[st][r][c4], g_xtf + (size_t)(row0 + r) * Dc + kk + c4);
            cp16(&bs[st][r][c4], Wt    + (size_t)(col0 + r) * Dc + kk + c4);
        }
        cp_commit();
    };

    load_stage(0, 0);

    const int nT = Dc / 16;   // 64
    for (int tt = 0; tt < nT; ++tt) {
        const int cur = tt & 1;
        if (tt + 1 < nT) { load_stage((tt + 1) * 16, cur ^ 1); cp_wait<1>(); }
        else             { cp_wait<0>(); }
        __syncthreads();

        #pragma unroll
        for (int kf = 0; kf < 2; ++kf) {
            const int k0 = kf * 8;
            unsigned A[2][4];
            #pragma unroll
            for (int mt = 0; mt < 2; ++mt) {
                int r = wm * 32 + mt * 16 + g;
                A[mt][0] = __float_as_uint(as[cur][r    ][k0 + t]);
                A[mt][1] = __float_as_uint(as[cur][r + 8][k0 + t]);
                A[mt][2] = __float_as_uint(as[cur][r    ][k0 + t + 4]);
                A[mt][3] = __float_as_uint(as[cur][r + 8][k0 + t + 4]);
            }
            #pragma unroll
            for (int nt = 0; nt < 8; ++nt) {
                int n = wn * 64 + nt * 8 + g;
                unsigned b0 = __float_as_uint(bs[cur][n][k0 + t]);
                unsigned b1 = __float_as_uint(bs[cur][n][k0 + t + 4]);
                mma_tf32(c[0][nt][0], c[0][nt][1], c[0][nt][2], c[0][nt][3],
                         A[0][0], A[0][1], A[0][2], A[0][3], b0, b1);
                mma_tf32(c[1][nt][0], c[1][nt][1], c[1][nt][2], c[1][nt][3],
                         A[1][0], A[1][1], A[1][2], A[1][3], b0, b1);
            }
        }
        __syncthreads();
    }

    #pragma unroll
    for (int mt = 0; mt < 2; ++mt) {
        #pragma unroll
        for (int nt = 0; nt < 8; ++nt) {
            const int col = col0 + wn * 64 + nt * 8 + t * 2;
            const int h = col >> 6, dk = col & 63;
            const float bi0 = bias[col], bi1 = bias[col + 1];
            const int r0 = row0 + wm * 32 + mt * 16 + g;
            #pragma unroll
            for (int rr = 0; rr < 2; ++rr) {
                const int rowg = r0 + rr * 8;
                const int b = rowg >> 11, s = rowg & 2047;
                const float v0 = c[mt][nt][rr * 2 + 0] + bi0;
                const float v1 = c[mt][nt][rr * 2 + 1] + bi1;
                const size_t off = ((size_t)(b * Hc + h) * Sc + s) * DKc + dk;
                *(float2*)(outp + off) = make_float2(f2tf_f(v0), f2tf_f(v1));
                if (z == 1)
                    *(__nv_bfloat162*)(g_kb + off) = __floats2bfloat162_rn(v0, v1);
            }
        }
    }
}

// ---------------------------------------------------------------------------
// Kernel 1b: v projection, bf16 MMA, cp.async 2-stage, BK=32.
// ---------------------------------------------------------------------------
__global__ __launch_bounds__(256) void proj_v_mma_kernel(const float* __restrict__ bv)
{
    const __nv_bfloat16* Wt = g_wT[2];

    __shared__ __align__(16) __nv_bfloat16 as[2][128][40];
    __shared__ __align__(16) __nv_bfloat16 bs[2][128][40];

    const int tid  = threadIdx.x;
    const int warp = tid >> 5, lane = tid & 31;
    const int g = lane >> 2, t = lane & 3;
    const int wm = warp >> 1, wn = warp & 1;
    const int row0 = blockIdx.y * 128;
    const int col0 = blockIdx.x * 128;

    float c[2][8][4];
    #pragma unroll
    for (int mt = 0; mt < 2; ++mt)
        #pragma unroll
        for (int nt = 0; nt < 8; ++nt)
            #pragma unroll
            for (int q = 0; q < 4; ++q) c[mt][nt][q] = 0.f;

    auto load_stage = [&](int kk, int st) {
        #pragma unroll
        for (int it = 0; it < 2; ++it) {
            int f = tid + it * 256;
            int r = f >> 2, c8 = (f & 3) * 8;
            cp16(&as[st][r][c8], g_xb + (size_t)(row0 + r) * Dc + kk + c8);
            cp16(&bs[st][r][c8], Wt   + (size_t)(col0 + r) * Dc + kk + c8);
        }
        cp_commit();
    };

    load_stage(0, 0);

    const int nT = Dc / 32;   // 32
    for (int tt = 0; tt < nT; ++tt) {
        const int cur = tt & 1;
        if (tt + 1 < nT) { load_stage((tt + 1) * 32, cur ^ 1); cp_wait<1>(); }
        else             { cp_wait<0>(); }
        __syncthreads();

        #pragma unroll
        for (int kf = 0; kf < 2; ++kf) {
            const int k0 = kf * 16;
            unsigned A[2][4];
            #pragma unroll
            for (int mt = 0; mt < 2; ++mt) {
                int r = wm * 32 + mt * 16 + g;
                A[mt][0] = *(const unsigned*)&as[cur][r    ][k0     + t * 2];
                A[mt][1] = *(const unsigned*)&as[cur][r + 8][k0     + t * 2];
                A[mt][2] = *(const unsigned*)&as[cur][r    ][k0 + 8 + t * 2];
                A[mt][3] = *(const unsigned*)&as[cur][r + 8][k0 + 8 + t * 2];
            }
            #pragma unroll
            for (int nt = 0; nt < 8; ++nt) {
                int n = wn * 64 + nt * 8 + g;
                unsigned b0 = *(const unsigned*)&bs[cur][n][k0     + t * 2];
                unsigned b1 = *(const unsigned*)&bs[cur][n][k0 + 8 + t * 2];
                mma_bf16(c[0][nt][0], c[0][nt][1], c[0][nt][2], c[0][nt][3],
                         A[0][0], A[0][1], A[0][2], A[0][3], b0, b1);
                mma_bf16(c[1][nt][0], c[1][nt][1], c[1][nt][2], c[1][nt][3],
                         A[1][0], A[1][1], A[1][2], A[1][3], b0, b1);
            }
        }
        __syncthreads();
    }

    #pragma unroll
    for (int mt = 0; mt < 2; ++mt) {
        #pragma unroll
        for (int nt = 0; nt < 8; ++nt) {
            const int col = col0 + wn * 64 + nt * 8 + t * 2;
            const int h = col >> 6, dk = col & 63;
            const float bi0 = bv[col], bi1 = bv[col + 1];
            const int r0 = row0 + wm * 32 + mt * 16 + g;
            #pragma unroll
            for (int rr = 0; rr < 2; ++rr) {
                const int rowg = r0 + rr * 8;
                const int b = rowg >> 11, s = rowg & 2047;
                g_vT[((size_t)(b * Hc + h) * DKc + dk    ) * Sc + s] =
                    __float2bfloat16(c[mt][nt][rr * 2 + 0] + bi0);
                g_vT[((size_t)(b * Hc + h) * DKc + dk + 1) * Sc + s] =
                    __float2bfloat16(c[mt][nt][rr * 2 + 1] + bi1);
            }
        }
    }
}

// ---------------------------------------------------------------------------
// Kernel 2: FUSED attention, 2 blocks/SM.
//   pass 1: bf16 q.k^T (ldmatrix B) -> masked-exp row sums only.
//   pass 2: tf32 q.k^T in two nt-halves (lower register pressure) ->
//           p = e/l, streaming-store p, C-frags -> bf16 A-frags of p @ V.
// ---------------------------------------------------------------------------
__global__ __launch_bounds__(256, 2) void attn_fused_kernel(float* __restrict__ attn)
{
    const int bh = blockIdx.y;
    const int i0 = blockIdx.x * 128;
    const int b  = bh >> 4, h = bh & 15;

    __shared__ __align__(16) unsigned char sbuf[44032];
    float (*qs)[68] = (float (*)[68])sbuf;
    __nv_bfloat16 (*kb0)[72] = (__nv_bfloat16 (*)[72])sbuf;
    __nv_bfloat16 (*kb1)[72] = (__nv_bfloat16 (*)[72])(sbuf + 9216);
    float (*ks0)[68] = (float (*)[68])sbuf;
    float (*ks1)[68] = (float (*)[68])(sbuf + 17408);
    __nv_bfloat16 (*vs)[72] = (__nv_bfloat16 (*)[72])(sbuf + 34816);

    const int tid = threadIdx.x, warp = tid >> 5, lane = tid & 31;
    const int g = lane >> 2, t = lane & 3;
    const int lm = lane >> 3, lr = lane & 7;

    const float* qbase = g_qf + ((size_t)bh * Sc + i0) * DKc;
    const float* kbase = g_kf + (size_t)bh * Sc * DKc;
    const __nv_bfloat16* kbbase = g_kb + (size_t)bh * Sc * DKc;
    const __nv_bfloat16* vbase  = g_vT + (size_t)bh * DKc * Sc;

    #pragma unroll
    for (int it = 0; it < 8; ++it) {
        int f = tid + it * 256;
        int r = f >> 4, c4 = (f & 15) * 4;
        *(float4*)&qs[r][c4] = *(const float4*)(qbase + (size_t)r * DKc + c4);
    }
    __syncthreads();

    unsigned A[8][4];    // tf32 fragments (pass 2)
    unsigned Ab[4][4];   // bf16 fragments (pass 1)
    {
        const int r = warp * 16 + g;
        #pragma unroll
        for (int kf = 0; kf < 8; ++kf) {
            const int k0 = kf * 8;
            A[kf][0] = __float_as_uint(qs[r    ][k0 + t]);
            A[kf][1] = __float_as_uint(qs[r + 8][k0 + t]);
            A[kf][2] = __float_as_uint(qs[r    ][k0 + t + 4]);
            A[kf][3] = __float_as_uint(qs[r + 8][k0 + t + 4]);
        }
        #pragma unroll
        for (int kf = 0; kf < 4; ++kf) {
            const int k0 = kf * 16;
            Ab[kf][0] = pack_bf16x2(qs[r    ][k0     + t * 2], qs[r    ][k0     + t * 2 + 1]);
            Ab[kf][1] = pack_bf16x2(qs[r + 8][k0     + t * 2], qs[r + 8][k0     + t * 2 + 1]);
            Ab[kf][2] = pack_bf16x2(qs[r    ][k0 + 8 + t * 2], qs[r    ][k0 + 8 + t * 2 + 1]);
            Ab[kf][3] = pack_bf16x2(qs[r + 8][k0 + 8 + t * 2], qs[r + 8][k0 + 8 + t * 2 + 1]);
        }
    }
    __syncthreads();

    const int ig0 = i0 + warp * 16 + g;
    const int ig1 = ig0 + 8;
    const unsigned* mp0 = g_mask + ((size_t)b * Sc + ig0) * (Sc / 32);
    const unsigned* mp1 = g_mask + ((size_t)b * Sc + ig1) * (Sc / 32);
    float* arow0 = attn + ((size_t)bh * Sc + ig0) * Sc;
    float* arow1 = attn + ((size_t)bh * Sc + ig1) * Sc;

    auto load_kb = [&](int jj, int st) {
        __nv_bfloat16 (*dst)[72] = st ? kb1 : kb0;
        #pragma unroll
        for (int it = 0; it < 2; ++it) {
            int f = tid + it * 256;
            int r = f >> 3, c8 = (f & 7) * 8;
            cp16(&dst[r][c8], kbbase + (size_t)(jj + r) * DKc + c8);
        }
        cp_commit();
    };
    auto load_k = [&](int jj, int st) {
        float (*dst)[68] = st ? ks1 : ks0;
        #pragma unroll
        for (int it = 0; it < 4; ++it) {
            int f = tid + it * 256;
            int r = f >> 4, c4 = (f & 15) * 4;
            cp16(&dst[r][c4], kbase + (size_t)(jj + r) * DKc + c4);
        }
        cp_commit();
    };
    auto load_v = [&](int jj) {
        #pragma unroll
        for (int it = 0; it < 2; ++it) {
            int f = tid + it * 256;
            int dk = f >> 3, c8 = (f & 7) * 8;
            cp16(&vs[dk][c8], vbase + (size_t)dk * Sc + jj + c8);
        }
        cp_commit();
    };

    // ---------------- pass 1: row sums (bf16 MMA, ldmatrix B) ----------------
    float rsum0 = 0.f, rsum1 = 0.f;
    load_kb(0, 0);
    for (int jj = 0; jj < Sc; jj += 64) {
        const int cur = (jj >> 6) & 1;
        if (jj + 64 < Sc) { load_kb(jj + 64, cur ^ 1); cp_wait<1>(); }
        else              { cp_wait<0>(); }
        __syncthreads();
        __nv_bfloat16 (*kb)[72] = cur ? kb1 : kb0;

        float c[8][4];
        #pragma unroll
        for (int nt = 0; nt < 8; ++nt)
            #pragma unroll
            for (int q = 0; q < 4; ++q) c[nt][q] = 0.f;
        #pragma unroll
        for (int kf = 0; kf < 4; ++kf) {
            const int k0 = kf * 16;
            #pragma unroll
            for (int q = 0; q < 4; ++q) {
                const int nt0 = 2 * q;
                unsigned r0, r1, r2, r3;
                ldm_x4(r0, r1, r2, r3,
                       &kb[(nt0 + (lm >> 1)) * 8 + lr][k0 + (lm & 1) * 8]);
                mma_bf16(c[nt0][0], c[nt0][1], c[nt0][2], c[nt0][3],
                         Ab[kf][0], Ab[kf][1], Ab[kf][2], Ab[kf][3], r0, r1);
                mma_bf16(c[nt0 + 1][0], c[nt0 + 1][1], c[nt0 + 1][2], c[nt0 + 1][3],
                         Ab[kf][0], Ab[kf][1], Ab[kf][2], Ab[kf][3], r2, r3);
            }
        }

        const unsigned m00 = mp0[jj >> 5], m01 = mp0[(jj >> 5) + 1];
        const unsigned m10 = mp1[jj >> 5], m11 = mp1[(jj >> 5) + 1];
        #pragma unroll
        for (int nt = 0; nt < 8; ++nt) {
            const int jl = nt * 8 + t * 2;
            const unsigned w0 = (jl & 32) ? m01 : m00;
            const unsigned w1 = (jl & 32) ? m11 : m10;
            const int sh = jl & 31;
            rsum0 += (((w0 >> sh)       & 1u) ? 0.f : __expf(c[nt][0] * 0.125f))
                   + (((w0 >> (sh + 1)) & 1u) ? 0.f : __expf(c[nt][1] * 0.125f));
            rsum1 += (((w1 >> sh)       & 1u) ? 0.f : __expf(c[nt][2] * 0.125f))
                   + (((w1 >> (sh + 1)) & 1u) ? 0.f : __expf(c[nt][3] * 0.125f));
        }
        __syncthreads();
    }
    rsum0 += __shfl_xor_sync(0xffffffffu, rsum0, 1);
    rsum0 += __shfl_xor_sync(0xffffffffu, rsum0, 2);
    rsum1 += __shfl_xor_sync(0xffffffffu, rsum1, 1);
    rsum1 += __shfl_xor_sync(0xffffffffu, rsum1, 2);
    const float invl0 = 1.0f / rsum0;
    const float invl1 = 1.0f / rsum1;

    // ---------------- pass 2: write p, ctx = p @ V (tf32 scores) ----------
    float ctx[8][4];
    #pragma unroll
    for (int nt = 0; nt < 8; ++nt)
        #pragma unroll
        for (int q = 0; q < 4; ++q) ctx[nt][q] = 0.f;

    load_k(0, 0);
    for (int jj = 0; jj < Sc; jj += 64) {
        const int cur = (jj >> 6) & 1;
        load_v(jj);
        if (jj + 64 < Sc) { load_k(jj + 64, cur ^ 1); cp_wait<1>(); }
        else              { cp_wait<0>(); }
        __syncthreads();
        float (*ks)[68] = cur ? ks1 : ks0;

        #pragma unroll
        for (int half = 0; half < 2; ++half) {
            float c[4][4];
            #pragma unroll
            for (int ntl = 0; ntl < 4; ++ntl)
                #pragma unroll
                for (int q = 0; q < 4; ++q) c[ntl][q] = 0.f;

            #pragma unroll
            for (int kf = 0; kf < 8; ++kf) {
                const int k0 = kf * 8;
                #pragma unroll
                for (int ntl = 0; ntl < 4; ++ntl) {
                    const int n = (half * 4 + ntl) * 8 + g;
                    unsigned b0 = __float_as_uint(ks[n][k0 + t]);
                    unsigned b1 = __float_as_uint(ks[n][k0 + t + 4]);
                    mma_tf32(c[ntl][0], c[ntl][1], c[ntl][2], c[ntl][3],
                             A[kf][0], A[kf][1], A[kf][2], A[kf][3], b0, b1);
                }
            }

            // masks: this half touches j-local [32*half, 32*half+32)
            const unsigned w0 = mp0[(jj >> 5) + half];
            const unsigned w1 = mp1[(jj >> 5) + half];

            unsigned pf[4][2];
            #pragma unroll
            for (int ntl = 0; ntl < 4; ++ntl) {
                const int nt = half * 4 + ntl;
                const int jl = nt * 8 + t * 2;
                const int sh = jl & 31;
                float p0 = ((w0 >> sh)       & 1u) ? 0.f : __expf(c[ntl][0] * 0.125f) * invl0;
                float p1 = ((w0 >> (sh + 1)) & 1u) ? 0.f : __expf(c[ntl][1] * 0.125f) * invl0;
                float p2 = ((w1 >> sh)       & 1u) ? 0.f : __expf(c[ntl][2] * 0.125f) * invl1;
                float p3 = ((w1 >> (sh + 1)) & 1u) ? 0.f : __expf(c[ntl][3] * 0.125f) * invl1;
                stcs2(arow0 + jj + jl, p0, p1);
                stcs2(arow1 + jj + jl, p2, p3);
                pf[ntl][0] = pack_bf16x2(p0, p1);
                pf[ntl][1] = pack_bf16x2(p2, p3);
            }

            #pragma unroll
            for (int kfl = 0; kfl < 2; ++kfl) {
                const int k0 = (half * 2 + kfl) * 16;
                const unsigned a0 = pf[2 * kfl    ][0];
                const unsigned a1 = pf[2 * kfl    ][1];
                const unsigned a2 = pf[2 * kfl + 1][0];
                const unsigned a3 = pf[2 * kfl + 1][1];
                #pragma unroll
                for (int q = 0; q < 4; ++q) {
                    const int nt0 = 2 * q;
                    unsigned r0, r1, r2, r3;
                    ldm_x4(r0, r1, r2, r3,
                           &vs[(nt0 + (lm >> 1)) * 8 + lr][k0 + (lm & 1) * 8]);
                    mma_bf16(ctx[nt0][0], ctx[nt0][1], ctx[nt0][2], ctx[nt0][3],
                             a0, a1, a2, a3, r0, r1);
                    mma_bf16(ctx[nt0 + 1][0], ctx[nt0 + 1][1], ctx[nt0 + 1][2], ctx[nt0 + 1][3],
                             a0, a1, a2, a3, r2, r3);
                }
            }
        }
        __syncthreads();
    }

    const int s = i0 + warp * 16 + g;
    const size_t crow0 = ((size_t)b * Sc + s)     * Dc;
    const size_t crow1 = ((size_t)b * Sc + s + 8) * Dc;
    #pragma unroll
    for (int nt = 0; nt < 8; ++nt) {
        const int col = h * DKc + nt * 8 + t * 2;
        *(__nv_bfloat162*)&g_ctxb[crow0 + col] = __floats2bfloat162_rn(ctx[nt][0], ctx[nt][1]);
        *(__nv_bfloat162*)&g_ctxb[crow1 + col] = __floats2bfloat162_rn(ctx[nt][2], ctx[nt][3]);
    }
}

// ---------------------------------------------------------------------------
// Kernel 3: output projection, bf16 MMA, cp.async 2-stage.
// ---------------------------------------------------------------------------
__global__ __launch_bounds__(256) void oproj_mma_kernel(
    const float* __restrict__ bo, const float* __restrict__ Qres)
{
    const __nv_bfloat16* Wt = g_wT[3];

    __shared__ __align__(16) __nv_bfloat16 as[2][128][40];
    __shared__ __align__(16) __nv_bfloat16 bs[2][128][40];

    const int tid  = threadIdx.x;
    const int warp = tid >> 5, lane = tid & 31;
    const int g = lane >> 2, t = lane & 3;
    const int wm = warp >> 1, wn = warp & 1;
    const int row0 = blockIdx.y * 128;
    const int col0 = blockIdx.x * 128;

    float c[2][8][4];
    #pragma unroll
    for (int mt = 0; mt < 2; ++mt)
        #pragma unroll
        for (int nt = 0; nt < 8; ++nt)
            #pragma unroll
            for (int q = 0; q < 4; ++q) c[mt][nt][q] = 0.f;

    auto load_stage = [&](int kk, int st) {
        #pragma unroll
        for (int it = 0; it < 2; ++it) {
            int f = tid + it * 256;
            int r = f >> 2, c8 = (f & 3) * 8;
            cp16(&as[st][r][c8], g_ctxb + (size_t)(row0 + r) * Dc + kk + c8);
            cp16(&bs[st][r][c8], Wt     + (size_t)(col0 + r) * Dc + kk + c8);
        }
        cp_commit();
    };

    load_stage(0, 0);

    const int nT = Dc / 32;
    for (int tt = 0; tt < nT; ++tt) {
        const int cur = tt & 1;
        if (tt + 1 < nT) { load_stage((tt + 1) * 32, cur ^ 1); cp_wait<1>(); }
        else             { cp_wait<0>(); }
        __syncthreads();

        #pragma unroll
        for (int kf = 0; kf < 2; ++kf) {
            const int k0 = kf * 16;
            unsigned A[2][4];
            #pragma unroll
            for (int mt = 0; mt < 2; ++mt) {
                int r = wm * 32 + mt * 16 + g;
                A[mt][0] = *(const unsigned*)&as[cur][r    ][k0     + t * 2];
                A[mt][1] = *(const unsigned*)&as[cur][r + 8][k0     + t * 2];
                A[mt][2] = *(const unsigned*)&as[cur][r    ][k0 + 8 + t * 2];
                A[mt][3] = *(const unsigned*)&as[cur][r + 8][k0 + 8 + t * 2];
            }
            #pragma unroll
            for (int nt = 0; nt < 8; ++nt) {
                int n = wn * 64 + nt * 8 + g;
                unsigned b0 = *(const unsigned*)&bs[cur][n][k0     + t * 2];
                unsigned b1 = *(const unsigned*)&bs[cur][n][k0 + 8 + t * 2];
                mma_bf16(c[0][nt][0], c[0][nt][1], c[0][nt][2], c[0][nt][3],
                         A[0][0], A[0][1], A[0][2], A[0][3], b0, b1);
                mma_bf16(c[1][nt][0], c[1][nt][1], c[1][nt][2], c[1][nt][3],
                         A[1][0], A[1][1], A[1][2], A[1][3], b0, b1);
            }
        }
        __syncthreads();
    }

    #pragma unroll
    for (int mt = 0; mt < 2; ++mt) {
        #pragma unroll
        for (int nt = 0; nt < 8; ++nt) {
            const int col = col0 + wn * 64 + nt * 8 + t * 2;
            const float bi0 = bo[col], bi1 = bo[col + 1];
            const int r0 = row0 + wm * 32 + mt * 16 + g;
            #pragma unroll
            for (int rr = 0; rr < 2; ++rr) {
                const int rowg = r0 + rr * 8;
                const float* res = Qres + (size_t)rowg * Dc + col;
                float2 rv = *(const float2*)res;
                float2 o = make_float2(c[mt][nt][rr * 2 + 0] + bi0 + rv.x,
                                       c[mt][nt][rr * 2 + 1] + bi1 + rv.y);
                *(float2*)(g_y + (size_t)rowg * Dc + col) = o;
            }
        }
    }
}

// ---------------------------------------------------------------------------
// Kernel 4: LayerNorm per row (fp32).
// ---------------------------------------------------------------------------
__global__ __launch_bounds__(256) void ln_kernel(
    const float* __restrict__ gamma, const float* __restrict__ beta,
    float* __restrict__ out)
{
    const int row = blockIdx.x;
    const int tid = threadIdx.x;
    const float* y = g_y + (size_t)row * Dc;

    float4 v = ((const float4*)y)[tid];
    float s  = v.x + v.y + v.z + v.w;
    float q  = v.x * v.x + v.y * v.y + v.z * v.z + v.w * v.w;

    __shared__ float ss[8];
    __shared__ float sq[8];
    #pragma unroll
    for (int o = 16; o > 0; o >>= 1) {
        s += __shfl_xor_sync(0xffffffffu, s, o);
        q += __shfl_xor_sync(0xffffffffu, q, o);
    }
    if ((tid & 31) == 0) { ss[tid >> 5] = s; sq[tid >> 5] = q; }
    __syncthreads();
    s = ss[tid & 7];
    q = sq[tid & 7];
    #pragma unroll
    for (int o = 4; o > 0; o >>= 1) {
        s += __shfl_xor_sync(0xffffffffu, s, o);
        q += __shfl_xor_sync(0xffffffffu, q, o);
    }

    const float mu  = s * (1.0f / Dc);
    const float var = q * (1.0f / Dc) - mu * mu;
    const float inv = rsqrtf(var + 1e-5f);

    float4 gv = ((const float4*)gamma)[tid];
    float4 bv = ((const float4*)beta)[tid];
    float4 o4 = make_float4((v.x - mu) * inv * gv.x + bv.x,
                            (v.y - mu) * inv * gv.y + bv.y,
                            (v.z - mu) * inv * gv.z + bv.z,
                            (v.w - mu) * inv * gv.w + bv.w);
    ((float4*)(out + (size_t)row * Dc))[tid] = o4;
}

// ---------------------------------------------------------------------------
// Launch
// ---------------------------------------------------------------------------
extern "C" void kernel_launch(void* const* d_in, const int* in_sizes, int n_in,
                              void* d_out, int out_size)
{
    const float* Qin  = (const float*)d_in[0];
    const unsigned* mask = (const unsigned*)d_in[3];
    const float* Wq = (const float*)d_in[4];
    const float* bq = (const float*)d_in[5];
    const float* Wk = (const float*)d_in[6];
    const float* bk = (const float*)d_in[7];
    const float* Wv = (const float*)d_in[8];
    const float* bv = (const float*)d_in[9];
    const float* Wo = (const float*)d_in[10];
    const float* bo = (const float*)d_in[11];
    const float* ln_g = (const float*)d_in[12];
    const float* ln_b = (const float*)d_in[13];

    float* out  = (float*)d_out;
    float* attn = out + (size_t)Bc * Sc * Dc;

    cvt_x_kernel    <<<(Mc * Dc) / 1024, 256>>>(Qin);
    cvt_wT_kernel   <<<dim3(32, 32, 4), 256>>>(Wq, Wk, Wv, Wo);
    mask_pack_kernel<<<(Bc * Sc * (Sc / 32)) / 8, 256>>>(mask);

    proj_qk_tf32_kernel<<<dim3(Dc / 128, Mc / 128, 2), 256>>>(bq, bk);
    proj_v_mma_kernel  <<<dim3(Dc / 128, Mc / 128), 256>>>(bv);
    attn_fused_kernel  <<<dim3(Sc / 128, BHc), 256>>>(attn);
    oproj_mma_kernel   <<<dim3(Dc / 128, Mc / 128), 256>>>(bo, Qin);
    ln_kernel          <<<Mc, 256>>>(ln_g, ln_b, out);
}

// round 11
// speedup vs baseline: 4.0363x; 1.0532x over previous
#include <cuda_runtime.h>
#include <cuda_bf16.h>

#define Bc   2
#define Sc   2048
#define Dc   1024
#define Hc   16
#define DKc  64
#define Mc   (Bc * Sc)        // 4096
#define BHc  (Bc * Hc)        // 32

// exp(0.125*x) == 2^(x * 0.125*log2(e))
#define EXP_SCALE 0.18033688011112042f

// ---------------------------------------------------------------------------
// Scratch (__device__ globals; no cudaMalloc allowed)
// ---------------------------------------------------------------------------
__device__ __align__(16) __nv_bfloat16 g_xb [(size_t)Mc * Dc];          // X bf16 (V path)
__device__ __align__(16) float         g_xtf[(size_t)Mc * Dc];          // X tf32-rounded (QK path)
__device__ __align__(16) __nv_bfloat16 g_wT [4][(size_t)Dc * Dc];       // bf16 W^T ([2],[3] used)
__device__ __align__(16) float         g_wTf[2][(size_t)Dc * Dc];       // tf32-rounded W^T (Wq,Wk)
__device__ __align__(16) float         g_qf [(size_t)BHc * Sc * DKc];   // q tf32-rounded [bh][s][dk]
__device__ __align__(16) float         g_kf [(size_t)BHc * Sc * DKc];   // k tf32-rounded [bh][s][dk]
__device__ __align__(16) __nv_bfloat16 g_kb [(size_t)BHc * Sc * DKc];   // k bf16 (pass-1 sums)
__device__ __align__(16) __nv_bfloat16 g_vT [(size_t)BHc * DKc * Sc];   // v bf16 [bh][dk][s]
__device__ __align__(16) __nv_bfloat16 g_ctxb[(size_t)Mc * Dc];         // ctx bf16
__device__ unsigned g_mask[(size_t)Bc * Sc * (Sc / 32)];                 // bit-packed mask
__device__ __align__(16) float g_y [(size_t)Mc * Dc];                    // pre-LN

// ---------------------------------------------------------------------------
// MMA + async-copy + ldmatrix helpers
// ---------------------------------------------------------------------------
__device__ __forceinline__ void mma_bf16(
    float& c0, float& c1, float& c2, float& c3,
    unsigned a0, unsigned a1, unsigned a2, unsigned a3,
    unsigned b0, unsigned b1)
{
    asm volatile(
        "mma.sync.aligned.m16n8k16.row.col.f32.bf16.bf16.f32 "
        "{%0,%1,%2,%3}, {%4,%5,%6,%7}, {%8,%9}, {%0,%1,%2,%3};\n"
        : "+f"(c0), "+f"(c1), "+f"(c2), "+f"(c3)
        : "r"(a0), "r"(a1), "r"(a2), "r"(a3), "r"(b0), "r"(b1));
}

__device__ __forceinline__ void mma_tf32(
    float& c0, float& c1, float& c2, float& c3,
    unsigned a0, unsigned a1, unsigned a2, unsigned a3,
    unsigned b0, unsigned b1)
{
    asm volatile(
        "mma.sync.aligned.m16n8k8.row.col.f32.tf32.tf32.f32 "
        "{%0,%1,%2,%3}, {%4,%5,%6,%7}, {%8,%9}, {%0,%1,%2,%3};\n"
        : "+f"(c0), "+f"(c1), "+f"(c2), "+f"(c3)
        : "r"(a0), "r"(a1), "r"(a2), "r"(a3), "r"(b0), "r"(b1));
}

__device__ __forceinline__ float f2tf_f(float x)
{
    unsigned r;
    asm("cvt.rna.tf32.f32 %0, %1;" : "=r"(r) : "f"(x));
    return __uint_as_float(r);
}

__device__ __forceinline__ unsigned pack_bf16x2(float a, float b)
{
    unsigned r;
    asm("cvt.rn.bf16x2.f32 %0, %1, %2;" : "=r"(r) : "f"(b), "f"(a));
    return r;
}

__device__ __forceinline__ float ex2(float x)
{
    float r;
    asm("ex2.approx.f32 %0, %1;" : "=f"(r) : "f"(x));
    return r;
}

__device__ __forceinline__ void cp16(void* smem, const void* gmem)
{
    unsigned sa = (unsigned)__cvta_generic_to_shared(smem);
    asm volatile("cp.async.cg.shared.global [%0], [%1], 16;\n"
                 :: "r"(sa), "l"(gmem));
}
__device__ __forceinline__ void cp_commit()
{
    asm volatile("cp.async.commit_group;\n");
}
template<int N> __device__ __forceinline__ void cp_wait()
{
    asm volatile("cp.async.wait_group %0;\n" :: "n"(N));
}

__device__ __forceinline__ void ldm_x4(unsigned& r0, unsigned& r1,
                                       unsigned& r2, unsigned& r3, const void* p)
{
    unsigned a = (unsigned)__cvta_generic_to_shared(p);
    asm volatile("ldmatrix.sync.aligned.m8n8.x4.shared.b16 {%0,%1,%2,%3}, [%4];\n"
                 : "=r"(r0), "=r"(r1), "=r"(r2), "=r"(r3) : "r"(a));
}

__device__ __forceinline__ void stcs2(float* p, float a, float b)
{
    asm volatile("st.global.cs.v2.f32 [%0], {%1, %2};\n"
                 :: "l"(p), "f"(a), "f"(b) : "memory");
}

// ---------------------------------------------------------------------------
// Pre-pass: X fp32 -> bf16 (V path) + tf32-rounded fp32 (QK path)
// ---------------------------------------------------------------------------
__global__ __launch_bounds__(256) void cvt_x_kernel(const float* __restrict__ X)
{
    size_t i = ((size_t)blockIdx.x * 256 + threadIdx.x) * 4;
    float4 v = *(const float4*)(X + i);
    __nv_bfloat162* d = (__nv_bfloat162*)(g_xb + i);
    d[0] = __floats2bfloat162_rn(v.x, v.y);
    d[1] = __floats2bfloat162_rn(v.z, v.w);
    float4 tv = make_float4(f2tf_f(v.x), f2tf_f(v.y), f2tf_f(v.z), f2tf_f(v.w));
    *(float4*)(g_xtf + i) = tv;
}

// ---------------------------------------------------------------------------
// Pre-pass: weights [k][n] -> transposed [n][k]; tf32 for Wq/Wk, bf16 Wv/Wo
// ---------------------------------------------------------------------------
__global__ __launch_bounds__(256) void cvt_wT_kernel(
    const float* __restrict__ W0, const float* __restrict__ W1,
    const float* __restrict__ W2, const float* __restrict__ W3)
{
    const int z = blockIdx.z;
    const float* W = z == 0 ? W0 : z == 1 ? W1 : z == 2 ? W2 : W3;
    __shared__ float tile[32][33];
    const int tx = threadIdx.x & 31, ty = threadIdx.x >> 5;
    const int k0 = blockIdx.x * 32, n0 = blockIdx.y * 32;
    #pragma unroll
    for (int i = 0; i < 4; ++i)
        tile[ty + i * 8][tx] = W[(size_t)(k0 + ty + i * 8) * Dc + n0 + tx];
    __syncthreads();
    if (z < 2) {
        float* out = g_wTf[z];
        #pragma unroll
        for (int i = 0; i < 4; ++i)
            out[(size_t)(n0 + ty + i * 8) * Dc + k0 + tx] = f2tf_f(tile[tx][ty + i * 8]);
    } else {
        __nv_bfloat16* out = g_wT[z];
        #pragma unroll
        for (int i = 0; i < 4; ++i)
            out[(size_t)(n0 + ty + i * 8) * Dc + k0 + tx] =
                __float2bfloat16(tile[tx][ty + i * 8]);
    }
}

// ---------------------------------------------------------------------------
// Pre-pass: bit-pack mask (int32 nonzero -> 1 bit)
// ---------------------------------------------------------------------------
__global__ __launch_bounds__(256) void mask_pack_kernel(const unsigned* __restrict__ mask)
{
    const int w    = blockIdx.x * 8 + (threadIdx.x >> 5);
    const int lane = threadIdx.x & 31;
    unsigned v = mask[(size_t)w * 32 + lane];
    unsigned bits = __ballot_sync(0xffffffffu, v != 0);
    if (lane == 0) g_mask[w] = bits;
}

// ---------------------------------------------------------------------------
// Kernel 1: ALL projections in one launch (better SM packing).
//   z=0: q (tf32, BK=16), z=1: k (tf32, + bf16 copy), z=2: v (bf16, BK=32).
// ---------------------------------------------------------------------------
__global__ __launch_bounds__(256, 2) void proj_all_kernel(
    const float* __restrict__ bq, const float* __restrict__ bk,
    const float* __restrict__ bv)
{
    __shared__ __align__(16) unsigned char smA[20480];
    __shared__ __align__(16) unsigned char smB[20480];

    const int z    = blockIdx.z;
    const int tid  = threadIdx.x;
    const int warp = tid >> 5, lane = tid & 31;
    const int g = lane >> 2, t = lane & 3;
    const int wm = warp >> 1, wn = warp & 1;
    const int row0 = blockIdx.y * 128;
    const int col0 = blockIdx.x * 128;

    float c[2][8][4];
    #pragma unroll
    for (int mt = 0; mt < 2; ++mt)
        #pragma unroll
        for (int nt = 0; nt < 8; ++nt)
            #pragma unroll
            for (int q = 0; q < 4; ++q) c[mt][nt][q] = 0.f;

    if (z < 2) {
        // ---------------- tf32 path (q / k) ----------------
        const float* Wt   = g_wTf[z];
        const float* bias = z == 0 ? bq : bk;
        float* outp = z == 0 ? g_qf : g_kf;

        float (*as)[128][20] = (float (*)[128][20])smA;
        float (*bs)[128][20] = (float (*)[128][20])smB;

        auto load_stage = [&](int kk, int st) {
            #pragma unroll
            for (int it = 0; it < 2; ++it) {
                int f = tid + it * 256;
                int r = f >> 2, c4 = (f & 3) * 4;
                cp16(&as[st][r][c4], g_xtf + (size_t)(row0 + r) * Dc + kk + c4);
                cp16(&bs[st][r][c4], Wt    + (size_t)(col0 + r) * Dc + kk + c4);
            }
            cp_commit();
        };

        load_stage(0, 0);
        const int nT = Dc / 16;
        for (int tt = 0; tt < nT; ++tt) {
            const int cur = tt & 1;
            if (tt + 1 < nT) { load_stage((tt + 1) * 16, cur ^ 1); cp_wait<1>(); }
            else             { cp_wait<0>(); }
            __syncthreads();

            #pragma unroll
            for (int kf = 0; kf < 2; ++kf) {
                const int k0 = kf * 8;
                unsigned A[2][4];
                #pragma unroll
                for (int mt = 0; mt < 2; ++mt) {
                    int r = wm * 32 + mt * 16 + g;
                    A[mt][0] = __float_as_uint(as[cur][r    ][k0 + t]);
                    A[mt][1] = __float_as_uint(as[cur][r + 8][k0 + t]);
                    A[mt][2] = __float_as_uint(as[cur][r    ][k0 + t + 4]);
                    A[mt][3] = __float_as_uint(as[cur][r + 8][k0 + t + 4]);
                }
                #pragma unroll
                for (int nt = 0; nt < 8; ++nt) {
                    int n = wn * 64 + nt * 8 + g;
                    unsigned b0 = __float_as_uint(bs[cur][n][k0 + t]);
                    unsigned b1 = __float_as_uint(bs[cur][n][k0 + t + 4]);
                    mma_tf32(c[0][nt][0], c[0][nt][1], c[0][nt][2], c[0][nt][3],
                             A[0][0], A[0][1], A[0][2], A[0][3], b0, b1);
                    mma_tf32(c[1][nt][0], c[1][nt][1], c[1][nt][2], c[1][nt][3],
                             A[1][0], A[1][1], A[1][2], A[1][3], b0, b1);
                }
            }
            __syncthreads();
        }

        #pragma unroll
        for (int mt = 0; mt < 2; ++mt) {
            #pragma unroll
            for (int nt = 0; nt < 8; ++nt) {
                const int col = col0 + wn * 64 + nt * 8 + t * 2;
                const int h = col >> 6, dk = col & 63;
                const float bi0 = bias[col], bi1 = bias[col + 1];
                const int r0 = row0 + wm * 32 + mt * 16 + g;
                #pragma unroll
                for (int rr = 0; rr < 2; ++rr) {
                    const int rowg = r0 + rr * 8;
                    const int b = rowg >> 11, s = rowg & 2047;
                    const float v0 = c[mt][nt][rr * 2 + 0] + bi0;
                    const float v1 = c[mt][nt][rr * 2 + 1] + bi1;
                    const size_t off = ((size_t)(b * Hc + h) * Sc + s) * DKc + dk;
                    *(float2*)(outp + off) = make_float2(f2tf_f(v0), f2tf_f(v1));
                    if (z == 1)
                        *(__nv_bfloat162*)(g_kb + off) = __floats2bfloat162_rn(v0, v1);
                }
            }
        }
    } else {
        // ---------------- bf16 path (v) ----------------
        const __nv_bfloat16* Wt = g_wT[2];

        __nv_bfloat16 (*as)[128][40] = (__nv_bfloat16 (*)[128][40])smA;
        __nv_bfloat16 (*bs)[128][40] = (__nv_bfloat16 (*)[128][40])smB;

        auto load_stage = [&](int kk, int st) {
            #pragma unroll
            for (int it = 0; it < 2; ++it) {
                int f = tid + it * 256;
                int r = f >> 2, c8 = (f & 3) * 8;
                cp16(&as[st][r][c8], g_xb + (size_t)(row0 + r) * Dc + kk + c8);
                cp16(&bs[st][r][c8], Wt   + (size_t)(col0 + r) * Dc + kk + c8);
            }
            cp_commit();
        };

        load_stage(0, 0);
        const int nT = Dc / 32;
        for (int tt = 0; tt < nT; ++tt) {
            const int cur = tt & 1;
            if (tt + 1 < nT) { load_stage((tt + 1) * 32, cur ^ 1); cp_wait<1>(); }
            else             { cp_wait<0>(); }
            __syncthreads();

            #pragma unroll
            for (int kf = 0; kf < 2; ++kf) {
                const int k0 = kf * 16;
                unsigned A[2][4];
                #pragma unroll
                for (int mt = 0; mt < 2; ++mt) {
                    int r = wm * 32 + mt * 16 + g;
                    A[mt][0] = *(const unsigned*)&as[cur][r    ][k0     + t * 2];
                    A[mt][1] = *(const unsigned*)&as[cur][r + 8][k0     + t * 2];
                    A[mt][2] = *(const unsigned*)&as[cur][r    ][k0 + 8 + t * 2];
                    A[mt][3] = *(const unsigned*)&as[cur][r + 8][k0 + 8 + t * 2];
                }
                #pragma unroll
                for (int nt = 0; nt < 8; ++nt) {
                    int n = wn * 64 + nt * 8 + g;
                    unsigned b0 = *(const unsigned*)&bs[cur][n][k0     + t * 2];
                    unsigned b1 = *(const unsigned*)&bs[cur][n][k0 + 8 + t * 2];
                    mma_bf16(c[0][nt][0], c[0][nt][1], c[0][nt][2], c[0][nt][3],
                             A[0][0], A[0][1], A[0][2], A[0][3], b0, b1);
                    mma_bf16(c[1][nt][0], c[1][nt][1], c[1][nt][2], c[1][nt][3],
                             A[1][0], A[1][1], A[1][2], A[1][3], b0, b1);
                }
            }
            __syncthreads();
        }

        #pragma unroll
        for (int mt = 0; mt < 2; ++mt) {
            #pragma unroll
            for (int nt = 0; nt < 8; ++nt) {
                const int col = col0 + wn * 64 + nt * 8 + t * 2;
                const int h = col >> 6, dk = col & 63;
                const float bi0 = bv[col], bi1 = bv[col + 1];
                const int r0 = row0 + wm * 32 + mt * 16 + g;
                #pragma unroll
                for (int rr = 0; rr < 2; ++rr) {
                    const int rowg = r0 + rr * 8;
                    const int b = rowg >> 11, s = rowg & 2047;
                    g_vT[((size_t)(b * Hc + h) * DKc + dk    ) * Sc + s] =
                        __float2bfloat16(c[mt][nt][rr * 2 + 0] + bi0);
                    g_vT[((size_t)(b * Hc + h) * DKc + dk + 1) * Sc + s] =
                        __float2bfloat16(c[mt][nt][rr * 2 + 1] + bi1);
                }
            }
        }
    }
}

// ---------------------------------------------------------------------------
// Kernel 2: FUSED attention, 2 blocks/SM.
//   pass 1: bf16 q.k^T (ldmatrix B) -> masked-exp row sums only.
//   pass 2: tf32 q.k^T in two nt-halves -> p = e/l, streaming-store p,
//           C-frags -> bf16 A-frags of p @ V (ldmatrix V).
// ---------------------------------------------------------------------------
__global__ __launch_bounds__(256, 2) void attn_fused_kernel(float* __restrict__ attn)
{
    const int bh = blockIdx.y;
    const int i0 = blockIdx.x * 128;
    const int b  = bh >> 4, h = bh & 15;

    __shared__ __align__(16) unsigned char sbuf[44032];
    float (*qs)[68] = (float (*)[68])sbuf;
    __nv_bfloat16 (*kb0)[72] = (__nv_bfloat16 (*)[72])sbuf;
    __nv_bfloat16 (*kb1)[72] = (__nv_bfloat16 (*)[72])(sbuf + 9216);
    float (*ks0)[68] = (float (*)[68])sbuf;
    float (*ks1)[68] = (float (*)[68])(sbuf + 17408);
    __nv_bfloat16 (*vs)[72] = (__nv_bfloat16 (*)[72])(sbuf + 34816);

    const int tid = threadIdx.x, warp = tid >> 5, lane = tid & 31;
    const int g = lane >> 2, t = lane & 3;
    const int lm = lane >> 3, lr = lane & 7;

    const float* qbase = g_qf + ((size_t)bh * Sc + i0) * DKc;
    const float* kbase = g_kf + (size_t)bh * Sc * DKc;
    const __nv_bfloat16* kbbase = g_kb + (size_t)bh * Sc * DKc;
    const __nv_bfloat16* vbase  = g_vT + (size_t)bh * DKc * Sc;

    #pragma unroll
    for (int it = 0; it < 8; ++it) {
        int f = tid + it * 256;
        int r = f >> 4, c4 = (f & 15) * 4;
        *(float4*)&qs[r][c4] = *(const float4*)(qbase + (size_t)r * DKc + c4);
    }
    __syncthreads();

    unsigned A[8][4];    // tf32 fragments (pass 2)
    unsigned Ab[4][4];   // bf16 fragments (pass 1)
    {
        const int r = warp * 16 + g;
        #pragma unroll
        for (int kf = 0; kf < 8; ++kf) {
            const int k0 = kf * 8;
            A[kf][0] = __float_as_uint(qs[r    ][k0 + t]);
            A[kf][1] = __float_as_uint(qs[r + 8][k0 + t]);
            A[kf][2] = __float_as_uint(qs[r    ][k0 + t + 4]);
            A[kf][3] = __float_as_uint(qs[r + 8][k0 + t + 4]);
        }
        #pragma unroll
        for (int kf = 0; kf < 4; ++kf) {
            const int k0 = kf * 16;
            Ab[kf][0] = pack_bf16x2(qs[r    ][k0     + t * 2], qs[r    ][k0     + t * 2 + 1]);
            Ab[kf][1] = pack_bf16x2(qs[r + 8][k0     + t * 2], qs[r + 8][k0     + t * 2 + 1]);
            Ab[kf][2] = pack_bf16x2(qs[r    ][k0 + 8 + t * 2], qs[r    ][k0 + 8 + t * 2 + 1]);
            Ab[kf][3] = pack_bf16x2(qs[r + 8][k0 + 8 + t * 2], qs[r + 8][k0 + 8 + t * 2 + 1]);
        }
    }
    __syncthreads();

    const int ig0 = i0 + warp * 16 + g;
    const int ig1 = ig0 + 8;
    const unsigned* mp0 = g_mask + ((size_t)b * Sc + ig0) * (Sc / 32);
    const unsigned* mp1 = g_mask + ((size_t)b * Sc + ig1) * (Sc / 32);
    float* arow0 = attn + ((size_t)bh * Sc + ig0) * Sc;
    float* arow1 = attn + ((size_t)bh * Sc + ig1) * Sc;

    auto load_kb = [&](int jj, int st) {
        __nv_bfloat16 (*dst)[72] = st ? kb1 : kb0;
        #pragma unroll
        for (int it = 0; it < 2; ++it) {
            int f = tid + it * 256;
            int r = f >> 3, c8 = (f & 7) * 8;
            cp16(&dst[r][c8], kbbase + (size_t)(jj + r) * DKc + c8);
        }
        cp_commit();
    };
    auto load_k = [&](int jj, int st) {
        float (*dst)[68] = st ? ks1 : ks0;
        #pragma unroll
        for (int it = 0; it < 4; ++it) {
            int f = tid + it * 256;
            int r = f >> 4, c4 = (f & 15) * 4;
            cp16(&dst[r][c4], kbase + (size_t)(jj + r) * DKc + c4);
        }
        cp_commit();
    };
    auto load_v = [&](int jj) {
        #pragma unroll
        for (int it = 0; it < 2; ++it) {
            int f = tid + it * 256;
            int dk = f >> 3, c8 = (f & 7) * 8;
            cp16(&vs[dk][c8], vbase + (size_t)dk * Sc + jj + c8);
        }
        cp_commit();
    };

    // ---------------- pass 1: row sums (bf16 MMA, ldmatrix B) ----------------
    float rsum0 = 0.f, rsum1 = 0.f;
    load_kb(0, 0);
    for (int jj = 0; jj < Sc; jj += 64) {
        const int cur = (jj >> 6) & 1;
        if (jj + 64 < Sc) { load_kb(jj + 64, cur ^ 1); cp_wait<1>(); }
        else              { cp_wait<0>(); }
        __syncthreads();
        __nv_bfloat16 (*kb)[72] = cur ? kb1 : kb0;

        float c[8][4];
        #pragma unroll
        for (int nt = 0; nt < 8; ++nt)
            #pragma unroll
            for (int q = 0; q < 4; ++q) c[nt][q] = 0.f;
        #pragma unroll
        for (int kf = 0; kf < 4; ++kf) {
            const int k0 = kf * 16;
            #pragma unroll
            for (int q = 0; q < 4; ++q) {
                const int nt0 = 2 * q;
                unsigned r0, r1, r2, r3;
                ldm_x4(r0, r1, r2, r3,
                       &kb[(nt0 + (lm >> 1)) * 8 + lr][k0 + (lm & 1) * 8]);
                mma_bf16(c[nt0][0], c[nt0][1], c[nt0][2], c[nt0][3],
                         Ab[kf][0], Ab[kf][1], Ab[kf][2], Ab[kf][3], r0, r1);
                mma_bf16(c[nt0 + 1][0], c[nt0 + 1][1], c[nt0 + 1][2], c[nt0 + 1][3],
                         Ab[kf][0], Ab[kf][1], Ab[kf][2], Ab[kf][3], r2, r3);
            }
        }

        const unsigned m00 = mp0[jj >> 5], m01 = mp0[(jj >> 5) + 1];
        const unsigned m10 = mp1[jj >> 5], m11 = mp1[(jj >> 5) + 1];
        #pragma unroll
        for (int nt = 0; nt < 8; ++nt) {
            const int jl = nt * 8 + t * 2;
            const unsigned w0 = (jl & 32) ? m01 : m00;
            const unsigned w1 = (jl & 32) ? m11 : m10;
            const int sh = jl & 31;
            rsum0 += (((w0 >> sh)       & 1u) ? 0.f : ex2(c[nt][0] * EXP_SCALE))
                   + (((w0 >> (sh + 1)) & 1u) ? 0.f : ex2(c[nt][1] * EXP_SCALE));
            rsum1 += (((w1 >> sh)       & 1u) ? 0.f : ex2(c[nt][2] * EXP_SCALE))
                   + (((w1 >> (sh + 1)) & 1u) ? 0.f : ex2(c[nt][3] * EXP_SCALE));
        }
        __syncthreads();
    }
    rsum0 += __shfl_xor_sync(0xffffffffu, rsum0, 1);
    rsum0 += __shfl_xor_sync(0xffffffffu, rsum0, 2);
    rsum1 += __shfl_xor_sync(0xffffffffu, rsum1, 1);
    rsum1 += __shfl_xor_sync(0xffffffffu, rsum1, 2);
    const float invl0 = 1.0f / rsum0;
    const float invl1 = 1.0f / rsum1;

    // ---------------- pass 2: write p, ctx = p @ V (tf32 scores) ----------
    float ctx[8][4];
    #pragma unroll
    for (int nt = 0; nt < 8; ++nt)
        #pragma unroll
        for (int q = 0; q < 4; ++q) ctx[nt][q] = 0.f;

    load_k(0, 0);
    for (int jj = 0; jj < Sc; jj += 64) {
        const int cur = (jj >> 6) & 1;
        load_v(jj);
        if (jj + 64 < Sc) { load_k(jj + 64, cur ^ 1); cp_wait<1>(); }
        else              { cp_wait<0>(); }
        __syncthreads();
        float (*ks)[68] = cur ? ks1 : ks0;

        #pragma unroll
        for (int half = 0; half < 2; ++half) {
            float c[4][4];
            #pragma unroll
            for (int ntl = 0; ntl < 4; ++ntl)
                #pragma unroll
                for (int q = 0; q < 4; ++q) c[ntl][q] = 0.f;

            #pragma unroll
            for (int kf = 0; kf < 8; ++kf) {
                const int k0 = kf * 8;
                #pragma unroll
                for (int ntl = 0; ntl < 4; ++ntl) {
                    const int n = (half * 4 + ntl) * 8 + g;
                    unsigned b0 = __float_as_uint(ks[n][k0 + t]);
                    unsigned b1 = __float_as_uint(ks[n][k0 + t + 4]);
                    mma_tf32(c[ntl][0], c[ntl][1], c[ntl][2], c[ntl][3],
                             A[kf][0], A[kf][1], A[kf][2], A[kf][3], b0, b1);
                }
            }

            const unsigned w0 = mp0[(jj >> 5) + half];
            const unsigned w1 = mp1[(jj >> 5) + half];

            unsigned pf[4][2];
            #pragma unroll
            for (int ntl = 0; ntl < 4; ++ntl) {
                const int nt = half * 4 + ntl;
                const int jl = nt * 8 + t * 2;
                const int sh = jl & 31;
                float p0 = ((w0 >> sh)       & 1u) ? 0.f : ex2(c[ntl][0] * EXP_SCALE) * invl0;
                float p1 = ((w0 >> (sh + 1)) & 1u) ? 0.f : ex2(c[ntl][1] * EXP_SCALE) * invl0;
                float p2 = ((w1 >> sh)       & 1u) ? 0.f : ex2(c[ntl][2] * EXP_SCALE) * invl1;
                float p3 = ((w1 >> (sh + 1)) & 1u) ? 0.f : ex2(c[ntl][3] * EXP_SCALE) * invl1;
                stcs2(arow0 + jj + jl, p0, p1);
                stcs2(arow1 + jj + jl, p2, p3);
                pf[ntl][0] = pack_bf16x2(p0, p1);
                pf[ntl][1] = pack_bf16x2(p2, p3);
            }

            #pragma unroll
            for (int kfl = 0; kfl < 2; ++kfl) {
                const int k0 = (half * 2 + kfl) * 16;
                const unsigned a0 = pf[2 * kfl    ][0];
                const unsigned a1 = pf[2 * kfl    ][1];
                const unsigned a2 = pf[2 * kfl + 1][0];
                const unsigned a3 = pf[2 * kfl + 1][1];
                #pragma unroll
                for (int q = 0; q < 4; ++q) {
                    const int nt0 = 2 * q;
                    unsigned r0, r1, r2, r3;
                    ldm_x4(r0, r1, r2, r3,
                           &vs[(nt0 + (lm >> 1)) * 8 + lr][k0 + (lm & 1) * 8]);
                    mma_bf16(ctx[nt0][0], ctx[nt0][1], ctx[nt0][2], ctx[nt0][3],
                             a0, a1, a2, a3, r0, r1);
                    mma_bf16(ctx[nt0 + 1][0], ctx[nt0 + 1][1], ctx[nt0 + 1][2], ctx[nt0 + 1][3],
                             a0, a1, a2, a3, r2, r3);
                }
            }
        }
        __syncthreads();
    }

    const int s = i0 + warp * 16 + g;
    const size_t crow0 = ((size_t)b * Sc + s)     * Dc;
    const size_t crow1 = ((size_t)b * Sc + s + 8) * Dc;
    #pragma unroll
    for (int nt = 0; nt < 8; ++nt) {
        const int col = h * DKc + nt * 8 + t * 2;
        *(__nv_bfloat162*)&g_ctxb[crow0 + col] = __floats2bfloat162_rn(ctx[nt][0], ctx[nt][1]);
        *(__nv_bfloat162*)&g_ctxb[crow1 + col] = __floats2bfloat162_rn(ctx[nt][2], ctx[nt][3]);
    }
}

// ---------------------------------------------------------------------------
// Kernel 3: output projection, bf16 MMA, cp.async 2-stage.
// ---------------------------------------------------------------------------
__global__ __launch_bounds__(256, 2) void oproj_mma_kernel(
    const float* __restrict__ bo, const float* __restrict__ Qres)
{
    const __nv_bfloat16* Wt = g_wT[3];

    __shared__ __align__(16) __nv_bfloat16 as[2][128][40];
    __shared__ __align__(16) __nv_bfloat16 bs[2][128][40];

    const int tid  = threadIdx.x;
    const int warp = tid >> 5, lane = tid & 31;
    const int g = lane >> 2, t = lane & 3;
    const int wm = warp >> 1, wn = warp & 1;
    const int row0 = blockIdx.y * 128;
    const int col0 = blockIdx.x * 128;

    float c[2][8][4];
    #pragma unroll
    for (int mt = 0; mt < 2; ++mt)
        #pragma unroll
        for (int nt = 0; nt < 8; ++nt)
            #pragma unroll
            for (int q = 0; q < 4; ++q) c[mt][nt][q] = 0.f;

    auto load_stage = [&](int kk, int st) {
        #pragma unroll
        for (int it = 0; it < 2; ++it) {
            int f = tid + it * 256;
            int r = f >> 2, c8 = (f & 3) * 8;
            cp16(&as[st][r][c8], g_ctxb + (size_t)(row0 + r) * Dc + kk + c8);
            cp16(&bs[st][r][c8], Wt     + (size_t)(col0 + r) * Dc + kk + c8);
        }
        cp_commit();
    };

    load_stage(0, 0);

    const int nT = Dc / 32;
    for (int tt = 0; tt < nT; ++tt) {
        const int cur = tt & 1;
        if (tt + 1 < nT) { load_stage((tt + 1) * 32, cur ^ 1); cp_wait<1>(); }
        else             { cp_wait<0>(); }
        __syncthreads();

        #pragma unroll
        for (int kf = 0; kf < 2; ++kf) {
            const int k0 = kf * 16;
            unsigned A[2][4];
            #pragma unroll
            for (int mt = 0; mt < 2; ++mt) {
                int r = wm * 32 + mt * 16 + g;
                A[mt][0] = *(const unsigned*)&as[cur][r    ][k0     + t * 2];
                A[mt][1] = *(const unsigned*)&as[cur][r + 8][k0     + t * 2];
                A[mt][2] = *(const unsigned*)&as[cur][r    ][k0 + 8 + t * 2];
                A[mt][3] = *(const unsigned*)&as[cur][r + 8][k0 + 8 + t * 2];
            }
            #pragma unroll
            for (int nt = 0; nt < 8; ++nt) {
                int n = wn * 64 + nt * 8 + g;
                unsigned b0 = *(const unsigned*)&bs[cur][n][k0     + t * 2];
                unsigned b1 = *(const unsigned*)&bs[cur][n][k0 + 8 + t * 2];
                mma_bf16(c[0][nt][0], c[0][nt][1], c[0][nt][2], c[0][nt][3],
                         A[0][0], A[0][1], A[0][2], A[0][3], b0, b1);
                mma_bf16(c[1][nt][0], c[1][nt][1], c[1][nt][2], c[1][nt][3],
                         A[1][0], A[1][1], A[1][2], A[1][3], b0, b1);
            }
        }
        __syncthreads();
    }

    #pragma unroll
    for (int mt = 0; mt < 2; ++mt) {
        #pragma unroll
        for (int nt = 0; nt < 8; ++nt) {
            const int col = col0 + wn * 64 + nt * 8 + t * 2;
            const float bi0 = bo[col], bi1 = bo[col + 1];
            const int r0 = row0 + wm * 32 + mt * 16 + g;
            #pragma unroll
            for (int rr = 0; rr < 2; ++rr) {
                const int rowg = r0 + rr * 8;
                const float* res = Qres + (size_t)rowg * Dc + col;
                float2 rv = *(const float2*)res;
                float2 o = make_float2(c[mt][nt][rr * 2 + 0] + bi0 + rv.x,
                                       c[mt][nt][rr * 2 + 1] + bi1 + rv.y);
                *(float2*)(g_y + (size_t)rowg * Dc + col) = o;
            }
        }
    }
}

// ---------------------------------------------------------------------------
// Kernel 4: LayerNorm per row (fp32).
// ---------------------------------------------------------------------------
__global__ __launch_bounds__(256) void ln_kernel(
    const float* __restrict__ gamma, const float* __restrict__ beta,
    float* __restrict__ out)
{
    const int row = blockIdx.x;
    const int tid = threadIdx.x;
    const float* y = g_y + (size_t)row * Dc;

    float4 v = ((const float4*)y)[tid];
    float s  = v.x + v.y + v.z + v.w;
    float q  = v.x * v.x + v.y * v.y + v.z * v.z + v.w * v.w;

    __shared__ float ss[8];
    __shared__ float sq[8];
    #pragma unroll
    for (int o = 16; o > 0; o >>= 1) {
        s += __shfl_xor_sync(0xffffffffu, s, o);
        q += __shfl_xor_sync(0xffffffffu, q, o);
    }
    if ((tid & 31) == 0) { ss[tid >> 5] = s; sq[tid >> 5] = q; }
    __syncthreads();
    s = ss[tid & 7];
    q = sq[tid & 7];
    #pragma unroll
    for (int o = 4; o > 0; o >>= 1) {
        s += __shfl_xor_sync(0xffffffffu, s, o);
        q += __shfl_xor_sync(0xffffffffu, q, o);
    }

    const float mu  = s * (1.0f / Dc);
    const float var = q * (1.0f / Dc) - mu * mu;
    const float inv = rsqrtf(var + 1e-5f);

    float4 gv = ((const float4*)gamma)[tid];
    float4 bv = ((const float4*)beta)[tid];
    float4 o4 = make_float4((v.x - mu) * inv * gv.x + bv.x,
                            (v.y - mu) * inv * gv.y + bv.y,
                            (v.z - mu) * inv * gv.z + bv.z,
                            (v.w - mu) * inv * gv.w + bv.w);
    ((float4*)(out + (size_t)row * Dc))[tid] = o4;
}

// ---------------------------------------------------------------------------
// Launch
// ---------------------------------------------------------------------------
extern "C" void kernel_launch(void* const* d_in, const int* in_sizes, int n_in,
                              void* d_out, int out_size)
{
    const float* Qin  = (const float*)d_in[0];
    const unsigned* mask = (const unsigned*)d_in[3];
    const float* Wq = (const float*)d_in[4];
    const float* bq = (const float*)d_in[5];
    const float* Wk = (const float*)d_in[6];
    const float* bk = (const float*)d_in[7];
    const float* Wv = (const float*)d_in[8];
    const float* bv = (const float*)d_in[9];
    const float* Wo = (const float*)d_in[10];
    const float* bo = (const float*)d_in[11];
    const float* ln_g = (const float*)d_in[12];
    const float* ln_b = (const float*)d_in[13];

    float* out  = (float*)d_out;
    float* attn = out + (size_t)Bc * Sc * Dc;

    cvt_x_kernel    <<<(Mc * Dc) / 1024, 256>>>(Qin);
    cvt_wT_kernel   <<<dim3(32, 32, 4), 256>>>(Wq, Wk, Wv, Wo);
    mask_pack_kernel<<<(Bc * Sc * (Sc / 32)) / 8, 256>>>(mask);

    proj_all_kernel  <<<dim3(Dc / 128, Mc / 128, 3), 256>>>(bq, bk, bv);
    attn_fused_kernel<<<dim3(Sc / 128, BHc), 256>>>(attn);
    oproj_mma_kernel <<<dim3(Dc / 128, Mc / 128), 256>>>(bo, Qin);
    ln_kernel        <<<Mc, 256>>>(ln_g, ln_b, out);
}

// round 12
// speedup vs baseline: 4.1489x; 1.0279x over previous
#include <cuda_runtime.h>
#include <cuda_bf16.h>

#define Bc   2
#define Sc   2048
#define Dc   1024
#define Hc   16
#define DKc  64
#define Mc   (Bc * Sc)        // 4096
#define BHc  (Bc * Hc)        // 32

// exp(0.125*x) == 2^(x * 0.125*log2(e))
#define EXP_SCALE 0.18033688011112042f

// ---------------------------------------------------------------------------
// Scratch (__device__ globals; no cudaMalloc allowed)
// ---------------------------------------------------------------------------
__device__ __align__(16) __nv_bfloat16 g_xb [(size_t)Mc * Dc];          // X bf16 (V path)
__device__ __align__(16) float         g_xtf[(size_t)Mc * Dc];          // X tf32-rounded (QK path)
__device__ __align__(16) __nv_bfloat16 g_wT [4][(size_t)Dc * Dc];       // bf16 W^T ([2],[3] used)
__device__ __align__(16) float         g_wTf[2][(size_t)Dc * Dc];       // tf32-rounded W^T (Wq,Wk)
__device__ __align__(16) float         g_qf [(size_t)BHc * Sc * DKc];   // q tf32-rounded [bh][s][dk]
__device__ __align__(16) float         g_kf [(size_t)BHc * Sc * DKc];   // k tf32-rounded [bh][s][dk]
__device__ __align__(16) __nv_bfloat16 g_kb [(size_t)BHc * Sc * DKc];   // k bf16 (pass-1 sums)
__device__ __align__(16) __nv_bfloat16 g_vT [(size_t)BHc * DKc * Sc];   // v bf16 [bh][dk][s]
__device__ __align__(16) __nv_bfloat16 g_ctxb[(size_t)Mc * Dc];         // ctx bf16
__device__ unsigned g_mask[(size_t)Bc * Sc * (Sc / 32)];                 // bit-packed mask
__device__ __align__(16) float g_y [(size_t)Mc * Dc];                    // pre-LN

// ---------------------------------------------------------------------------
// MMA + async-copy + ldmatrix helpers
// ---------------------------------------------------------------------------
__device__ __forceinline__ void mma_bf16(
    float& c0, float& c1, float& c2, float& c3,
    unsigned a0, unsigned a1, unsigned a2, unsigned a3,
    unsigned b0, unsigned b1)
{
    asm volatile(
        "mma.sync.aligned.m16n8k16.row.col.f32.bf16.bf16.f32 "
        "{%0,%1,%2,%3}, {%4,%5,%6,%7}, {%8,%9}, {%0,%1,%2,%3};\n"
        : "+f"(c0), "+f"(c1), "+f"(c2), "+f"(c3)
        : "r"(a0), "r"(a1), "r"(a2), "r"(a3), "r"(b0), "r"(b1));
}

__device__ __forceinline__ void mma_tf32(
    float& c0, float& c1, float& c2, float& c3,
    unsigned a0, unsigned a1, unsigned a2, unsigned a3,
    unsigned b0, unsigned b1)
{
    asm volatile(
        "mma.sync.aligned.m16n8k8.row.col.f32.tf32.tf32.f32 "
        "{%0,%1,%2,%3}, {%4,%5,%6,%7}, {%8,%9}, {%0,%1,%2,%3};\n"
        : "+f"(c0), "+f"(c1), "+f"(c2), "+f"(c3)
        : "r"(a0), "r"(a1), "r"(a2), "r"(a3), "r"(b0), "r"(b1));
}

__device__ __forceinline__ float f2tf_f(float x)
{
    unsigned r;
    asm("cvt.rna.tf32.f32 %0, %1;" : "=r"(r) : "f"(x));
    return __uint_as_float(r);
}

__device__ __forceinline__ unsigned pack_bf16x2(float a, float b)
{
    unsigned r;
    asm("cvt.rn.bf16x2.f32 %0, %1, %2;" : "=r"(r) : "f"(b), "f"(a));
    return r;
}

__device__ __forceinline__ float ex2(float x)
{
    float r;
    asm("ex2.approx.f32 %0, %1;" : "=f"(r) : "f"(x));
    return r;
}

__device__ __forceinline__ void cp16(void* smem, const void* gmem)
{
    unsigned sa = (unsigned)__cvta_generic_to_shared(smem);
    asm volatile("cp.async.cg.shared.global [%0], [%1], 16;\n"
                 :: "r"(sa), "l"(gmem));
}
__device__ __forceinline__ void cp_commit()
{
    asm volatile("cp.async.commit_group;\n");
}
template<int N> __device__ __forceinline__ void cp_wait()
{
    asm volatile("cp.async.wait_group %0;\n" :: "n"(N));
}

__device__ __forceinline__ void ldm_x4(unsigned& r0, unsigned& r1,
                                       unsigned& r2, unsigned& r3, const void* p)
{
    unsigned a = (unsigned)__cvta_generic_to_shared(p);
    asm volatile("ldmatrix.sync.aligned.m8n8.x4.shared.b16 {%0,%1,%2,%3}, [%4];\n"
                 : "=r"(r0), "=r"(r1), "=r"(r2), "=r"(r3) : "r"(a));
}

__device__ __forceinline__ void stcs2(float* p, float a, float b)
{
    asm volatile("st.global.cs.v2.f32 [%0], {%1, %2};\n"
                 :: "l"(p), "f"(a), "f"(b) : "memory");
}

// ---------------------------------------------------------------------------
// Kernel 0: merged pre-pass.
//   blocks [0,4096):        X -> bf16 + tf32
//   blocks [4096,8192):     W transpose (z = idx>>10)
//   blocks [8192,10240):    mask bit-pack (128 words per block)
// ---------------------------------------------------------------------------
__global__ __launch_bounds__(256) void pre_kernel(
    const float* __restrict__ X, const unsigned* __restrict__ mask,
    const float* __restrict__ W0, const float* __restrict__ W1,
    const float* __restrict__ W2, const float* __restrict__ W3)
{
    __shared__ float tile[32][33];
    const int bid = blockIdx.x;
    const int tid = threadIdx.x;

    if (bid < 4096) {
        size_t i = ((size_t)bid * 256 + tid) * 4;
        float4 v = *(const float4*)(X + i);
        __nv_bfloat162* d = (__nv_bfloat162*)(g_xb + i);
        d[0] = __floats2bfloat162_rn(v.x, v.y);
        d[1] = __floats2bfloat162_rn(v.z, v.w);
        float4 tv = make_float4(f2tf_f(v.x), f2tf_f(v.y), f2tf_f(v.z), f2tf_f(v.w));
        *(float4*)(g_xtf + i) = tv;
    } else if (bid < 8192) {
        const int wb = bid - 4096;
        const int z  = wb >> 10;
        const int li = wb & 1023;
        const float* W = z == 0 ? W0 : z == 1 ? W1 : z == 2 ? W2 : W3;
        const int tx = tid & 31, ty = tid >> 5;
        const int k0 = (li & 31) * 32, n0 = (li >> 5) * 32;
        #pragma unroll
        for (int i = 0; i < 4; ++i)
            tile[ty + i * 8][tx] = W[(size_t)(k0 + ty + i * 8) * Dc + n0 + tx];
        __syncthreads();
        if (z < 2) {
            float* out = g_wTf[z];
            #pragma unroll
            for (int i = 0; i < 4; ++i)
                out[(size_t)(n0 + ty + i * 8) * Dc + k0 + tx] =
                    f2tf_f(tile[tx][ty + i * 8]);
        } else {
            __nv_bfloat16* out = g_wT[z];
            #pragma unroll
            for (int i = 0; i < 4; ++i)
                out[(size_t)(n0 + ty + i * 8) * Dc + k0 + tx] =
                    __float2bfloat16(tile[tx][ty + i * 8]);
        }
    } else {
        const int mb   = bid - 8192;           // 0..2047, 128 words each
        const int warp = tid >> 5, lane = tid & 31;
        const int wbase = mb * 128 + warp * 16;
        #pragma unroll
        for (int k = 0; k < 16; ++k) {
            const int w = wbase + k;
            unsigned v = mask[(size_t)w * 32 + lane];
            unsigned bits = __ballot_sync(0xffffffffu, v != 0);
            if (lane == 0) g_mask[w] = bits;
        }
    }
}

// ---------------------------------------------------------------------------
// Kernel 1: ALL projections in one launch.
//   z=0: q (tf32, BK=16), z=1: k (tf32, + bf16 copy), z=2: v (bf16, BK=32).
// ---------------------------------------------------------------------------
__global__ __launch_bounds__(256, 2) void proj_all_kernel(
    const float* __restrict__ bq, const float* __restrict__ bk,
    const float* __restrict__ bv)
{
    __shared__ __align__(16) unsigned char smA[20480];
    __shared__ __align__(16) unsigned char smB[20480];

    const int z    = blockIdx.z;
    const int tid  = threadIdx.x;
    const int warp = tid >> 5, lane = tid & 31;
    const int g = lane >> 2, t = lane & 3;
    const int wm = warp >> 1, wn = warp & 1;
    const int row0 = blockIdx.y * 128;
    const int col0 = blockIdx.x * 128;

    float c[2][8][4];
    #pragma unroll
    for (int mt = 0; mt < 2; ++mt)
        #pragma unroll
        for (int nt = 0; nt < 8; ++nt)
            #pragma unroll
            for (int q = 0; q < 4; ++q) c[mt][nt][q] = 0.f;

    if (z < 2) {
        const float* Wt   = g_wTf[z];
        const float* bias = z == 0 ? bq : bk;
        float* outp = z == 0 ? g_qf : g_kf;

        float (*as)[128][20] = (float (*)[128][20])smA;
        float (*bs)[128][20] = (float (*)[128][20])smB;

        auto load_stage = [&](int kk, int st) {
            #pragma unroll
            for (int it = 0; it < 2; ++it) {
                int f = tid + it * 256;
                int r = f >> 2, c4 = (f & 3) * 4;
                cp16(&as[st][r][c4], g_xtf + (size_t)(row0 + r) * Dc + kk + c4);
                cp16(&bs[st][r][c4], Wt    + (size_t)(col0 + r) * Dc + kk + c4);
            }
            cp_commit();
        };

        load_stage(0, 0);
        const int nT = Dc / 16;
        for (int tt = 0; tt < nT; ++tt) {
            const int cur = tt & 1;
            if (tt + 1 < nT) { load_stage((tt + 1) * 16, cur ^ 1); cp_wait<1>(); }
            else             { cp_wait<0>(); }
            __syncthreads();

            #pragma unroll
            for (int kf = 0; kf < 2; ++kf) {
                const int k0 = kf * 8;
                unsigned A[2][4];
                #pragma unroll
                for (int mt = 0; mt < 2; ++mt) {
                    int r = wm * 32 + mt * 16 + g;
                    A[mt][0] = __float_as_uint(as[cur][r    ][k0 + t]);
                    A[mt][1] = __float_as_uint(as[cur][r + 8][k0 + t]);
                    A[mt][2] = __float_as_uint(as[cur][r    ][k0 + t + 4]);
                    A[mt][3] = __float_as_uint(as[cur][r + 8][k0 + t + 4]);
                }
                #pragma unroll
                for (int nt = 0; nt < 8; ++nt) {
                    int n = wn * 64 + nt * 8 + g;
                    unsigned b0 = __float_as_uint(bs[cur][n][k0 + t]);
                    unsigned b1 = __float_as_uint(bs[cur][n][k0 + t + 4]);
                    mma_tf32(c[0][nt][0], c[0][nt][1], c[0][nt][2], c[0][nt][3],
                             A[0][0], A[0][1], A[0][2], A[0][3], b0, b1);
                    mma_tf32(c[1][nt][0], c[1][nt][1], c[1][nt][2], c[1][nt][3],
                             A[1][0], A[1][1], A[1][2], A[1][3], b0, b1);
                }
            }
            __syncthreads();
        }

        #pragma unroll
        for (int mt = 0; mt < 2; ++mt) {
            #pragma unroll
            for (int nt = 0; nt < 8; ++nt) {
                const int col = col0 + wn * 64 + nt * 8 + t * 2;
                const int h = col >> 6, dk = col & 63;
                const float bi0 = bias[col], bi1 = bias[col + 1];
                const int r0 = row0 + wm * 32 + mt * 16 + g;
                #pragma unroll
                for (int rr = 0; rr < 2; ++rr) {
                    const int rowg = r0 + rr * 8;
                    const int b = rowg >> 11, s = rowg & 2047;
                    const float v0 = c[mt][nt][rr * 2 + 0] + bi0;
                    const float v1 = c[mt][nt][rr * 2 + 1] + bi1;
                    const size_t off = ((size_t)(b * Hc + h) * Sc + s) * DKc + dk;
                    *(float2*)(outp + off) = make_float2(f2tf_f(v0), f2tf_f(v1));
                    if (z == 1)
                        *(__nv_bfloat162*)(g_kb + off) = __floats2bfloat162_rn(v0, v1);
                }
            }
        }
    } else {
        const __nv_bfloat16* Wt = g_wT[2];

        __nv_bfloat16 (*as)[128][40] = (__nv_bfloat16 (*)[128][40])smA;
        __nv_bfloat16 (*bs)[128][40] = (__nv_bfloat16 (*)[128][40])smB;

        auto load_stage = [&](int kk, int st) {
            #pragma unroll
            for (int it = 0; it < 2; ++it) {
                int f = tid + it * 256;
                int r = f >> 2, c8 = (f & 3) * 8;
                cp16(&as[st][r][c8], g_xb + (size_t)(row0 + r) * Dc + kk + c8);
                cp16(&bs[st][r][c8], Wt   + (size_t)(col0 + r) * Dc + kk + c8);
            }
            cp_commit();
        };

        load_stage(0, 0);
        const int nT = Dc / 32;
        for (int tt = 0; tt < nT; ++tt) {
            const int cur = tt & 1;
            if (tt + 1 < nT) { load_stage((tt + 1) * 32, cur ^ 1); cp_wait<1>(); }
            else             { cp_wait<0>(); }
            __syncthreads();

            #pragma unroll
            for (int kf = 0; kf < 2; ++kf) {
                const int k0 = kf * 16;
                unsigned A[2][4];
                #pragma unroll
                for (int mt = 0; mt < 2; ++mt) {
                    int r = wm * 32 + mt * 16 + g;
                    A[mt][0] = *(const unsigned*)&as[cur][r    ][k0     + t * 2];
                    A[mt][1] = *(const unsigned*)&as[cur][r + 8][k0     + t * 2];
                    A[mt][2] = *(const unsigned*)&as[cur][r    ][k0 + 8 + t * 2];
                    A[mt][3] = *(const unsigned*)&as[cur][r + 8][k0 + 8 + t * 2];
                }
                #pragma unroll
                for (int nt = 0; nt < 8; ++nt) {
                    int n = wn * 64 + nt * 8 + g;
                    unsigned b0 = *(const unsigned*)&bs[cur][n][k0     + t * 2];
                    unsigned b1 = *(const unsigned*)&bs[cur][n][k0 + 8 + t * 2];
                    mma_bf16(c[0][nt][0], c[0][nt][1], c[0][nt][2], c[0][nt][3],
                             A[0][0], A[0][1], A[0][2], A[0][3], b0, b1);
                    mma_bf16(c[1][nt][0], c[1][nt][1], c[1][nt][2], c[1][nt][3],
                             A[1][0], A[1][1], A[1][2], A[1][3], b0, b1);
                }
            }
            __syncthreads();
        }

        #pragma unroll
        for (int mt = 0; mt < 2; ++mt) {
            #pragma unroll
            for (int nt = 0; nt < 8; ++nt) {
                const int col = col0 + wn * 64 + nt * 8 + t * 2;
                const int h = col >> 6, dk = col & 63;
                const float bi0 = bv[col], bi1 = bv[col + 1];
                const int r0 = row0 + wm * 32 + mt * 16 + g;
                #pragma unroll
                for (int rr = 0; rr < 2; ++rr) {
                    const int rowg = r0 + rr * 8;
                    const int b = rowg >> 11, s = rowg & 2047;
                    g_vT[((size_t)(b * Hc + h) * DKc + dk    ) * Sc + s] =
                        __float2bfloat16(c[mt][nt][rr * 2 + 0] + bi0);
                    g_vT[((size_t)(b * Hc + h) * DKc + dk + 1) * Sc + s] =
                        __float2bfloat16(c[mt][nt][rr * 2 + 1] + bi1);
                }
            }
        }
    }
}

// ---------------------------------------------------------------------------
// Kernel 2: FUSED attention, 2 blocks/SM.
//   pass 1: bf16 q.k^T (ldmatrix B) -> masked-exp row sums only.
//   pass 2: tf32 q.k^T in two nt-halves -> p = e/l, streaming-store p,
//           C-frags -> bf16 A-frags of p @ V (ldmatrix V).
// ---------------------------------------------------------------------------
__global__ __launch_bounds__(256, 2) void attn_fused_kernel(float* __restrict__ attn)
{
    const int bh = blockIdx.y;
    const int i0 = blockIdx.x * 128;
    const int b  = bh >> 4, h = bh & 15;

    __shared__ __align__(16) unsigned char sbuf[44032];
    float (*qs)[68] = (float (*)[68])sbuf;
    __nv_bfloat16 (*kb0)[72] = (__nv_bfloat16 (*)[72])sbuf;
    __nv_bfloat16 (*kb1)[72] = (__nv_bfloat16 (*)[72])(sbuf + 9216);
    float (*ks0)[68] = (float (*)[68])sbuf;
    float (*ks1)[68] = (float (*)[68])(sbuf + 17408);
    __nv_bfloat16 (*vs)[72] = (__nv_bfloat16 (*)[72])(sbuf + 34816);

    const int tid = threadIdx.x, warp = tid >> 5, lane = tid & 31;
    const int g = lane >> 2, t = lane & 3;
    const int lm = lane >> 3, lr = lane & 7;

    const float* qbase = g_qf + ((size_t)bh * Sc + i0) * DKc;
    const float* kbase = g_kf + (size_t)bh * Sc * DKc;
    const __nv_bfloat16* kbbase = g_kb + (size_t)bh * Sc * DKc;
    const __nv_bfloat16* vbase  = g_vT + (size_t)bh * DKc * Sc;

    #pragma unroll
    for (int it = 0; it < 8; ++it) {
        int f = tid + it * 256;
        int r = f >> 4, c4 = (f & 15) * 4;
        *(float4*)&qs[r][c4] = *(const float4*)(qbase + (size_t)r * DKc + c4);
    }
    __syncthreads();

    unsigned A[8][4];    // tf32 fragments (pass 2)
    unsigned Ab[4][4];   // bf16 fragments (pass 1)
    {
        const int r = warp * 16 + g;
        #pragma unroll
        for (int kf = 0; kf < 8; ++kf) {
            const int k0 = kf * 8;
            A[kf][0] = __float_as_uint(qs[r    ][k0 + t]);
            A[kf][1] = __float_as_uint(qs[r + 8][k0 + t]);
            A[kf][2] = __float_as_uint(qs[r    ][k0 + t + 4]);
            A[kf][3] = __float_as_uint(qs[r + 8][k0 + t + 4]);
        }
        #pragma unroll
        for (int kf = 0; kf < 4; ++kf) {
            const int k0 = kf * 16;
            Ab[kf][0] = pack_bf16x2(qs[r    ][k0     + t * 2], qs[r    ][k0     + t * 2 + 1]);
            Ab[kf][1] = pack_bf16x2(qs[r + 8][k0     + t * 2], qs[r + 8][k0     + t * 2 + 1]);
            Ab[kf][2] = pack_bf16x2(qs[r    ][k0 + 8 + t * 2], qs[r    ][k0 + 8 + t * 2 + 1]);
            Ab[kf][3] = pack_bf16x2(qs[r + 8][k0 + 8 + t * 2], qs[r + 8][k0 + 8 + t * 2 + 1]);
        }
    }
    __syncthreads();

    const int ig0 = i0 + warp * 16 + g;
    const int ig1 = ig0 + 8;
    const unsigned* mp0 = g_mask + ((size_t)b * Sc + ig0) * (Sc / 32);
    const unsigned* mp1 = g_mask + ((size_t)b * Sc + ig1) * (Sc / 32);
    float* arow0 = attn + ((size_t)bh * Sc + ig0) * Sc;
    float* arow1 = attn + ((size_t)bh * Sc + ig1) * Sc;

    auto load_kb = [&](int jj, int st) {
        __nv_bfloat16 (*dst)[72] = st ? kb1 : kb0;
        #pragma unroll
        for (int it = 0; it < 2; ++it) {
            int f = tid + it * 256;
            int r = f >> 3, c8 = (f & 7) * 8;
            cp16(&dst[r][c8], kbbase + (size_t)(jj + r) * DKc + c8);
        }
        cp_commit();
    };
    auto load_k = [&](int jj, int st) {
        float (*dst)[68] = st ? ks1 : ks0;
        #pragma unroll
        for (int it = 0; it < 4; ++it) {
            int f = tid + it * 256;
            int r = f >> 4, c4 = (f & 15) * 4;
            cp16(&dst[r][c4], kbase + (size_t)(jj + r) * DKc + c4);
        }
        cp_commit();
    };
    auto load_v = [&](int jj) {
        #pragma unroll
        for (int it = 0; it < 2; ++it) {
            int f = tid + it * 256;
            int dk = f >> 3, c8 = (f & 7) * 8;
            cp16(&vs[dk][c8], vbase + (size_t)dk * Sc + jj + c8);
        }
        cp_commit();
    };

    // ---------------- pass 1: row sums (bf16 MMA, ldmatrix B) ----------------
    float rsum0 = 0.f, rsum1 = 0.f;
    load_kb(0, 0);
    for (int jj = 0; jj < Sc; jj += 64) {
        const int cur = (jj >> 6) & 1;
        if (jj + 64 < Sc) { load_kb(jj + 64, cur ^ 1); cp_wait<1>(); }
        else              { cp_wait<0>(); }
        __syncthreads();
        __nv_bfloat16 (*kb)[72] = cur ? kb1 : kb0;

        float c[8][4];
        #pragma unroll
        for (int nt = 0; nt < 8; ++nt)
            #pragma unroll
            for (int q = 0; q < 4; ++q) c[nt][q] = 0.f;
        #pragma unroll
        for (int kf = 0; kf < 4; ++kf) {
            const int k0 = kf * 16;
            #pragma unroll
            for (int q = 0; q < 4; ++q) {
                const int nt0 = 2 * q;
                unsigned r0, r1, r2, r3;
                ldm_x4(r0, r1, r2, r3,
                       &kb[(nt0 + (lm >> 1)) * 8 + lr][k0 + (lm & 1) * 8]);
                mma_bf16(c[nt0][0], c[nt0][1], c[nt0][2], c[nt0][3],
                         Ab[kf][0], Ab[kf][1], Ab[kf][2], Ab[kf][3], r0, r1);
                mma_bf16(c[nt0 + 1][0], c[nt0 + 1][1], c[nt0 + 1][2], c[nt0 + 1][3],
                         Ab[kf][0], Ab[kf][1], Ab[kf][2], Ab[kf][3], r2, r3);
            }
        }

        const unsigned m00 = mp0[jj >> 5], m01 = mp0[(jj >> 5) + 1];
        const unsigned m10 = mp1[jj >> 5], m11 = mp1[(jj >> 5) + 1];
        #pragma unroll
        for (int nt = 0; nt < 8; ++nt) {
            const int jl = nt * 8 + t * 2;
            const unsigned w0 = (jl & 32) ? m01 : m00;
            const unsigned w1 = (jl & 32) ? m11 : m10;
            const int sh = jl & 31;
            rsum0 += (((w0 >> sh)       & 1u) ? 0.f : ex2(c[nt][0] * EXP_SCALE))
                   + (((w0 >> (sh + 1)) & 1u) ? 0.f : ex2(c[nt][1] * EXP_SCALE));
            rsum1 += (((w1 >> sh)       & 1u) ? 0.f : ex2(c[nt][2] * EXP_SCALE))
                   + (((w1 >> (sh + 1)) & 1u) ? 0.f : ex2(c[nt][3] * EXP_SCALE));
        }
        __syncthreads();
    }
    rsum0 += __shfl_xor_sync(0xffffffffu, rsum0, 1);
    rsum0 += __shfl_xor_sync(0xffffffffu, rsum0, 2);
    rsum1 += __shfl_xor_sync(0xffffffffu, rsum1, 1);
    rsum1 += __shfl_xor_sync(0xffffffffu, rsum1, 2);
    const float invl0 = 1.0f / rsum0;
    const float invl1 = 1.0f / rsum1;

    // ---------------- pass 2: write p, ctx = p @ V (tf32 scores) ----------
    float ctx[8][4];
    #pragma unroll
    for (int nt = 0; nt < 8; ++nt)
        #pragma unroll
        for (int q = 0; q < 4; ++q) ctx[nt][q] = 0.f;

    load_k(0, 0);
    for (int jj = 0; jj < Sc; jj += 64) {
        const int cur = (jj >> 6) & 1;
        load_v(jj);
        if (jj + 64 < Sc) { load_k(jj + 64, cur ^ 1); cp_wait<1>(); }
        else              { cp_wait<0>(); }
        __syncthreads();
        float (*ks)[68] = cur ? ks1 : ks0;

        #pragma unroll
        for (int half = 0; half < 2; ++half) {
            float c[4][4];
            #pragma unroll
            for (int ntl = 0; ntl < 4; ++ntl)
                #pragma unroll
                for (int q = 0; q < 4; ++q) c[ntl][q] = 0.f;

            #pragma unroll
            for (int kf = 0; kf < 8; ++kf) {
                const int k0 = kf * 8;
                #pragma unroll
                for (int ntl = 0; ntl < 4; ++ntl) {
                    const int n = (half * 4 + ntl) * 8 + g;
                    unsigned b0 = __float_as_uint(ks[n][k0 + t]);
                    unsigned b1 = __float_as_uint(ks[n][k0 + t + 4]);
                    mma_tf32(c[ntl][0], c[ntl][1], c[ntl][2], c[ntl][3],
                             A[kf][0], A[kf][1], A[kf][2], A[kf][3], b0, b1);
                }
            }

            const unsigned w0 = mp0[(jj >> 5) + half];
            const unsigned w1 = mp1[(jj >> 5) + half];

            unsigned pf[4][2];
            #pragma unroll
            for (int ntl = 0; ntl < 4; ++ntl) {
                const int nt = half * 4 + ntl;
                const int jl = nt * 8 + t * 2;
                const int sh = jl & 31;
                float p0 = ((w0 >> sh)       & 1u) ? 0.f : ex2(c[ntl][0] * EXP_SCALE) * invl0;
                float p1 = ((w0 >> (sh + 1)) & 1u) ? 0.f : ex2(c[ntl][1] * EXP_SCALE) * invl0;
                float p2 = ((w1 >> sh)       & 1u) ? 0.f : ex2(c[ntl][2] * EXP_SCALE) * invl1;
                float p3 = ((w1 >> (sh + 1)) & 1u) ? 0.f : ex2(c[ntl][3] * EXP_SCALE) * invl1;
                stcs2(arow0 + jj + jl, p0, p1);
                stcs2(arow1 + jj + jl, p2, p3);
                pf[ntl][0] = pack_bf16x2(p0, p1);
                pf[ntl][1] = pack_bf16x2(p2, p3);
            }

            #pragma unroll
            for (int kfl = 0; kfl < 2; ++kfl) {
                const int k0 = (half * 2 + kfl) * 16;
                const unsigned a0 = pf[2 * kfl    ][0];
                const unsigned a1 = pf[2 * kfl    ][1];
                const unsigned a2 = pf[2 * kfl + 1][0];
                const unsigned a3 = pf[2 * kfl + 1][1];
                #pragma unroll
                for (int q = 0; q < 4; ++q) {
                    const int nt0 = 2 * q;
                    unsigned r0, r1, r2, r3;
                    ldm_x4(r0, r1, r2, r3,
                           &vs[(nt0 + (lm >> 1)) * 8 + lr][k0 + (lm & 1) * 8]);
                    mma_bf16(ctx[nt0][0], ctx[nt0][1], ctx[nt0][2], ctx[nt0][3],
                             a0, a1, a2, a3, r0, r1);
                    mma_bf16(ctx[nt0 + 1][0], ctx[nt0 + 1][1], ctx[nt0 + 1][2], ctx[nt0 + 1][3],
                             a0, a1, a2, a3, r2, r3);
                }
            }
        }
        __syncthreads();
    }

    const int s = i0 + warp * 16 + g;
    const size_t crow0 = ((size_t)b * Sc + s)     * Dc;
    const size_t crow1 = ((size_t)b * Sc + s + 8) * Dc;
    #pragma unroll
    for (int nt = 0; nt < 8; ++nt) {
        const int col = h * DKc + nt * 8 + t * 2;
        *(__nv_bfloat162*)&g_ctxb[crow0 + col] = __floats2bfloat162_rn(ctx[nt][0], ctx[nt][1]);
        *(__nv_bfloat162*)&g_ctxb[crow1 + col] = __floats2bfloat162_rn(ctx[nt][2], ctx[nt][3]);
    }
}

// ---------------------------------------------------------------------------
// Kernel 3: output projection, bf16 MMA, cp.async 2-stage.
// ---------------------------------------------------------------------------
__global__ __launch_bounds__(256, 2) void oproj_mma_kernel(
    const float* __restrict__ bo, const float* __restrict__ Qres)
{
    const __nv_bfloat16* Wt = g_wT[3];

    __shared__ __align__(16) __nv_bfloat16 as[2][128][40];
    __shared__ __align__(16) __nv_bfloat16 bs[2][128][40];

    const int tid  = threadIdx.x;
    const int warp = tid >> 5, lane = tid & 31;
    const int g = lane >> 2, t = lane & 3;
    const int wm = warp >> 1, wn = warp & 1;
    const int row0 = blockIdx.y * 128;
    const int col0 = blockIdx.x * 128;

    float c[2][8][4];
    #pragma unroll
    for (int mt = 0; mt < 2; ++mt)
        #pragma unroll
        for (int nt = 0; nt < 8; ++nt)
            #pragma unroll
            for (int q = 0; q < 4; ++q) c[mt][nt][q] = 0.f;

    auto load_stage = [&](int kk, int st) {
        #pragma unroll
        for (int it = 0; it < 2; ++it) {
            int f = tid + it * 256;
            int r = f >> 2, c8 = (f & 3) * 8;
            cp16(&as[st][r][c8], g_ctxb + (size_t)(row0 + r) * Dc + kk + c8);
            cp16(&bs[st][r][c8], Wt     + (size_t)(col0 + r) * Dc + kk + c8);
        }
        cp_commit();
    };

    load_stage(0, 0);

    const int nT = Dc / 32;
    for (int tt = 0; tt < nT; ++tt) {
        const int cur = tt & 1;
        if (tt + 1 < nT) { load_stage((tt + 1) * 32, cur ^ 1); cp_wait<1>(); }
        else             { cp_wait<0>(); }
        __syncthreads();

        #pragma unroll
        for (int kf = 0; kf < 2; ++kf) {
            const int k0 = kf * 16;
            unsigned A[2][4];
            #pragma unroll
            for (int mt = 0; mt < 2; ++mt) {
                int r = wm * 32 + mt * 16 + g;
                A[mt][0] = *(const unsigned*)&as[cur][r    ][k0     + t * 2];
                A[mt][1] = *(const unsigned*)&as[cur][r + 8][k0     + t * 2];
                A[mt][2] = *(const unsigned*)&as[cur][r    ][k0 + 8 + t * 2];
                A[mt][3] = *(const unsigned*)&as[cur][r + 8][k0 + 8 + t * 2];
            }
            #pragma unroll
            for (int nt = 0; nt < 8; ++nt) {
                int n = wn * 64 + nt * 8 + g;
                unsigned b0 = *(const unsigned*)&bs[cur][n][k0     + t * 2];
                unsigned b1 = *(const unsigned*)&bs[cur][n][k0 + 8 + t * 2];
                mma_bf16(c[0][nt][0], c[0][nt][1], c[0][nt][2], c[0][nt][3],
                         A[0][0], A[0][1], A[0][2], A[0][3], b0, b1);
                mma_bf16(c[1][nt][0], c[1][nt][1], c[1][nt][2], c[1][nt][3],
                         A[1][0], A[1][1], A[1][2], A[1][3], b0, b1);
            }
        }
        __syncthreads();
    }

    #pragma unroll
    for (int mt = 0; mt < 2; ++mt) {
        #pragma unroll
        for (int nt = 0; nt < 8; ++nt) {
            const int col = col0 + wn * 64 + nt * 8 + t * 2;
            const float bi0 = bo[col], bi1 = bo[col + 1];
            const int r0 = row0 + wm * 32 + mt * 16 + g;
            #pragma unroll
            for (int rr = 0; rr < 2; ++rr) {
                const int rowg = r0 + rr * 8;
                const float* res = Qres + (size_t)rowg * Dc + col;
                float2 rv = *(const float2*)res;
                float2 o = make_float2(c[mt][nt][rr * 2 + 0] + bi0 + rv.x,
                                       c[mt][nt][rr * 2 + 1] + bi1 + rv.y);
                *(float2*)(g_y + (size_t)rowg * Dc + col) = o;
            }
        }
    }
}

// ---------------------------------------------------------------------------
// Kernel 4: LayerNorm per row (fp32).
// ---------------------------------------------------------------------------
__global__ __launch_bounds__(256) void ln_kernel(
    const float* __restrict__ gamma, const float* __restrict__ beta,
    float* __restrict__ out)
{
    const int row = blockIdx.x;
    const int tid = threadIdx.x;
    const float* y = g_y + (size_t)row * Dc;

    float4 v = ((const float4*)y)[tid];
    float s  = v.x + v.y + v.z + v.w;
    float q  = v.x * v.x + v.y * v.y + v.z * v.z + v.w * v.w;

    __shared__ float ss[8];
    __shared__ float sq[8];
    #pragma unroll
    for (int o = 16; o > 0; o >>= 1) {
        s += __shfl_xor_sync(0xffffffffu, s, o);
        q += __shfl_xor_sync(0xffffffffu, q, o);
    }
    if ((tid & 31) == 0) { ss[tid >> 5] = s; sq[tid >> 5] = q; }
    __syncthreads();
    s = ss[tid & 7];
    q = sq[tid & 7];
    #pragma unroll
    for (int o = 4; o > 0; o >>= 1) {
        s += __shfl_xor_sync(0xffffffffu, s, o);
        q += __shfl_xor_sync(0xffffffffu, q, o);
    }

    const float mu  = s * (1.0f / Dc);
    const float var = q * (1.0f / Dc) - mu * mu;
    const float inv = rsqrtf(var + 1e-5f);

    float4 gv = ((const float4*)gamma)[tid];
    float4 bv = ((const float4*)beta)[tid];
    float4 o4 = make_float4((v.x - mu) * inv * gv.x + bv.x,
                            (v.y - mu) * inv * gv.y + bv.y,
                            (v.z - mu) * inv * gv.z + bv.z,
                            (v.w - mu) * inv * gv.w + bv.w);
    ((float4*)(out + (size_t)row * Dc))[tid] = o4;
}

// ---------------------------------------------------------------------------
// Launch
// ---------------------------------------------------------------------------
extern "C" void kernel_launch(void* const* d_in, const int* in_sizes, int n_in,
                              void* d_out, int out_size)
{
    const float* Qin  = (const float*)d_in[0];
    const unsigned* mask = (const unsigned*)d_in[3];
    const float* Wq = (const float*)d_in[4];
    const float* bq = (const float*)d_in[5];
    const float* Wk = (const float*)d_in[6];
    const float* bk = (const float*)d_in[7];
    const float* Wv = (const float*)d_in[8];
    const float* bv = (const float*)d_in[9];
    const float* Wo = (const float*)d_in[10];
    const float* bo = (const float*)d_in[11];
    const float* ln_g = (const float*)d_in[12];
    const float* ln_b = (const float*)d_in[13];

    float* out  = (float*)d_out;
    float* attn = out + (size_t)Bc * Sc * Dc;

    pre_kernel       <<<10240, 256>>>(Qin, mask, Wq, Wk, Wv, Wo);
    proj_all_kernel  <<<dim3(Dc / 128, Mc / 128, 3), 256>>>(bq, bk, bv);
    attn_fused_kernel<<<dim3(Sc / 128, BHc), 256>>>(attn);
    oproj_mma_kernel <<<dim3(Dc / 128, Mc / 128), 256>>>(bo, Qin);
    ln_kernel        <<<Mc, 256>>>(ln_g, ln_b, out);
}